// round 2
// baseline (speedup 1.0000x reference)
#include <cuda_runtime.h>
#include <math.h>

#define SQ   2048
#define HID  1024
#define NH   16
#define HD   64
#define BSZ  2
#define MFREQ (SQ/2 + 1)
#define KTOP 15   // int(2*ln(2049)) = 15 for S=2048

// ---------------- scratch (static device allocations) ----------------
__device__ float d_c[SQ];
__device__ float d_dcflag;
__device__ float d_Cmat[SQ * SQ];
__device__ float d_Xf  [BSZ * SQ * HID];
__device__ float d_Qfil[BSZ * SQ * HID];
__device__ float d_Kfil[BSZ * SQ * HID];
__device__ float d_Vfil[BSZ * SQ * HID];
__device__ float d_Vbuf[BSZ * SQ * HID];
__device__ float d_Comb[BSZ * SQ * HID];
__device__ float d_ac  [BSZ * NH * SQ];
__device__ int   d_topi[BSZ * NH * KTOP];
__device__ float d_topw[BSZ * NH * KTOP];

// ---------------- filter vector c[n] ----------------
__global__ void filter_kernel(const int* __restrict__ li_p, const int* __restrict__ nl_p,
                              float* __restrict__ c, float* __restrict__ dcflag)
{
    int n = blockIdx.x * blockDim.x + threadIdx.x;
    if (n >= SQ) return;
    int li = *li_p;
    int nl = *nl_p;
    const double ALPHA = 0.5;
    int M = MFREQ;
    int p, q;
    if (ALPHA <= 1.0 / (double)nl) {
        p = (int)(M * (1.0 - (double)(li + 1) / (double)nl));
        q = (int)((double)p + (double)M / (double)nl);
    } else {
        p = (nl > 1) ? (int)(M * (1.0 - ALPHA) * (1.0 - (double)li / (double)(nl - 1))) : 0;
        q = (int)((double)p + ALPHA * (double)M);
    }
    p = max(0, min(p, M - 1));
    q = max(p + 1, min(q, M));

    double acc = 0.0;
    const double w2 = 2.0 / (double)SQ;
    const double w1 = 1.0 / (double)SQ;
    const double twopi_n_over_S = 6.283185307179586476925286766559 * (double)n / (double)SQ;
    for (int f = p; f < q; f++) {
        double wf = (f == 0 || f == M - 1) ? w1 : w2;
        acc += wf * cos(twopi_n_over_S * (double)f);
    }
    c[n] = (float)acc;
    if (n == 0) *dcflag = (p == 0) ? 1.0f : 0.0f;
}

// ---------------- circulant matrix ----------------
__global__ void cmat_kernel(float* __restrict__ Cm, const float* __restrict__ c)
{
    int idx = blockIdx.x * blockDim.x + threadIdx.x;   // 4M threads
    int t = idx >> 11;
    int s = idx & (SQ - 1);
    Cm[idx] = c[(t - s) & (SQ - 1)];
}

__global__ void zero_kernel(float* __restrict__ p, int n)
{
    int i = blockIdx.x * blockDim.x + threadIdx.x;
    if (i < n) p[i] = 0.f;
}

// ---------------- generic fp32 SGEMM: C = A@B (+ bias*scale) ----------------
// 128x128 tile, BK=8, 256 threads, 8x8 micro-tile.
__global__ __launch_bounds__(256) void gemm_kernel(
    const float* __restrict__ A, const float* __restrict__ B,
    const float* __restrict__ bias, const float* __restrict__ bscalep,
    float* __restrict__ C,
    int M, int N, int K,
    long long sA, long long sB, long long sC)
{
    __shared__ float As[8 * 128];
    __shared__ float Bs[8 * 128];

    int z = blockIdx.z;
    A += (size_t)z * sA;
    B += (size_t)z * sB;
    C += (size_t)z * sC;

    int tid = threadIdx.x;
    int tx = tid & 15, ty = tid >> 4;
    int row0 = blockIdx.y * 128;
    int col0 = blockIdx.x * 128;

    int arow = tid >> 1;            // 0..127
    int acol = (tid & 1) << 2;      // 0 or 4
    int brow = tid >> 5;            // 0..7
    int bcol = (tid & 31) << 2;     // 0..124

    float acc[8][8];
#pragma unroll
    for (int i = 0; i < 8; i++)
#pragma unroll
        for (int j = 0; j < 8; j++) acc[i][j] = 0.f;

    const float* Aptr = A + (size_t)(row0 + arow) * K + acol;
    const float* Bptr = B + (size_t)brow * N + col0 + bcol;

    for (int k0 = 0; k0 < K; k0 += 8) {
        float4 av = *(const float4*)(Aptr + k0);
        float4 bv = *(const float4*)(Bptr + (size_t)k0 * N);
        __syncthreads();
        As[(acol + 0) * 128 + arow] = av.x;
        As[(acol + 1) * 128 + arow] = av.y;
        As[(acol + 2) * 128 + arow] = av.z;
        As[(acol + 3) * 128 + arow] = av.w;
        *(float4*)&Bs[brow * 128 + bcol] = bv;
        __syncthreads();
#pragma unroll
        for (int kk = 0; kk < 8; kk++) {
            float a[8], b[8];
            *(float4*)(a)     = *(float4*)&As[kk * 128 + ty * 8];
            *(float4*)(a + 4) = *(float4*)&As[kk * 128 + ty * 8 + 4];
            *(float4*)(b)     = *(float4*)&Bs[kk * 128 + tx * 8];
            *(float4*)(b + 4) = *(float4*)&Bs[kk * 128 + tx * 8 + 4];
#pragma unroll
            for (int i = 0; i < 8; i++)
#pragma unroll
                for (int j = 0; j < 8; j++) acc[i][j] += a[i] * b[j];
        }
    }

    float bscale = 0.f;
    if (bias) bscale = bscalep ? *bscalep : 1.f;

#pragma unroll
    for (int i = 0; i < 8; i++) {
        float out[8];
#pragma unroll
        for (int j = 0; j < 8; j++) {
            float v = acc[i][j];
            if (bias) v += bias[col0 + tx * 8 + j] * bscale;
            out[j] = v;
        }
        float* crow = C + (size_t)(row0 + ty * 8 + i) * N + col0 + tx * 8;
        *(float4*)(crow)     = *(float4*)(out);
        *(float4*)(crow + 4) = *(float4*)(out + 4);
    }
}

// ---------------- fused flash attention + autocorrelation diag-sums ----------------
// grid (32 qblocks, NH, BSZ), 256 threads, BM=BN=64, HD=64.
// dyn smem: Qt[64*64] | Kt[64*64] (reused as P^T) | Vs[64*64] | acb[128]
__global__ __launch_bounds__(256) void flash_kernel(
    const float* __restrict__ Qf, const float* __restrict__ Kf,
    const float* __restrict__ Vf, const float* __restrict__ mask,
    float* __restrict__ Comb, float* __restrict__ ac)
{
    extern __shared__ float sm_[];
    float* Qt  = sm_;
    float* Kt  = sm_ + 4096;
    float* Vs  = sm_ + 8192;
    float* acb = sm_ + 12288;

    int tid = threadIdx.x;
    int tx = tid & 15, ty = tid >> 4;
    int qb = blockIdx.x, h = blockIdx.y, b = blockIdx.z;
    int t0 = qb * 64;

    const float* Qbase = Qf + (size_t)b * SQ * HID + h * HD;
    const float* Kbase = Kf + (size_t)b * SQ * HID + h * HD;
    const float* Vbase = Vf + (size_t)b * SQ * HID + h * HD;
    const float* Mbase = mask + (size_t)b * SQ * SQ;
    float* acrow = ac + (size_t)(b * NH + h) * SQ;

    // Load Q tile transposed: Qt[d][row]
#pragma unroll
    for (int l = 0; l < 4; l++) {
        int id4 = tid + l * 256;
        int r = id4 >> 4;
        int cc = (id4 & 15) << 2;
        float4 v = *(const float4*)&Qbase[(size_t)(t0 + r) * HID + cc];
        Qt[(cc + 0) * 64 + r] = v.x;
        Qt[(cc + 1) * 64 + r] = v.y;
        Qt[(cc + 2) * 64 + r] = v.z;
        Qt[(cc + 3) * 64 + r] = v.w;
    }

    float m_run[4], l_run[4], o[4][4];
#pragma unroll
    for (int i = 0; i < 4; i++) {
        m_run[i] = -INFINITY;
        l_run[i] = 0.f;
#pragma unroll
        for (int j = 0; j < 4; j++) o[i][j] = 0.f;
    }

    for (int kt = 0; kt < SQ / 64; kt++) {
        int s0 = kt * 64;
        __syncthreads();                 // prev iter done with Kt/Vs/acb
        if (tid < 128) acb[tid] = 0.f;
        // Load K tile transposed (Kt[d][key]) and V tile (Vs[key][d])
#pragma unroll
        for (int l = 0; l < 4; l++) {
            int id4 = tid + l * 256;
            int r = id4 >> 4;
            int cc = (id4 & 15) << 2;
            float4 kv = *(const float4*)&Kbase[(size_t)(s0 + r) * HID + cc];
            Kt[(cc + 0) * 64 + r] = kv.x;
            Kt[(cc + 1) * 64 + r] = kv.y;
            Kt[(cc + 2) * 64 + r] = kv.z;
            Kt[(cc + 3) * 64 + r] = kv.w;
            float4 vv = *(const float4*)&Vbase[(size_t)(s0 + r) * HID + cc];
            *(float4*)&Vs[r * 64 + cc] = vv;
        }
        __syncthreads();

        // raw scores S = Q @ K^T (4x4 per thread)
        float sv[4][4];
#pragma unroll
        for (int i = 0; i < 4; i++)
#pragma unroll
            for (int j = 0; j < 4; j++) sv[i][j] = 0.f;
#pragma unroll 8
        for (int dd = 0; dd < 64; dd++) {
            float a[4], bb[4];
#pragma unroll
            for (int i = 0; i < 4; i++) a[i]  = Qt[dd * 64 + ty * 4 + i];
#pragma unroll
            for (int j = 0; j < 4; j++) bb[j] = Kt[dd * 64 + tx * 4 + j];
#pragma unroll
            for (int i = 0; i < 4; i++)
#pragma unroll
                for (int j = 0; j < 4; j++) sv[i][j] += a[i] * bb[j];
        }

        // autocorrelation: bin by tau = (t - s) mod S; local delta in [-63,63]
        // (the 1/64 here IS the .mean(axis=-1) over head dim — no other scaling)
#pragma unroll
        for (int i = 0; i < 4; i++)
#pragma unroll
            for (int j = 0; j < 4; j++)
                atomicAdd(&acb[(ty * 4 + i) - (tx * 4 + j) + 63], sv[i][j] * (1.f / 64.f));

        // scale + mask + online softmax
        float p[4][4], corr[4];
#pragma unroll
        for (int i = 0; i < 4; i++) {
            float4 mrow = *(const float4*)&Mbase[(size_t)(t0 + ty * 4 + i) * SQ + s0 + tx * 4];
            float mv[4] = {mrow.x, mrow.y, mrow.z, mrow.w};
            float tm = -INFINITY;
#pragma unroll
            for (int j = 0; j < 4; j++) {
                sv[i][j] = sv[i][j] * 0.125f + mv[j];
                tm = fmaxf(tm, sv[i][j]);
            }
#pragma unroll
            for (int off = 8; off >= 1; off >>= 1)
                tm = fmaxf(tm, __shfl_xor_sync(0xffffffffu, tm, off, 16));
            float nm = fmaxf(m_run[i], tm);
            corr[i] = __expf(m_run[i] - nm);
            m_run[i] = nm;
            float rs = 0.f;
#pragma unroll
            for (int j = 0; j < 4; j++) {
                p[i][j] = __expf(sv[i][j] - nm);
                rs += p[i][j];
            }
#pragma unroll
            for (int off = 8; off >= 1; off >>= 1)
                rs += __shfl_xor_sync(0xffffffffu, rs, off, 16);
            l_run[i] = l_run[i] * corr[i] + rs;
#pragma unroll
            for (int j = 0; j < 4; j++) o[i][j] *= corr[i];
        }

        __syncthreads();                 // all S-reads of Kt finished
        // store P^T into Kt: Kt[key][row]
#pragma unroll
        for (int i = 0; i < 4; i++)
#pragma unroll
            for (int j = 0; j < 4; j++)
                Kt[(tx * 4 + j) * 64 + ty * 4 + i] = p[i][j];
        __syncthreads();

        // O += P @ V
#pragma unroll 8
        for (int jj = 0; jj < 64; jj++) {
            float a[4], bb[4];
#pragma unroll
            for (int i = 0; i < 4; i++) a[i]  = Kt[jj * 64 + ty * 4 + i];
#pragma unroll
            for (int j = 0; j < 4; j++) bb[j] = Vs[jj * 64 + tx * 4 + j];
#pragma unroll
            for (int i = 0; i < 4; i++)
#pragma unroll
                for (int j = 0; j < 4; j++) o[i][j] += a[i] * bb[j];
        }

        // flush ac bins
        for (int idx = tid; idx < 127; idx += 256)
            atomicAdd(&acrow[(t0 - s0 + idx - 63) & (SQ - 1)], acb[idx]);
    }

    // epilogue: Comb = GAMMA * time_ctx (GAMMA = 0.5)
    float* Crow = Comb + (size_t)b * SQ * HID + h * HD;
#pragma unroll
    for (int i = 0; i < 4; i++) {
        float inv = 0.5f / l_run[i];
        float out[4];
#pragma unroll
        for (int j = 0; j < 4; j++) out[j] = o[i][j] * inv;
        *(float4*)&Crow[(size_t)(t0 + ty * 4 + i) * HID + tx * 4] = *(float4*)out;
    }
}

// ---------------- top-k (k=15) + softmax weights ----------------
__global__ __launch_bounds__(256) void topk_kernel(
    const float* __restrict__ ac, int* __restrict__ topi, float* __restrict__ topw)
{
    int bh = blockIdx.x;
    __shared__ float svv[SQ];
    __shared__ float rv[256];
    __shared__ int ri[256];
    __shared__ float tvals[KTOP];
    __shared__ int tidxs[KTOP];
    int tid = threadIdx.x;

    // ac already holds mean over head dim (flash applied 1/64) — NO extra scale
    for (int i = tid; i < SQ; i += 256)
        svv[i] = ac[(size_t)bh * SQ + i];
    __syncthreads();

    for (int t = 0; t < KTOP; t++) {
        float bv = -INFINITY;
        int bi = 0;
        for (int i = tid; i < SQ; i += 256) {
            float v = svv[i];
            if (v > bv || (v == bv && i < bi)) { bv = v; bi = i; }
        }
        rv[tid] = bv; ri[tid] = bi;
        __syncthreads();
        for (int st = 128; st > 0; st >>= 1) {
            if (tid < st) {
                float v2 = rv[tid + st]; int i2 = ri[tid + st];
                if (v2 > rv[tid] || (v2 == rv[tid] && i2 < ri[tid])) { rv[tid] = v2; ri[tid] = i2; }
            }
            __syncthreads();
        }
        if (tid == 0) {
            tvals[t] = rv[0]; tidxs[t] = ri[0];
            svv[ri[0]] = -INFINITY;
        }
        __syncthreads();
    }

    if (tid == 0) {
        float mx = tvals[0];
        float e[KTOP], ssum = 0.f;
#pragma unroll
        for (int t = 0; t < KTOP; t++) { e[t] = __expf(tvals[t] - mx); ssum += e[t]; }
        float inv = 1.f / ssum;
#pragma unroll
        for (int t = 0; t < KTOP; t++) {
            topw[bh * KTOP + t] = e[t] * inv;
            topi[bh * KTOP + t] = tidxs[t];
        }
    }
}

// ---------------- frequency branch gather: Comb += (1-GAMMA) * freq_ctx ----------------
__global__ __launch_bounds__(256) void freq_kernel(
    const float* __restrict__ V, const int* __restrict__ topi,
    const float* __restrict__ topw, float* __restrict__ Comb)
{
    int t = blockIdx.x, b = blockIdx.y;
    __shared__ int si[NH * KTOP];
    __shared__ float sw[NH * KTOP];
    int tid = threadIdx.x;
    if (tid < NH * KTOP) {
        si[tid] = topi[b * NH * KTOP + tid];
        sw[tid] = topw[b * NH * KTOP + tid];
    }
    __syncthreads();

    int c = tid * 4;
    int h = c >> 6;
    float* crow = Comb + ((size_t)b * SQ + t) * HID + c;
    float4 acc = *(float4*)crow;
    const float* Vb = V + (size_t)b * SQ * HID;
#pragma unroll
    for (int j = 0; j < KTOP; j++) {
        int row = (t + si[h * KTOP + j]) & (SQ - 1);
        float w = 0.5f * sw[h * KTOP + j];
        float4 v = *(const float4*)&Vb[(size_t)row * HID + c];
        acc.x += w * v.x; acc.y += w * v.y; acc.z += w * v.z; acc.w += w * v.w;
    }
    *(float4*)crow = acc;
}

// ---------------- launcher ----------------
extern "C" void kernel_launch(void* const* d_in, const int* in_sizes, int n_in,
                              void* d_out, int out_size)
{
    const float* X    = (const float*)d_in[0];
    const float* mask = (const float*)d_in[1];
    const float* Wq   = (const float*)d_in[2];
    const float* bq   = (const float*)d_in[3];
    const float* Wk   = (const float*)d_in[4];
    const float* bk   = (const float*)d_in[5];
    const float* Wv   = (const float*)d_in[6];
    const float* bv   = (const float*)d_in[7];
    const float* Wo   = (const float*)d_in[8];
    const float* bo   = (const float*)d_in[9];
    const int*   li   = (const int*)d_in[10];
    const int*   nl   = (const int*)d_in[11];
    float* out = (float*)d_out;

    float *cP, *dcP, *CmP, *XfP, *QfP, *KfP, *VfP, *VbP, *CbP, *acP, *twP;
    int* tiP;
    cudaGetSymbolAddress((void**)&cP,  d_c);
    cudaGetSymbolAddress((void**)&dcP, d_dcflag);
    cudaGetSymbolAddress((void**)&CmP, d_Cmat);
    cudaGetSymbolAddress((void**)&XfP, d_Xf);
    cudaGetSymbolAddress((void**)&QfP, d_Qfil);
    cudaGetSymbolAddress((void**)&KfP, d_Kfil);
    cudaGetSymbolAddress((void**)&VfP, d_Vfil);
    cudaGetSymbolAddress((void**)&VbP, d_Vbuf);
    cudaGetSymbolAddress((void**)&CbP, d_Comb);
    cudaGetSymbolAddress((void**)&acP, d_ac);
    cudaGetSymbolAddress((void**)&tiP, d_topi);
    cudaGetSymbolAddress((void**)&twP, d_topw);

    const long long SH = (long long)SQ * HID;

    // 1) filter taps + circulant matrix
    filter_kernel<<<8, 256>>>(li, nl, cP, dcP);
    cmat_kernel<<<(SQ * SQ) / 256, 256>>>(CmP, cP);

    // 2) Xf = C @ X  (per batch)
    gemm_kernel<<<dim3(HID / 128, SQ / 128, BSZ), 256>>>(
        CmP, X, nullptr, nullptr, XfP, SQ, HID, SQ, 0, SH, SH);

    // 3) filtered projections (bias only if DC in band)
    gemm_kernel<<<dim3(HID / 128, SQ / 128, BSZ), 256>>>(
        XfP, Wq, bq, dcP, QfP, SQ, HID, HID, SH, 0, SH);
    gemm_kernel<<<dim3(HID / 128, SQ / 128, BSZ), 256>>>(
        XfP, Wk, bk, dcP, KfP, SQ, HID, HID, SH, 0, SH);
    gemm_kernel<<<dim3(HID / 128, SQ / 128, BSZ), 256>>>(
        XfP, Wv, bv, dcP, VfP, SQ, HID, HID, SH, 0, SH);

    // 4) unfiltered V (freq branch)
    gemm_kernel<<<dim3(HID / 128, SQ / 128, BSZ), 256>>>(
        X, Wv, bv, nullptr, VbP, SQ, HID, HID, SH, 0, SH);

    // 5) flash attention + autocorrelation diag sums
    zero_kernel<<<(BSZ * NH * SQ) / 256, 256>>>(acP, BSZ * NH * SQ);
    cudaFuncSetAttribute(flash_kernel, cudaFuncAttributeMaxDynamicSharedMemorySize, 49664);
    flash_kernel<<<dim3(SQ / 64, NH, BSZ), 256, 49664>>>(QfP, KfP, VfP, mask, CbP, acP);

    // 6) top-k weights + frequency gather
    topk_kernel<<<BSZ * NH, 256>>>(acP, tiP, twP);
    freq_kernel<<<dim3(SQ, BSZ), 256>>>(VbP, tiP, twP, CbP);

    // 7) output projection
    gemm_kernel<<<dim3(HID / 128, (BSZ * SQ) / 128, 1), 256>>>(
        CbP, Wo, bo, nullptr, out, BSZ * SQ, HID, HID, 0, 0, 0);
}

// round 3
// speedup vs baseline: 1.0285x; 1.0285x over previous
#include <cuda_runtime.h>
#include <math.h>

#define SQ   2048
#define HID  1024
#define NH   16
#define HD   64
#define BSZ  2
#define MFREQ (SQ/2 + 1)
#define KTOP 15   // int(2*ln(2049)) = 15 for S=2048

// ---------------- scratch (static device allocations) ----------------
__device__ float d_c[SQ];
__device__ float d_dcflag;
__device__ float d_Cmat[SQ * SQ];
__device__ float d_Xf  [BSZ * SQ * HID];
__device__ float d_Qfil[BSZ * SQ * HID];
__device__ float d_Kfil[BSZ * SQ * HID];
__device__ float d_Vfil[BSZ * SQ * HID];
__device__ float d_Vbuf[BSZ * SQ * HID];
__device__ float d_Comb[BSZ * SQ * HID];
__device__ float d_ac  [BSZ * NH * SQ];
__device__ int   d_topi[BSZ * NH * KTOP];
__device__ float d_topw[BSZ * NH * KTOP];

// ---------------- cp.async helpers ----------------
__device__ __forceinline__ void cp_async16(void* smem, const void* gmem) {
    unsigned s = (unsigned)__cvta_generic_to_shared(smem);
    asm volatile("cp.async.cg.shared.global [%0], [%1], 16;" :: "r"(s), "l"(gmem));
}
__device__ __forceinline__ void cp_commit() {
    asm volatile("cp.async.commit_group;");
}
__device__ __forceinline__ void cp_wait0() {
    asm volatile("cp.async.wait_group 0;");
}

// ---------------- filter vector c[n] ----------------
__global__ void filter_kernel(const int* __restrict__ li_p, const int* __restrict__ nl_p,
                              float* __restrict__ c, float* __restrict__ dcflag)
{
    int n = blockIdx.x * blockDim.x + threadIdx.x;
    if (n >= SQ) return;
    int li = *li_p;
    int nl = *nl_p;
    const double ALPHA = 0.5;
    int M = MFREQ;
    int p, q;
    if (ALPHA <= 1.0 / (double)nl) {
        p = (int)(M * (1.0 - (double)(li + 1) / (double)nl));
        q = (int)((double)p + (double)M / (double)nl);
    } else {
        p = (nl > 1) ? (int)(M * (1.0 - ALPHA) * (1.0 - (double)li / (double)(nl - 1))) : 0;
        q = (int)((double)p + ALPHA * (double)M);
    }
    p = max(0, min(p, M - 1));
    q = max(p + 1, min(q, M));

    double acc = 0.0;
    const double w2 = 2.0 / (double)SQ;
    const double w1 = 1.0 / (double)SQ;
    const double twopi_n_over_S = 6.283185307179586476925286766559 * (double)n / (double)SQ;
    for (int f = p; f < q; f++) {
        double wf = (f == 0 || f == M - 1) ? w1 : w2;
        acc += wf * cos(twopi_n_over_S * (double)f);
    }
    c[n] = (float)acc;
    if (n == 0) *dcflag = (p == 0) ? 1.0f : 0.0f;
}

// ---------------- circulant matrix ----------------
__global__ void cmat_kernel(float* __restrict__ Cm, const float* __restrict__ c)
{
    int idx = blockIdx.x * blockDim.x + threadIdx.x;   // 4M threads
    int t = idx >> 11;
    int s = idx & (SQ - 1);
    Cm[idx] = c[(t - s) & (SQ - 1)];
}

__global__ void zero_kernel(float* __restrict__ p, int n)
{
    int i = blockIdx.x * blockDim.x + threadIdx.x;
    if (i < n) p[i] = 0.f;
}

// ---------------- generic fp32 SGEMM: C = A@B (+ bias*scale) ----------------
// 128x128 tile, BK=8, 256 threads, 8x8 micro-tile, cp.async double buffer.
__global__ __launch_bounds__(256) void gemm_kernel(
    const float* __restrict__ A, const float* __restrict__ B,
    const float* __restrict__ bias, const float* __restrict__ bscalep,
    float* __restrict__ C,
    int M, int N, int K,
    long long sA, long long sB, long long sC)
{
    __shared__ float As[2][8 * 128];
    __shared__ float Bs[2][8 * 128];

    int z = blockIdx.z;
    A += (size_t)z * sA;
    B += (size_t)z * sB;
    C += (size_t)z * sC;

    int tid = threadIdx.x;
    int tx = tid & 15, ty = tid >> 4;
    int row0 = blockIdx.y * 128;
    int col0 = blockIdx.x * 128;

    int arow = tid >> 1;            // 0..127
    int acol = (tid & 1) << 2;      // 0 or 4
    int brow = tid >> 5;            // 0..7
    int bcol = (tid & 31) << 2;     // 0..124

    float acc[8][8];
#pragma unroll
    for (int i = 0; i < 8; i++)
#pragma unroll
        for (int j = 0; j < 8; j++) acc[i][j] = 0.f;

    const float* Aptr = A + (size_t)(row0 + arow) * K + acol;
    const float* Bptr = B + (size_t)brow * N + col0 + bcol;

    // ---- prologue: stage tile 0 into buffer 0 ----
    {
        float4 av = *(const float4*)(Aptr);
        cp_async16(&Bs[0][brow * 128 + bcol], Bptr);
        cp_commit();
        As[0][(acol + 0) * 128 + arow] = av.x;
        As[0][(acol + 1) * 128 + arow] = av.y;
        As[0][(acol + 2) * 128 + arow] = av.z;
        As[0][(acol + 3) * 128 + arow] = av.w;
        cp_wait0();
    }
    __syncthreads();

    int buf = 0;
    for (int k0 = 0; k0 < K; k0 += 8) {
        bool has_next = (k0 + 8) < K;
        float4 av2;
        if (has_next) {
            av2 = *(const float4*)(Aptr + k0 + 8);
            cp_async16(&Bs[buf ^ 1][brow * 128 + bcol], Bptr + (size_t)(k0 + 8) * N);
            cp_commit();
        }

        const float* Asb = As[buf];
        const float* Bsb = Bs[buf];
#pragma unroll
        for (int kk = 0; kk < 8; kk++) {
            float a[8], b[8];
            *(float4*)(a)     = *(float4*)&Asb[kk * 128 + ty * 8];
            *(float4*)(a + 4) = *(float4*)&Asb[kk * 128 + ty * 8 + 4];
            *(float4*)(b)     = *(float4*)&Bsb[kk * 128 + tx * 8];
            *(float4*)(b + 4) = *(float4*)&Bsb[kk * 128 + tx * 8 + 4];
#pragma unroll
            for (int i = 0; i < 8; i++)
#pragma unroll
                for (int j = 0; j < 8; j++) acc[i][j] += a[i] * b[j];
        }

        if (has_next) {
            As[buf ^ 1][(acol + 0) * 128 + arow] = av2.x;
            As[buf ^ 1][(acol + 1) * 128 + arow] = av2.y;
            As[buf ^ 1][(acol + 2) * 128 + arow] = av2.z;
            As[buf ^ 1][(acol + 3) * 128 + arow] = av2.w;
            cp_wait0();
            __syncthreads();
            buf ^= 1;
        }
    }

    float bscale = 0.f;
    if (bias) bscale = bscalep ? *bscalep : 1.f;

#pragma unroll
    for (int i = 0; i < 8; i++) {
        float out[8];
#pragma unroll
        for (int j = 0; j < 8; j++) {
            float v = acc[i][j];
            if (bias) v += bias[col0 + tx * 8 + j] * bscale;
            out[j] = v;
        }
        float* crow = C + (size_t)(row0 + ty * 8 + i) * N + col0 + tx * 8;
        *(float4*)(crow)     = *(float4*)(out);
        *(float4*)(crow + 4) = *(float4*)(out + 4);
    }
}

// ---------------- fused flash attention + autocorrelation diag-sums ----------------
// grid (32 qblocks, NH, BSZ), 256 threads, BM=BN=64, HD=64.
// dyn smem: Qt[64*64] | Kt[64*64] (reused as P^T) | Vs[64*64] | acb[2048]
__global__ __launch_bounds__(256) void flash_kernel(
    const float* __restrict__ Qf, const float* __restrict__ Kf,
    const float* __restrict__ Vf, const float* __restrict__ mask,
    float* __restrict__ Comb, float* __restrict__ ac)
{
    extern __shared__ float sm_[];
    float* Qt  = sm_;
    float* Kt  = sm_ + 4096;
    float* Vs  = sm_ + 8192;
    float* acb = sm_ + 12288;       // 2048 tau bins

    int tid = threadIdx.x;
    int tx = tid & 15, ty = tid >> 4;
    int qb = blockIdx.x, h = blockIdx.y, b = blockIdx.z;
    int t0 = qb * 64;

    const float* Qbase = Qf + (size_t)b * SQ * HID + h * HD;
    const float* Kbase = Kf + (size_t)b * SQ * HID + h * HD;
    const float* Vbase = Vf + (size_t)b * SQ * HID + h * HD;
    const float* Mbase = mask + (size_t)b * SQ * SQ;
    float* acrow = ac + (size_t)(b * NH + h) * SQ;

    // zero tau bins (whole-kernel accumulator)
    for (int i = tid; i < SQ; i += 256) acb[i] = 0.f;

    // Load Q tile transposed: Qt[d][row]
#pragma unroll
    for (int l = 0; l < 4; l++) {
        int id4 = tid + l * 256;
        int r = id4 >> 4;
        int cc = (id4 & 15) << 2;
        float4 v = *(const float4*)&Qbase[(size_t)(t0 + r) * HID + cc];
        Qt[(cc + 0) * 64 + r] = v.x;
        Qt[(cc + 1) * 64 + r] = v.y;
        Qt[(cc + 2) * 64 + r] = v.z;
        Qt[(cc + 3) * 64 + r] = v.w;
    }

    float m_run[4], l_run[4], o[4][4];
#pragma unroll
    for (int i = 0; i < 4; i++) {
        m_run[i] = -INFINITY;
        l_run[i] = 0.f;
#pragma unroll
        for (int j = 0; j < 4; j++) o[i][j] = 0.f;
    }

    for (int kt = 0; kt < SQ / 64; kt++) {
        int s0 = kt * 64;
        __syncthreads();                 // prev iter done with Kt/Vs (+ Qt/acb ready on iter 0)
        // Load K tile transposed (Kt[d][key]) and V tile (Vs[key][d])
#pragma unroll
        for (int l = 0; l < 4; l++) {
            int id4 = tid + l * 256;
            int r = id4 >> 4;
            int cc = (id4 & 15) << 2;
            float4 kv = *(const float4*)&Kbase[(size_t)(s0 + r) * HID + cc];
            Kt[(cc + 0) * 64 + r] = kv.x;
            Kt[(cc + 1) * 64 + r] = kv.y;
            Kt[(cc + 2) * 64 + r] = kv.z;
            Kt[(cc + 3) * 64 + r] = kv.w;
            float4 vv = *(const float4*)&Vbase[(size_t)(s0 + r) * HID + cc];
            *(float4*)&Vs[r * 64 + cc] = vv;
        }
        __syncthreads();

        // raw scores S = Q @ K^T (4x4 per thread)
        float sv[4][4];
#pragma unroll
        for (int i = 0; i < 4; i++)
#pragma unroll
            for (int j = 0; j < 4; j++) sv[i][j] = 0.f;
#pragma unroll 8
        for (int dd = 0; dd < 64; dd++) {
            float a[4], bb[4];
#pragma unroll
            for (int i = 0; i < 4; i++) a[i]  = Qt[dd * 64 + ty * 4 + i];
#pragma unroll
            for (int j = 0; j < 4; j++) bb[j] = Kt[dd * 64 + tx * 4 + j];
#pragma unroll
            for (int i = 0; i < 4; i++)
#pragma unroll
                for (int j = 0; j < 4; j++) sv[i][j] += a[i] * bb[j];
        }

        // autocorrelation: register-binned by (i-j), then 7 shared atomics.
        // tau = (t0+ty*4+i) - (s0+tx*4+j) mod S; 1/64 = mean over head dim.
        {
            float bins[7];
#pragma unroll
            for (int d = 0; d < 7; d++) bins[d] = 0.f;
#pragma unroll
            for (int i = 0; i < 4; i++)
#pragma unroll
                for (int j = 0; j < 4; j++) bins[i - j + 3] += sv[i][j];
            int taubase = t0 - s0 + (ty - tx) * 4 - 3;
#pragma unroll
            for (int d = 0; d < 7; d++)
                atomicAdd(&acb[(taubase + d) & (SQ - 1)], bins[d] * (1.f / 64.f));
        }

        // scale + mask + online softmax
        float p[4][4], corr[4];
#pragma unroll
        for (int i = 0; i < 4; i++) {
            float4 mrow = *(const float4*)&Mbase[(size_t)(t0 + ty * 4 + i) * SQ + s0 + tx * 4];
            float mv[4] = {mrow.x, mrow.y, mrow.z, mrow.w};
            float tm = -INFINITY;
#pragma unroll
            for (int j = 0; j < 4; j++) {
                sv[i][j] = sv[i][j] * 0.125f + mv[j];
                tm = fmaxf(tm, sv[i][j]);
            }
#pragma unroll
            for (int off = 8; off >= 1; off >>= 1)
                tm = fmaxf(tm, __shfl_xor_sync(0xffffffffu, tm, off, 16));
            float nm = fmaxf(m_run[i], tm);
            corr[i] = __expf(m_run[i] - nm);
            m_run[i] = nm;
            float rs = 0.f;
#pragma unroll
            for (int j = 0; j < 4; j++) {
                p[i][j] = __expf(sv[i][j] - nm);
                rs += p[i][j];
            }
#pragma unroll
            for (int off = 8; off >= 1; off >>= 1)
                rs += __shfl_xor_sync(0xffffffffu, rs, off, 16);
            l_run[i] = l_run[i] * corr[i] + rs;
#pragma unroll
            for (int j = 0; j < 4; j++) o[i][j] *= corr[i];
        }

        __syncthreads();                 // all S-reads of Kt finished
        // store P^T into Kt: Kt[key][row]
#pragma unroll
        for (int i = 0; i < 4; i++)
#pragma unroll
            for (int j = 0; j < 4; j++)
                Kt[(tx * 4 + j) * 64 + ty * 4 + i] = p[i][j];
        __syncthreads();

        // O += P @ V
#pragma unroll 8
        for (int jj = 0; jj < 64; jj++) {
            float a[4], bb[4];
#pragma unroll
            for (int i = 0; i < 4; i++) a[i]  = Kt[jj * 64 + ty * 4 + i];
#pragma unroll
            for (int j = 0; j < 4; j++) bb[j] = Vs[jj * 64 + tx * 4 + j];
#pragma unroll
            for (int i = 0; i < 4; i++)
#pragma unroll
                for (int j = 0; j < 4; j++) o[i][j] += a[i] * bb[j];
        }
    }

    // flush tau bins once
    __syncthreads();
    for (int i = tid; i < SQ; i += 256)
        atomicAdd(&acrow[i], acb[i]);

    // epilogue: Comb = GAMMA * time_ctx (GAMMA = 0.5)
    float* Crow = Comb + (size_t)b * SQ * HID + h * HD;
#pragma unroll
    for (int i = 0; i < 4; i++) {
        float inv = 0.5f / l_run[i];
        float out[4];
#pragma unroll
        for (int j = 0; j < 4; j++) out[j] = o[i][j] * inv;
        *(float4*)&Crow[(size_t)(t0 + ty * 4 + i) * HID + tx * 4] = *(float4*)out;
    }
}

// ---------------- top-k (k=15) + softmax weights ----------------
__global__ __launch_bounds__(256) void topk_kernel(
    const float* __restrict__ ac, int* __restrict__ topi, float* __restrict__ topw)
{
    int bh = blockIdx.x;
    __shared__ float svv[SQ];
    __shared__ float rv[256];
    __shared__ int ri[256];
    __shared__ float tvals[KTOP];
    __shared__ int tidxs[KTOP];
    int tid = threadIdx.x;

    // ac already holds mean over head dim (flash applied 1/64) — NO extra scale
    for (int i = tid; i < SQ; i += 256)
        svv[i] = ac[(size_t)bh * SQ + i];
    __syncthreads();

    for (int t = 0; t < KTOP; t++) {
        float bv = -INFINITY;
        int bi = 0;
        for (int i = tid; i < SQ; i += 256) {
            float v = svv[i];
            if (v > bv || (v == bv && i < bi)) { bv = v; bi = i; }
        }
        rv[tid] = bv; ri[tid] = bi;
        __syncthreads();
        for (int st = 128; st > 0; st >>= 1) {
            if (tid < st) {
                float v2 = rv[tid + st]; int i2 = ri[tid + st];
                if (v2 > rv[tid] || (v2 == rv[tid] && i2 < ri[tid])) { rv[tid] = v2; ri[tid] = i2; }
            }
            __syncthreads();
        }
        if (tid == 0) {
            tvals[t] = rv[0]; tidxs[t] = ri[0];
            svv[ri[0]] = -INFINITY;
        }
        __syncthreads();
    }

    if (tid == 0) {
        float mx = tvals[0];
        float e[KTOP], ssum = 0.f;
#pragma unroll
        for (int t = 0; t < KTOP; t++) { e[t] = __expf(tvals[t] - mx); ssum += e[t]; }
        float inv = 1.f / ssum;
#pragma unroll
        for (int t = 0; t < KTOP; t++) {
            topw[bh * KTOP + t] = e[t] * inv;
            topi[bh * KTOP + t] = tidxs[t];
        }
    }
}

// ---------------- frequency branch gather: Comb += (1-GAMMA) * freq_ctx ----------------
__global__ __launch_bounds__(256) void freq_kernel(
    const float* __restrict__ V, const int* __restrict__ topi,
    const float* __restrict__ topw, float* __restrict__ Comb)
{
    int t = blockIdx.x, b = blockIdx.y;
    __shared__ int si[NH * KTOP];
    __shared__ float sw[NH * KTOP];
    int tid = threadIdx.x;
    if (tid < NH * KTOP) {
        si[tid] = topi[b * NH * KTOP + tid];
        sw[tid] = topw[b * NH * KTOP + tid];
    }
    __syncthreads();

    int c = tid * 4;
    int h = c >> 6;
    float* crow = Comb + ((size_t)b * SQ + t) * HID + c;
    float4 acc = *(float4*)crow;
    const float* Vb = V + (size_t)b * SQ * HID;
#pragma unroll
    for (int j = 0; j < KTOP; j++) {
        int row = (t + si[h * KTOP + j]) & (SQ - 1);
        float w = 0.5f * sw[h * KTOP + j];
        float4 v = *(const float4*)&Vb[(size_t)row * HID + c];
        acc.x += w * v.x; acc.y += w * v.y; acc.z += w * v.z; acc.w += w * v.w;
    }
    *(float4*)crow = acc;
}

// ---------------- launcher ----------------
extern "C" void kernel_launch(void* const* d_in, const int* in_sizes, int n_in,
                              void* d_out, int out_size)
{
    const float* X    = (const float*)d_in[0];
    const float* mask = (const float*)d_in[1];
    const float* Wq   = (const float*)d_in[2];
    const float* bq   = (const float*)d_in[3];
    const float* Wk   = (const float*)d_in[4];
    const float* bk   = (const float*)d_in[5];
    const float* Wv   = (const float*)d_in[6];
    const float* bv   = (const float*)d_in[7];
    const float* Wo   = (const float*)d_in[8];
    const float* bo   = (const float*)d_in[9];
    const int*   li   = (const int*)d_in[10];
    const int*   nl   = (const int*)d_in[11];
    float* out = (float*)d_out;

    float *cP, *dcP, *CmP, *XfP, *QfP, *KfP, *VfP, *VbP, *CbP, *acP, *twP;
    int* tiP;
    cudaGetSymbolAddress((void**)&cP,  d_c);
    cudaGetSymbolAddress((void**)&dcP, d_dcflag);
    cudaGetSymbolAddress((void**)&CmP, d_Cmat);
    cudaGetSymbolAddress((void**)&XfP, d_Xf);
    cudaGetSymbolAddress((void**)&QfP, d_Qfil);
    cudaGetSymbolAddress((void**)&KfP, d_Kfil);
    cudaGetSymbolAddress((void**)&VfP, d_Vfil);
    cudaGetSymbolAddress((void**)&VbP, d_Vbuf);
    cudaGetSymbolAddress((void**)&CbP, d_Comb);
    cudaGetSymbolAddress((void**)&acP, d_ac);
    cudaGetSymbolAddress((void**)&tiP, d_topi);
    cudaGetSymbolAddress((void**)&twP, d_topw);

    const long long SH = (long long)SQ * HID;

    // 1) filter taps + circulant matrix
    filter_kernel<<<8, 256>>>(li, nl, cP, dcP);
    cmat_kernel<<<(SQ * SQ) / 256, 256>>>(CmP, cP);

    // 2) Xf = C @ X  (per batch)
    gemm_kernel<<<dim3(HID / 128, SQ / 128, BSZ), 256>>>(
        CmP, X, nullptr, nullptr, XfP, SQ, HID, SQ, 0, SH, SH);

    // 3) filtered projections (bias only if DC in band)
    gemm_kernel<<<dim3(HID / 128, SQ / 128, BSZ), 256>>>(
        XfP, Wq, bq, dcP, QfP, SQ, HID, HID, SH, 0, SH);
    gemm_kernel<<<dim3(HID / 128, SQ / 128, BSZ), 256>>>(
        XfP, Wk, bk, dcP, KfP, SQ, HID, HID, SH, 0, SH);
    gemm_kernel<<<dim3(HID / 128, SQ / 128, BSZ), 256>>>(
        XfP, Wv, bv, dcP, VfP, SQ, HID, HID, SH, 0, SH);

    // 4) unfiltered V (freq branch)
    gemm_kernel<<<dim3(HID / 128, SQ / 128, BSZ), 256>>>(
        X, Wv, bv, nullptr, VbP, SQ, HID, HID, SH, 0, SH);

    // 5) flash attention + autocorrelation diag sums
    zero_kernel<<<(BSZ * NH * SQ) / 256, 256>>>(acP, BSZ * NH * SQ);
    cudaFuncSetAttribute(flash_kernel, cudaFuncAttributeMaxDynamicSharedMemorySize, 57344);
    flash_kernel<<<dim3(SQ / 64, NH, BSZ), 256, 57344>>>(QfP, KfP, VfP, mask, CbP, acP);

    // 6) top-k weights + frequency gather
    topk_kernel<<<BSZ * NH, 256>>>(acP, tiP, twP);
    freq_kernel<<<dim3(SQ, BSZ), 256>>>(VbP, tiP, twP, CbP);

    // 7) output projection
    gemm_kernel<<<dim3(HID / 128, (BSZ * SQ) / 128, 1), 256>>>(
        CbP, Wo, bo, nullptr, out, BSZ * SQ, HID, HID, 0, 0, 0);
}

// round 4
// speedup vs baseline: 1.1221x; 1.0909x over previous
#include <cuda_runtime.h>
#include <math.h>

#define SQ   2048
#define HID  1024
#define NH   16
#define HD   64
#define BSZ  2
#define MFREQ (SQ/2 + 1)
#define KTOP 15   // int(2*ln(2049)) = 15 for S=2048

// ---------------- scratch (static device allocations) ----------------
__device__ float d_c[SQ];
__device__ float d_dcflag;
__device__ float d_Cmat[SQ * SQ];
__device__ float d_Xf  [BSZ * SQ * HID];
__device__ float d_Qfil[BSZ * SQ * HID];
__device__ float d_Kfil[BSZ * SQ * HID];
__device__ float d_Vfil[BSZ * SQ * HID];
__device__ float d_Vbuf[BSZ * SQ * HID];
__device__ float d_Comb[BSZ * SQ * HID];
__device__ float d_ac  [BSZ * NH * SQ];
__device__ int   d_topi[BSZ * NH * KTOP];
__device__ float d_topw[BSZ * NH * KTOP];

// ---------------- cp.async helpers ----------------
__device__ __forceinline__ void cp_async16(void* smem, const void* gmem) {
    unsigned s = (unsigned)__cvta_generic_to_shared(smem);
    asm volatile("cp.async.cg.shared.global [%0], [%1], 16;" :: "r"(s), "l"(gmem));
}
__device__ __forceinline__ void cp_commit() {
    asm volatile("cp.async.commit_group;");
}
__device__ __forceinline__ void cp_wait0() {
    asm volatile("cp.async.wait_group 0;");
}

// ---------------- filter vector c[n] ----------------
__global__ void filter_kernel(const int* __restrict__ li_p, const int* __restrict__ nl_p,
                              float* __restrict__ c, float* __restrict__ dcflag)
{
    int n = blockIdx.x * blockDim.x + threadIdx.x;
    if (n >= SQ) return;
    int li = *li_p;
    int nl = *nl_p;
    const double ALPHA = 0.5;
    int M = MFREQ;
    int p, q;
    if (ALPHA <= 1.0 / (double)nl) {
        p = (int)(M * (1.0 - (double)(li + 1) / (double)nl));
        q = (int)((double)p + (double)M / (double)nl);
    } else {
        p = (nl > 1) ? (int)(M * (1.0 - ALPHA) * (1.0 - (double)li / (double)(nl - 1))) : 0;
        q = (int)((double)p + ALPHA * (double)M);
    }
    p = max(0, min(p, M - 1));
    q = max(p + 1, min(q, M));

    double acc = 0.0;
    const double w2 = 2.0 / (double)SQ;
    const double w1 = 1.0 / (double)SQ;
    const double twopi_n_over_S = 6.283185307179586476925286766559 * (double)n / (double)SQ;
    for (int f = p; f < q; f++) {
        double wf = (f == 0 || f == M - 1) ? w1 : w2;
        acc += wf * cos(twopi_n_over_S * (double)f);
    }
    c[n] = (float)acc;
    if (n == 0) *dcflag = (p == 0) ? 1.0f : 0.0f;
}

// ---------------- circulant matrix ----------------
__global__ void cmat_kernel(float* __restrict__ Cm, const float* __restrict__ c)
{
    int idx = blockIdx.x * blockDim.x + threadIdx.x;   // 4M threads
    int t = idx >> 11;
    int s = idx & (SQ - 1);
    Cm[idx] = c[(t - s) & (SQ - 1)];
}

__global__ void zero_kernel(float* __restrict__ p, int n)
{
    int i = blockIdx.x * blockDim.x + threadIdx.x;
    if (i < n) p[i] = 0.f;
}

// ---------------- generic fp32 SGEMM: C = A@B (+ bias*scale) ----------------
// 128x128 tile, BK=8, 256 threads, 8x8 micro-tile, cp.async double buffer.
__global__ __launch_bounds__(256) void gemm_kernel(
    const float* __restrict__ A, const float* __restrict__ B,
    const float* __restrict__ bias, const float* __restrict__ bscalep,
    float* __restrict__ C,
    int M, int N, int K,
    long long sA, long long sB, long long sC)
{
    __shared__ float As[2][8 * 128];
    __shared__ float Bs[2][8 * 128];

    int z = blockIdx.z;
    A += (size_t)z * sA;
    B += (size_t)z * sB;
    C += (size_t)z * sC;

    int tid = threadIdx.x;
    int tx = tid & 15, ty = tid >> 4;
    int row0 = blockIdx.y * 128;
    int col0 = blockIdx.x * 128;

    int arow = tid >> 1;            // 0..127
    int acol = (tid & 1) << 2;      // 0 or 4
    int brow = tid >> 5;            // 0..7
    int bcol = (tid & 31) << 2;     // 0..124

    float acc[8][8];
#pragma unroll
    for (int i = 0; i < 8; i++)
#pragma unroll
        for (int j = 0; j < 8; j++) acc[i][j] = 0.f;

    const float* Aptr = A + (size_t)(row0 + arow) * K + acol;
    const float* Bptr = B + (size_t)brow * N + col0 + bcol;

    // ---- prologue: stage tile 0 into buffer 0 ----
    {
        float4 av = *(const float4*)(Aptr);
        cp_async16(&Bs[0][brow * 128 + bcol], Bptr);
        cp_commit();
        As[0][(acol + 0) * 128 + arow] = av.x;
        As[0][(acol + 1) * 128 + arow] = av.y;
        As[0][(acol + 2) * 128 + arow] = av.z;
        As[0][(acol + 3) * 128 + arow] = av.w;
        cp_wait0();
    }
    __syncthreads();

    int buf = 0;
    for (int k0 = 0; k0 < K; k0 += 8) {
        bool has_next = (k0 + 8) < K;
        float4 av2;
        if (has_next) {
            av2 = *(const float4*)(Aptr + k0 + 8);
            cp_async16(&Bs[buf ^ 1][brow * 128 + bcol], Bptr + (size_t)(k0 + 8) * N);
            cp_commit();
        }

        const float* Asb = As[buf];
        const float* Bsb = Bs[buf];
#pragma unroll
        for (int kk = 0; kk < 8; kk++) {
            float a[8], b[8];
            *(float4*)(a)     = *(float4*)&Asb[kk * 128 + ty * 8];
            *(float4*)(a + 4) = *(float4*)&Asb[kk * 128 + ty * 8 + 4];
            *(float4*)(b)     = *(float4*)&Bsb[kk * 128 + tx * 8];
            *(float4*)(b + 4) = *(float4*)&Bsb[kk * 128 + tx * 8 + 4];
#pragma unroll
            for (int i = 0; i < 8; i++)
#pragma unroll
                for (int j = 0; j < 8; j++) acc[i][j] += a[i] * b[j];
        }

        if (has_next) {
            As[buf ^ 1][(acol + 0) * 128 + arow] = av2.x;
            As[buf ^ 1][(acol + 1) * 128 + arow] = av2.y;
            As[buf ^ 1][(acol + 2) * 128 + arow] = av2.z;
            As[buf ^ 1][(acol + 3) * 128 + arow] = av2.w;
            cp_wait0();
            __syncthreads();
            buf ^= 1;
        }
    }

    float bscale = 0.f;
    if (bias) bscale = bscalep ? *bscalep : 1.f;

#pragma unroll
    for (int i = 0; i < 8; i++) {
        float out[8];
#pragma unroll
        for (int j = 0; j < 8; j++) {
            float v = acc[i][j];
            if (bias) v += bias[col0 + tx * 8 + j] * bscale;
            out[j] = v;
        }
        float* crow = C + (size_t)(row0 + ty * 8 + i) * N + col0 + tx * 8;
        *(float4*)(crow)     = *(float4*)(out);
        *(float4*)(crow + 4) = *(float4*)(out + 4);
    }
}

// ---------------- fused flash attention + autocorrelation diag-sums ----------------
// grid (32 qblocks, NH, BSZ), 256 threads, BM=BN=64, HD=64.
// Padded stride-65 transposed tiles kill the 16-way STS bank conflicts.
// dyn smem: Qt[65*64] | Kt[65*64] | Vs[64*64] | Pt[65*64] | acb[2048]
#define QTS 65
__global__ __launch_bounds__(256) void flash_kernel(
    const float* __restrict__ Qf, const float* __restrict__ Kf,
    const float* __restrict__ Vf, const float* __restrict__ mask,
    float* __restrict__ Comb, float* __restrict__ ac)
{
    extern __shared__ float sm_[];
    float* Qt  = sm_;                      // [64 d][64 row] stride 65
    float* Kt  = sm_ + 4160;               // [64 d][64 key] stride 65
    float* Vs  = sm_ + 8320;               // [64 key][64 d] stride 64
    float* Pt  = sm_ + 12416;              // [64 key][64 row] stride 65
    float* acb = sm_ + 16576;              // 2048 tau bins

    int tid = threadIdx.x;
    int tx = tid & 15, ty = tid >> 4;
    int qb = blockIdx.x, h = blockIdx.y, b = blockIdx.z;
    int t0 = qb * 64;

    const float* Qbase = Qf + (size_t)b * SQ * HID + h * HD;
    const float* Kbase = Kf + (size_t)b * SQ * HID + h * HD;
    const float* Vbase = Vf + (size_t)b * SQ * HID + h * HD;
    const float* Mbase = mask + (size_t)b * SQ * SQ;
    float* acrow = ac + (size_t)(b * NH + h) * SQ;

    // zero tau bins (whole-kernel accumulator)
    for (int i = tid; i < SQ; i += 256) acb[i] = 0.f;

    // Load Q tile transposed: Qt[d][row], stride 65
#pragma unroll
    for (int l = 0; l < 4; l++) {
        int id4 = tid + l * 256;
        int r = id4 >> 4;
        int cc = (id4 & 15) << 2;
        float4 v = *(const float4*)&Qbase[(size_t)(t0 + r) * HID + cc];
        Qt[(cc + 0) * QTS + r] = v.x;
        Qt[(cc + 1) * QTS + r] = v.y;
        Qt[(cc + 2) * QTS + r] = v.z;
        Qt[(cc + 3) * QTS + r] = v.w;
    }

    float m_run[4], l_run[4], o[4][4];
#pragma unroll
    for (int i = 0; i < 4; i++) {
        m_run[i] = -INFINITY;
        l_run[i] = 0.f;
#pragma unroll
        for (int j = 0; j < 4; j++) o[i][j] = 0.f;
    }

    for (int kt = 0; kt < SQ / 64; kt++) {
        int s0 = kt * 64;
        __syncthreads();     // prev iter's PV reads of Pt/Vs done; Qt/acb ready on iter 0
        // Load K tile transposed (Kt[d][key], stride 65) and V tile (Vs[key][d])
#pragma unroll
        for (int l = 0; l < 4; l++) {
            int id4 = tid + l * 256;
            int r = id4 >> 4;
            int cc = (id4 & 15) << 2;
            float4 kv = *(const float4*)&Kbase[(size_t)(s0 + r) * HID + cc];
            Kt[(cc + 0) * QTS + r] = kv.x;
            Kt[(cc + 1) * QTS + r] = kv.y;
            Kt[(cc + 2) * QTS + r] = kv.z;
            Kt[(cc + 3) * QTS + r] = kv.w;
            float4 vv = *(const float4*)&Vbase[(size_t)(s0 + r) * HID + cc];
            *(float4*)&Vs[r * 64 + cc] = vv;
        }
        __syncthreads();

        // raw scores S = Q @ K^T (4x4 per thread)
        float sv[4][4];
#pragma unroll
        for (int i = 0; i < 4; i++)
#pragma unroll
            for (int j = 0; j < 4; j++) sv[i][j] = 0.f;
#pragma unroll 8
        for (int dd = 0; dd < 64; dd++) {
            float a[4], bb[4];
#pragma unroll
            for (int i = 0; i < 4; i++) a[i]  = Qt[dd * QTS + ty * 4 + i];
#pragma unroll
            for (int j = 0; j < 4; j++) bb[j] = Kt[dd * QTS + tx * 4 + j];
#pragma unroll
            for (int i = 0; i < 4; i++)
#pragma unroll
                for (int j = 0; j < 4; j++) sv[i][j] += a[i] * bb[j];
        }

        // autocorrelation: register-binned by (i-j), then 7 shared atomics.
        // tau = (t0+ty*4+i) - (s0+tx*4+j) mod S; 1/64 = mean over head dim.
        {
            float bins[7];
#pragma unroll
            for (int d = 0; d < 7; d++) bins[d] = 0.f;
#pragma unroll
            for (int i = 0; i < 4; i++)
#pragma unroll
                for (int j = 0; j < 4; j++) bins[i - j + 3] += sv[i][j];
            int taubase = t0 - s0 + (ty - tx) * 4 - 3;
#pragma unroll
            for (int d = 0; d < 7; d++)
                atomicAdd(&acb[(taubase + d) & (SQ - 1)], bins[d] * (1.f / 64.f));
        }

        // scale + mask + online softmax
        float p[4][4], corr[4];
#pragma unroll
        for (int i = 0; i < 4; i++) {
            float4 mrow = *(const float4*)&Mbase[(size_t)(t0 + ty * 4 + i) * SQ + s0 + tx * 4];
            float mv[4] = {mrow.x, mrow.y, mrow.z, mrow.w};
            float tm = -INFINITY;
#pragma unroll
            for (int j = 0; j < 4; j++) {
                sv[i][j] = sv[i][j] * 0.125f + mv[j];
                tm = fmaxf(tm, sv[i][j]);
            }
#pragma unroll
            for (int off = 8; off >= 1; off >>= 1)
                tm = fmaxf(tm, __shfl_xor_sync(0xffffffffu, tm, off, 16));
            float nm = fmaxf(m_run[i], tm);
            corr[i] = __expf(m_run[i] - nm);
            m_run[i] = nm;
            float rs = 0.f;
#pragma unroll
            for (int j = 0; j < 4; j++) {
                p[i][j] = __expf(sv[i][j] - nm);
                rs += p[i][j];
            }
#pragma unroll
            for (int off = 8; off >= 1; off >>= 1)
                rs += __shfl_xor_sync(0xffffffffu, rs, off, 16);
            l_run[i] = l_run[i] * corr[i] + rs;
#pragma unroll
            for (int j = 0; j < 4; j++) o[i][j] *= corr[i];
        }

        // store P^T into Pt[key][row] (stride 65) — no pre-sync needed:
        // prev-iter PV reads of Pt were fenced by this iter's top sync.
#pragma unroll
        for (int i = 0; i < 4; i++)
#pragma unroll
            for (int j = 0; j < 4; j++)
                Pt[(tx * 4 + j) * QTS + ty * 4 + i] = p[i][j];
        __syncthreads();

        // O += P @ V
#pragma unroll 8
        for (int jj = 0; jj < 64; jj++) {
            float a[4], bb[4];
#pragma unroll
            for (int i = 0; i < 4; i++) a[i]  = Pt[jj * QTS + ty * 4 + i];
#pragma unroll
            for (int j = 0; j < 4; j++) bb[j] = Vs[jj * 64 + tx * 4 + j];
#pragma unroll
            for (int i = 0; i < 4; i++)
#pragma unroll
                for (int j = 0; j < 4; j++) o[i][j] += a[i] * bb[j];
        }
    }

    // flush tau bins once
    __syncthreads();
    for (int i = tid; i < SQ; i += 256)
        atomicAdd(&acrow[i], acb[i]);

    // epilogue: Comb = GAMMA * time_ctx (GAMMA = 0.5)
    float* Crow = Comb + (size_t)b * SQ * HID + h * HD;
#pragma unroll
    for (int i = 0; i < 4; i++) {
        float inv = 0.5f / l_run[i];
        float out[4];
#pragma unroll
        for (int j = 0; j < 4; j++) out[j] = o[i][j] * inv;
        *(float4*)&Crow[(size_t)(t0 + ty * 4 + i) * HID + tx * 4] = *(float4*)out;
    }
}

// ---------------- top-k (k=15) + softmax weights ----------------
__global__ __launch_bounds__(256) void topk_kernel(
    const float* __restrict__ ac, int* __restrict__ topi, float* __restrict__ topw)
{
    int bh = blockIdx.x;
    __shared__ float svv[SQ];
    __shared__ float rv[256];
    __shared__ int ri[256];
    __shared__ float tvals[KTOP];
    __shared__ int tidxs[KTOP];
    int tid = threadIdx.x;

    // ac already holds mean over head dim (flash applied 1/64) — NO extra scale
    for (int i = tid; i < SQ; i += 256)
        svv[i] = ac[(size_t)bh * SQ + i];
    __syncthreads();

    for (int t = 0; t < KTOP; t++) {
        float bv = -INFINITY;
        int bi = 0;
        for (int i = tid; i < SQ; i += 256) {
            float v = svv[i];
            if (v > bv || (v == bv && i < bi)) { bv = v; bi = i; }
        }
        rv[tid] = bv; ri[tid] = bi;
        __syncthreads();
        for (int st = 128; st > 0; st >>= 1) {
            if (tid < st) {
                float v2 = rv[tid + st]; int i2 = ri[tid + st];
                if (v2 > rv[tid] || (v2 == rv[tid] && i2 < ri[tid])) { rv[tid] = v2; ri[tid] = i2; }
            }
            __syncthreads();
        }
        if (tid == 0) {
            tvals[t] = rv[0]; tidxs[t] = ri[0];
            svv[ri[0]] = -INFINITY;
        }
        __syncthreads();
    }

    if (tid == 0) {
        float mx = tvals[0];
        float e[KTOP], ssum = 0.f;
#pragma unroll
        for (int t = 0; t < KTOP; t++) { e[t] = __expf(tvals[t] - mx); ssum += e[t]; }
        float inv = 1.f / ssum;
#pragma unroll
        for (int t = 0; t < KTOP; t++) {
            topw[bh * KTOP + t] = e[t] * inv;
            topi[bh * KTOP + t] = tidxs[t];
        }
    }
}

// ---------------- frequency branch gather: Comb += (1-GAMMA) * freq_ctx ----------------
__global__ __launch_bounds__(256) void freq_kernel(
    const float* __restrict__ V, const int* __restrict__ topi,
    const float* __restrict__ topw, float* __restrict__ Comb)
{
    int t = blockIdx.x, b = blockIdx.y;
    __shared__ int si[NH * KTOP];
    __shared__ float sw[NH * KTOP];
    int tid = threadIdx.x;
    if (tid < NH * KTOP) {
        si[tid] = topi[b * NH * KTOP + tid];
        sw[tid] = topw[b * NH * KTOP + tid];
    }
    __syncthreads();

    int c = tid * 4;
    int h = c >> 6;
    float* crow = Comb + ((size_t)b * SQ + t) * HID + c;
    float4 acc = *(float4*)crow;
    const float* Vb = V + (size_t)b * SQ * HID;
#pragma unroll
    for (int j = 0; j < KTOP; j++) {
        int row = (t + si[h * KTOP + j]) & (SQ - 1);
        float w = 0.5f * sw[h * KTOP + j];
        float4 v = *(const float4*)&Vb[(size_t)row * HID + c];
        acc.x += w * v.x; acc.y += w * v.y; acc.z += w * v.z; acc.w += w * v.w;
    }
    *(float4*)crow = acc;
}

// ---------------- launcher ----------------
extern "C" void kernel_launch(void* const* d_in, const int* in_sizes, int n_in,
                              void* d_out, int out_size)
{
    const float* X    = (const float*)d_in[0];
    const float* mask = (const float*)d_in[1];
    const float* Wq   = (const float*)d_in[2];
    const float* bq   = (const float*)d_in[3];
    const float* Wk   = (const float*)d_in[4];
    const float* bk   = (const float*)d_in[5];
    const float* Wv   = (const float*)d_in[6];
    const float* bv   = (const float*)d_in[7];
    const float* Wo   = (const float*)d_in[8];
    const float* bo   = (const float*)d_in[9];
    const int*   li   = (const int*)d_in[10];
    const int*   nl   = (const int*)d_in[11];
    float* out = (float*)d_out;

    float *cP, *dcP, *CmP, *XfP, *QfP, *KfP, *VfP, *VbP, *CbP, *acP, *twP;
    int* tiP;
    cudaGetSymbolAddress((void**)&cP,  d_c);
    cudaGetSymbolAddress((void**)&dcP, d_dcflag);
    cudaGetSymbolAddress((void**)&CmP, d_Cmat);
    cudaGetSymbolAddress((void**)&XfP, d_Xf);
    cudaGetSymbolAddress((void**)&QfP, d_Qfil);
    cudaGetSymbolAddress((void**)&KfP, d_Kfil);
    cudaGetSymbolAddress((void**)&VfP, d_Vfil);
    cudaGetSymbolAddress((void**)&VbP, d_Vbuf);
    cudaGetSymbolAddress((void**)&CbP, d_Comb);
    cudaGetSymbolAddress((void**)&acP, d_ac);
    cudaGetSymbolAddress((void**)&tiP, d_topi);
    cudaGetSymbolAddress((void**)&twP, d_topw);

    const long long SH = (long long)SQ * HID;

    // 1) filter taps + circulant matrix
    filter_kernel<<<8, 256>>>(li, nl, cP, dcP);
    cmat_kernel<<<(SQ * SQ) / 256, 256>>>(CmP, cP);

    // 2) Xf = C @ X  (per batch)
    gemm_kernel<<<dim3(HID / 128, SQ / 128, BSZ), 256>>>(
        CmP, X, nullptr, nullptr, XfP, SQ, HID, SQ, 0, SH, SH);

    // 3) filtered projections (bias only if DC in band)
    gemm_kernel<<<dim3(HID / 128, SQ / 128, BSZ), 256>>>(
        XfP, Wq, bq, dcP, QfP, SQ, HID, HID, SH, 0, SH);
    gemm_kernel<<<dim3(HID / 128, SQ / 128, BSZ), 256>>>(
        XfP, Wk, bk, dcP, KfP, SQ, HID, HID, SH, 0, SH);
    gemm_kernel<<<dim3(HID / 128, SQ / 128, BSZ), 256>>>(
        XfP, Wv, bv, dcP, VfP, SQ, HID, HID, SH, 0, SH);

    // 4) unfiltered V (freq branch)
    gemm_kernel<<<dim3(HID / 128, SQ / 128, BSZ), 256>>>(
        X, Wv, bv, nullptr, VbP, SQ, HID, HID, SH, 0, SH);

    // 5) flash attention + autocorrelation diag sums
    zero_kernel<<<(BSZ * NH * SQ) / 256, 256>>>(acP, BSZ * NH * SQ);
    cudaFuncSetAttribute(flash_kernel, cudaFuncAttributeMaxDynamicSharedMemorySize, 75776);
    flash_kernel<<<dim3(SQ / 64, NH, BSZ), 256, 75776>>>(QfP, KfP, VfP, mask, CbP, acP);

    // 6) top-k weights + frequency gather
    topk_kernel<<<BSZ * NH, 256>>>(acP, tiP, twP);
    freq_kernel<<<dim3(SQ, BSZ), 256>>>(VbP, tiP, twP, CbP);

    // 7) output projection
    gemm_kernel<<<dim3(HID / 128, (BSZ * SQ) / 128, 1), 256>>>(
        CbP, Wo, bo, nullptr, out, BSZ * SQ, HID, HID, 0, 0, 0);
}

// round 5
// speedup vs baseline: 1.4954x; 1.3327x over previous
#include <cuda_runtime.h>
#include <cuda_bf16.h>
#include <math.h>
#include <stdint.h>

#define SQ   2048
#define HID  1024
#define NH   16
#define HD   64
#define BSZ  2
#define MFREQ (SQ/2 + 1)
#define KTOP 15   // int(2*ln(2049)) = 15 for S=2048

// ---------------- scratch (static device allocations) ----------------
__device__ float d_c[SQ];
__device__ float d_dcflag;
__device__ float d_Xf  [BSZ * SQ * HID];
__device__ float d_Qfil[BSZ * SQ * HID];
__device__ float d_Kfil[BSZ * SQ * HID];
__device__ float d_Vfil[BSZ * SQ * HID];
__device__ float d_Vbuf[BSZ * SQ * HID];
__device__ float d_Comb[BSZ * SQ * HID];
__device__ float d_ac  [BSZ * NH * SQ];
__device__ int   d_topi[BSZ * NH * KTOP];
__device__ float d_topw[BSZ * NH * KTOP];

// bf16 split operands
__device__ __nv_bfloat16 d_chi[SQ], d_clo[SQ];
__device__ __nv_bfloat16 d_Chi [SQ * SQ],        d_Clo [SQ * SQ];
__device__ __nv_bfloat16 d_Xhi [BSZ * SQ * HID], d_Xlo [BSZ * SQ * HID];
__device__ __nv_bfloat16 d_Xfhi[BSZ * SQ * HID], d_Xflo[BSZ * SQ * HID];
__device__ __nv_bfloat16 d_Cbhi[BSZ * SQ * HID], d_Cblo[BSZ * SQ * HID];
__device__ __nv_bfloat16 d_Wqhi[HID * HID], d_Wqlo[HID * HID];
__device__ __nv_bfloat16 d_Wkhi[HID * HID], d_Wklo[HID * HID];
__device__ __nv_bfloat16 d_Wvhi[HID * HID], d_Wvlo[HID * HID];
__device__ __nv_bfloat16 d_Wohi[HID * HID], d_Wolo[HID * HID];

// ---------------- cp.async helpers ----------------
__device__ __forceinline__ void cp_async16(void* smem, const void* gmem) {
    unsigned s = (unsigned)__cvta_generic_to_shared(smem);
    asm volatile("cp.async.cg.shared.global [%0], [%1], 16;" :: "r"(s), "l"(gmem));
}
__device__ __forceinline__ void cp_commit() {
    asm volatile("cp.async.commit_group;");
}
__device__ __forceinline__ void cp_wait0() {
    asm volatile("cp.async.wait_group 0;");
}

// ---------------- mma / ldmatrix helpers ----------------
__device__ __forceinline__ void mma16816(float* d, const uint32_t* a, const uint32_t* b) {
    asm volatile(
        "mma.sync.aligned.m16n8k16.row.col.f32.bf16.bf16.f32 "
        "{%0,%1,%2,%3}, {%4,%5,%6,%7}, {%8,%9}, {%0,%1,%2,%3};"
        : "+f"(d[0]), "+f"(d[1]), "+f"(d[2]), "+f"(d[3])
        : "r"(a[0]), "r"(a[1]), "r"(a[2]), "r"(a[3]), "r"(b[0]), "r"(b[1]));
}
__device__ __forceinline__ void ldsm_x4(uint32_t* r, uint32_t addr) {
    asm volatile("ldmatrix.sync.aligned.m8n8.x4.shared.b16 {%0,%1,%2,%3}, [%4];"
        : "=r"(r[0]), "=r"(r[1]), "=r"(r[2]), "=r"(r[3]) : "r"(addr));
}
__device__ __forceinline__ void ldsm_x2t(uint32_t* r, uint32_t addr) {
    asm volatile("ldmatrix.sync.aligned.m8n8.x2.trans.shared.b16 {%0,%1}, [%2];"
        : "=r"(r[0]), "=r"(r[1]) : "r"(addr));
}

// ---------------- filter vector c[n] (+ bf16 split taps) ----------------
__global__ void filter_kernel(const int* __restrict__ li_p, const int* __restrict__ nl_p,
                              float* __restrict__ c, float* __restrict__ dcflag,
                              __nv_bfloat16* __restrict__ chi, __nv_bfloat16* __restrict__ clo)
{
    int n = blockIdx.x * blockDim.x + threadIdx.x;
    if (n >= SQ) return;
    int li = *li_p;
    int nl = *nl_p;
    const double ALPHA = 0.5;
    int M = MFREQ;
    int p, q;
    if (ALPHA <= 1.0 / (double)nl) {
        p = (int)(M * (1.0 - (double)(li + 1) / (double)nl));
        q = (int)((double)p + (double)M / (double)nl);
    } else {
        p = (nl > 1) ? (int)(M * (1.0 - ALPHA) * (1.0 - (double)li / (double)(nl - 1))) : 0;
        q = (int)((double)p + ALPHA * (double)M);
    }
    p = max(0, min(p, M - 1));
    q = max(p + 1, min(q, M));

    double acc = 0.0;
    const double w2 = 2.0 / (double)SQ;
    const double w1 = 1.0 / (double)SQ;
    const double twopi_n_over_S = 6.283185307179586476925286766559 * (double)n / (double)SQ;
    for (int f = p; f < q; f++) {
        double wf = (f == 0 || f == M - 1) ? w1 : w2;
        acc += wf * cos(twopi_n_over_S * (double)f);
    }
    float cf = (float)acc;
    c[n] = cf;
    __nv_bfloat16 h = __float2bfloat16_rn(cf);
    chi[n] = h;
    clo[n] = __float2bfloat16_rn(cf - __bfloat162float(h));
    if (n == 0) *dcflag = (p == 0) ? 1.0f : 0.0f;
}

// ---------------- circulant matrix (bf16 hi/lo) ----------------
__global__ void cmat_kernel(__nv_bfloat16* __restrict__ Chi, __nv_bfloat16* __restrict__ Clo,
                            const __nv_bfloat16* __restrict__ chi, const __nv_bfloat16* __restrict__ clo)
{
    int idx = blockIdx.x * blockDim.x + threadIdx.x;
    int t = idx >> 11;
    int s = idx & (SQ - 1);
    int tau = (t - s) & (SQ - 1);
    Chi[idx] = chi[tau];
    Clo[idx] = clo[tau];
}

// ---------------- fp32 -> bf16 hi/lo split ----------------
__global__ void split_kernel(const float* __restrict__ in,
                             __nv_bfloat16* __restrict__ hi, __nv_bfloat16* __restrict__ lo, int n)
{
    int i = blockIdx.x * blockDim.x + threadIdx.x;
    if (i >= n) return;
    float f = in[i];
    __nv_bfloat16 h = __float2bfloat16_rn(f);
    hi[i] = h;
    lo[i] = __float2bfloat16_rn(f - __bfloat162float(h));
}

__global__ void zero_kernel(float* __restrict__ p, int n)
{
    int i = blockIdx.x * blockDim.x + threadIdx.x;
    if (i < n) p[i] = 0.f;
}

// ---------------- bf16-split tensor-core GEMM ----------------
// C = Ahi@Bhi + Ahi@Blo + Alo@Bhi (+ bias*scale), fp32 accum/output.
// 128x128 block tile, BK=32, 8 warps (2x4), warp tile 64x32, m16n8k16 mma.
// smem layout (bf16 elements):
//   Ahi[2][128*40] | Alo[2][128*40] | Bhi[2][32*136] | Blo[2][32*136]
#define GA_STR 40
#define GB_STR 136
#define A_BUF_ELEMS (128 * GA_STR)
#define B_BUF_ELEMS (32 * GB_STR)
__global__ __launch_bounds__(256) void gemm_bf16_kernel(
    const __nv_bfloat16* __restrict__ Ahi, const __nv_bfloat16* __restrict__ Alo,
    const __nv_bfloat16* __restrict__ Bhi, const __nv_bfloat16* __restrict__ Blo,
    const float* __restrict__ bias, const float* __restrict__ bscalep,
    float* __restrict__ C,
    int M, int N, int K,
    long long sA, long long sB, long long sC)
{
    extern __shared__ __nv_bfloat16 sm[];
    __nv_bfloat16* AsHi = sm;
    __nv_bfloat16* AsLo = sm + 2 * A_BUF_ELEMS;
    __nv_bfloat16* BsHi = sm + 4 * A_BUF_ELEMS;
    __nv_bfloat16* BsLo = sm + 4 * A_BUF_ELEMS + 2 * B_BUF_ELEMS;
    uint32_t sbase = (uint32_t)__cvta_generic_to_shared(sm);

    int z = blockIdx.z;
    Ahi += (size_t)z * sA;  Alo += (size_t)z * sA;
    Bhi += (size_t)z * sB;  Blo += (size_t)z * sB;
    C   += (size_t)z * sC;

    int tid = threadIdx.x;
    int lane = tid & 31;
    int wid = tid >> 5;
    int mBase = (wid >> 2) * 64;
    int nBase = (wid & 3) * 32;
    int row0 = blockIdx.y * 128;
    int col0 = blockIdx.x * 128;

    float acc[4][4][4];
#pragma unroll
    for (int mf = 0; mf < 4; mf++)
#pragma unroll
        for (int nf = 0; nf < 4; nf++)
#pragma unroll
            for (int r = 0; r < 4; r++) acc[mf][nf][r] = 0.f;

    // ---- tile loaders ----
    int ar = tid >> 1;              // A row 0..127
    int br = tid >> 3;              // B k-row 0..31
    const __nv_bfloat16* Ah0 = Ahi + (size_t)(row0 + ar) * K;
    const __nv_bfloat16* Al0 = Alo + (size_t)(row0 + ar) * K;

#define LOAD_TILES(buf, k0)                                                             \
    do {                                                                                \
        _Pragma("unroll")                                                               \
        for (int j = 0; j < 2; j++) {                                                   \
            int s = (tid & 1) * 2 + j;                                                  \
            cp_async16(&AsHi[(buf) * A_BUF_ELEMS + ar * GA_STR + s * 8],                \
                       Ah0 + (k0) + s * 8);                                             \
            cp_async16(&AsLo[(buf) * A_BUF_ELEMS + ar * GA_STR + s * 8],                \
                       Al0 + (k0) + s * 8);                                             \
            int sb = (tid & 7) * 2 + j;                                                 \
            cp_async16(&BsHi[(buf) * B_BUF_ELEMS + br * GB_STR + sb * 8],               \
                       Bhi + (size_t)((k0) + br) * N + col0 + sb * 8);                  \
            cp_async16(&BsLo[(buf) * B_BUF_ELEMS + br * GB_STR + sb * 8],               \
                       Blo + (size_t)((k0) + br) * N + col0 + sb * 8);                  \
        }                                                                               \
    } while (0)

    LOAD_TILES(0, 0);
    cp_commit();
    cp_wait0();
    __syncthreads();

    int nIter = K >> 5;
    int lr = lane & 15;
    int khalf = (lane >> 4) << 3;

    for (int it = 0; it < nIter; it++) {
        int buf = it & 1;
        if (it + 1 < nIter) {
            LOAD_TILES(buf ^ 1, (it + 1) << 5);
            cp_commit();
        }

        uint32_t aHiB = sbase + 2 * (buf * A_BUF_ELEMS);
        uint32_t aLoB = sbase + 2 * (2 * A_BUF_ELEMS + buf * A_BUF_ELEMS);
        uint32_t bHiB = sbase + 2 * (4 * A_BUF_ELEMS + buf * B_BUF_ELEMS);
        uint32_t bLoB = sbase + 2 * (4 * A_BUF_ELEMS + 2 * B_BUF_ELEMS + buf * B_BUF_ELEMS);

#pragma unroll
        for (int ks = 0; ks < 32; ks += 16) {
            uint32_t ahi[4][4], alo[4][4], bhi[4][2], blo[4][2];
#pragma unroll
            for (int mf = 0; mf < 4; mf++) {
                uint32_t off = 2 * ((mBase + mf * 16 + lr) * GA_STR + ks + khalf);
                ldsm_x4(ahi[mf], aHiB + off);
                ldsm_x4(alo[mf], aLoB + off);
            }
#pragma unroll
            for (int nf = 0; nf < 4; nf++) {
                uint32_t off = 2 * ((ks + lr) * GB_STR + nBase + nf * 8);
                ldsm_x2t(bhi[nf], bHiB + off);
                ldsm_x2t(blo[nf], bLoB + off);
            }
#pragma unroll
            for (int mf = 0; mf < 4; mf++)
#pragma unroll
                for (int nf = 0; nf < 4; nf++) {
                    mma16816(acc[mf][nf], ahi[mf], bhi[nf]);
                    mma16816(acc[mf][nf], ahi[mf], blo[nf]);
                    mma16816(acc[mf][nf], alo[mf], bhi[nf]);
                }
        }

        if (it + 1 < nIter) {
            cp_wait0();
        }
        __syncthreads();
    }

    // ---- epilogue ----
    float bscale = 0.f;
    if (bias) bscale = bscalep ? *bscalep : 1.f;

#pragma unroll
    for (int mf = 0; mf < 4; mf++) {
        int r0 = row0 + mBase + mf * 16 + (lane >> 2);
#pragma unroll
        for (int nf = 0; nf < 4; nf++) {
            int c0 = col0 + nBase + nf * 8 + (lane & 3) * 2;
            float b0 = 0.f, b1 = 0.f;
            if (bias) { b0 = bias[c0] * bscale; b1 = bias[c0 + 1] * bscale; }
            float2 v0 = { acc[mf][nf][0] + b0, acc[mf][nf][1] + b1 };
            float2 v1 = { acc[mf][nf][2] + b0, acc[mf][nf][3] + b1 };
            *(float2*)&C[(size_t)r0 * N + c0]       = v0;
            *(float2*)&C[(size_t)(r0 + 8) * N + c0] = v1;
        }
    }
}

// ---------------- fused flash attention + autocorrelation diag-sums ----------------
#define QTS 65
__global__ __launch_bounds__(256) void flash_kernel(
    const float* __restrict__ Qf, const float* __restrict__ Kf,
    const float* __restrict__ Vf, const float* __restrict__ mask,
    float* __restrict__ Comb, float* __restrict__ ac)
{
    extern __shared__ float sm_[];
    float* Qt  = sm_;                      // [64 d][64 row] stride 65
    float* Kt  = sm_ + 4160;               // [64 d][64 key] stride 65
    float* Vs  = sm_ + 8320;               // [64 key][64 d] stride 64
    float* Pt  = sm_ + 12416;              // [64 key][64 row] stride 65
    float* acb = sm_ + 16576;              // 2048 tau bins

    int tid = threadIdx.x;
    int tx = tid & 15, ty = tid >> 4;
    int qb = blockIdx.x, h = blockIdx.y, b = blockIdx.z;
    int t0 = qb * 64;

    const float* Qbase = Qf + (size_t)b * SQ * HID + h * HD;
    const float* Kbase = Kf + (size_t)b * SQ * HID + h * HD;
    const float* Vbase = Vf + (size_t)b * SQ * HID + h * HD;
    const float* Mbase = mask + (size_t)b * SQ * SQ;
    float* acrow = ac + (size_t)(b * NH + h) * SQ;

    for (int i = tid; i < SQ; i += 256) acb[i] = 0.f;

#pragma unroll
    for (int l = 0; l < 4; l++) {
        int id4 = tid + l * 256;
        int r = id4 >> 4;
        int cc = (id4 & 15) << 2;
        float4 v = *(const float4*)&Qbase[(size_t)(t0 + r) * HID + cc];
        Qt[(cc + 0) * QTS + r] = v.x;
        Qt[(cc + 1) * QTS + r] = v.y;
        Qt[(cc + 2) * QTS + r] = v.z;
        Qt[(cc + 3) * QTS + r] = v.w;
    }

    float m_run[4], l_run[4], o[4][4];
#pragma unroll
    for (int i = 0; i < 4; i++) {
        m_run[i] = -INFINITY;
        l_run[i] = 0.f;
#pragma unroll
        for (int j = 0; j < 4; j++) o[i][j] = 0.f;
    }

    for (int kt = 0; kt < SQ / 64; kt++) {
        int s0 = kt * 64;
        __syncthreads();
#pragma unroll
        for (int l = 0; l < 4; l++) {
            int id4 = tid + l * 256;
            int r = id4 >> 4;
            int cc = (id4 & 15) << 2;
            float4 kv = *(const float4*)&Kbase[(size_t)(s0 + r) * HID + cc];
            Kt[(cc + 0) * QTS + r] = kv.x;
            Kt[(cc + 1) * QTS + r] = kv.y;
            Kt[(cc + 2) * QTS + r] = kv.z;
            Kt[(cc + 3) * QTS + r] = kv.w;
            float4 vv = *(const float4*)&Vbase[(size_t)(s0 + r) * HID + cc];
            *(float4*)&Vs[r * 64 + cc] = vv;
        }
        __syncthreads();

        float sv[4][4];
#pragma unroll
        for (int i = 0; i < 4; i++)
#pragma unroll
            for (int j = 0; j < 4; j++) sv[i][j] = 0.f;
#pragma unroll 8
        for (int dd = 0; dd < 64; dd++) {
            float a[4], bb[4];
#pragma unroll
            for (int i = 0; i < 4; i++) a[i]  = Qt[dd * QTS + ty * 4 + i];
#pragma unroll
            for (int j = 0; j < 4; j++) bb[j] = Kt[dd * QTS + tx * 4 + j];
#pragma unroll
            for (int i = 0; i < 4; i++)
#pragma unroll
                for (int j = 0; j < 4; j++) sv[i][j] += a[i] * bb[j];
        }

        {
            float bins[7];
#pragma unroll
            for (int d = 0; d < 7; d++) bins[d] = 0.f;
#pragma unroll
            for (int i = 0; i < 4; i++)
#pragma unroll
                for (int j = 0; j < 4; j++) bins[i - j + 3] += sv[i][j];
            int taubase = t0 - s0 + (ty - tx) * 4 - 3;
#pragma unroll
            for (int d = 0; d < 7; d++)
                atomicAdd(&acb[(taubase + d) & (SQ - 1)], bins[d] * (1.f / 64.f));
        }

        float p[4][4], corr[4];
#pragma unroll
        for (int i = 0; i < 4; i++) {
            float4 mrow = *(const float4*)&Mbase[(size_t)(t0 + ty * 4 + i) * SQ + s0 + tx * 4];
            float mv[4] = {mrow.x, mrow.y, mrow.z, mrow.w};
            float tm = -INFINITY;
#pragma unroll
            for (int j = 0; j < 4; j++) {
                sv[i][j] = sv[i][j] * 0.125f + mv[j];
                tm = fmaxf(tm, sv[i][j]);
            }
#pragma unroll
            for (int off = 8; off >= 1; off >>= 1)
                tm = fmaxf(tm, __shfl_xor_sync(0xffffffffu, tm, off, 16));
            float nm = fmaxf(m_run[i], tm);
            corr[i] = __expf(m_run[i] - nm);
            m_run[i] = nm;
            float rs = 0.f;
#pragma unroll
            for (int j = 0; j < 4; j++) {
                p[i][j] = __expf(sv[i][j] - nm);
                rs += p[i][j];
            }
#pragma unroll
            for (int off = 8; off >= 1; off >>= 1)
                rs += __shfl_xor_sync(0xffffffffu, rs, off, 16);
            l_run[i] = l_run[i] * corr[i] + rs;
#pragma unroll
            for (int j = 0; j < 4; j++) o[i][j] *= corr[i];
        }

#pragma unroll
        for (int i = 0; i < 4; i++)
#pragma unroll
            for (int j = 0; j < 4; j++)
                Pt[(tx * 4 + j) * QTS + ty * 4 + i] = p[i][j];
        __syncthreads();

#pragma unroll 8
        for (int jj = 0; jj < 64; jj++) {
            float a[4], bb[4];
#pragma unroll
            for (int i = 0; i < 4; i++) a[i]  = Pt[jj * QTS + ty * 4 + i];
#pragma unroll
            for (int j = 0; j < 4; j++) bb[j] = Vs[jj * 64 + tx * 4 + j];
#pragma unroll
            for (int i = 0; i < 4; i++)
#pragma unroll
                for (int j = 0; j < 4; j++) o[i][j] += a[i] * bb[j];
        }
    }

    __syncthreads();
    for (int i = tid; i < SQ; i += 256)
        atomicAdd(&acrow[i], acb[i]);

    float* Crow = Comb + (size_t)b * SQ * HID + h * HD;
#pragma unroll
    for (int i = 0; i < 4; i++) {
        float inv = 0.5f / l_run[i];
        float out[4];
#pragma unroll
        for (int j = 0; j < 4; j++) out[j] = o[i][j] * inv;
        *(float4*)&Crow[(size_t)(t0 + ty * 4 + i) * HID + tx * 4] = *(float4*)out;
    }
}

// ---------------- top-k (k=15) + softmax weights ----------------
__global__ __launch_bounds__(256) void topk_kernel(
    const float* __restrict__ ac, int* __restrict__ topi, float* __restrict__ topw)
{
    int bh = blockIdx.x;
    __shared__ float svv[SQ];
    __shared__ float rv[256];
    __shared__ int ri[256];
    __shared__ float tvals[KTOP];
    __shared__ int tidxs[KTOP];
    int tid = threadIdx.x;

    for (int i = tid; i < SQ; i += 256)
        svv[i] = ac[(size_t)bh * SQ + i];
    __syncthreads();

    for (int t = 0; t < KTOP; t++) {
        float bv = -INFINITY;
        int bi = 0;
        for (int i = tid; i < SQ; i += 256) {
            float v = svv[i];
            if (v > bv || (v == bv && i < bi)) { bv = v; bi = i; }
        }
        rv[tid] = bv; ri[tid] = bi;
        __syncthreads();
        for (int st = 128; st > 0; st >>= 1) {
            if (tid < st) {
                float v2 = rv[tid + st]; int i2 = ri[tid + st];
                if (v2 > rv[tid] || (v2 == rv[tid] && i2 < ri[tid])) { rv[tid] = v2; ri[tid] = i2; }
            }
            __syncthreads();
        }
        if (tid == 0) {
            tvals[t] = rv[0]; tidxs[t] = ri[0];
            svv[ri[0]] = -INFINITY;
        }
        __syncthreads();
    }

    if (tid == 0) {
        float mx = tvals[0];
        float e[KTOP], ssum = 0.f;
#pragma unroll
        for (int t = 0; t < KTOP; t++) { e[t] = __expf(tvals[t] - mx); ssum += e[t]; }
        float inv = 1.f / ssum;
#pragma unroll
        for (int t = 0; t < KTOP; t++) {
            topw[bh * KTOP + t] = e[t] * inv;
            topi[bh * KTOP + t] = tidxs[t];
        }
    }
}

// ---------------- frequency branch gather: Comb += (1-GAMMA) * freq_ctx ----------------
__global__ __launch_bounds__(256) void freq_kernel(
    const float* __restrict__ V, const int* __restrict__ topi,
    const float* __restrict__ topw, float* __restrict__ Comb)
{
    int t = blockIdx.x, b = blockIdx.y;
    __shared__ int si[NH * KTOP];
    __shared__ float sw[NH * KTOP];
    int tid = threadIdx.x;
    if (tid < NH * KTOP) {
        si[tid] = topi[b * NH * KTOP + tid];
        sw[tid] = topw[b * NH * KTOP + tid];
    }
    __syncthreads();

    int c = tid * 4;
    int h = c >> 6;
    float* crow = Comb + ((size_t)b * SQ + t) * HID + c;
    float4 acc = *(float4*)crow;
    const float* Vb = V + (size_t)b * SQ * HID;
#pragma unroll
    for (int j = 0; j < KTOP; j++) {
        int row = (t + si[h * KTOP + j]) & (SQ - 1);
        float w = 0.5f * sw[h * KTOP + j];
        float4 v = *(const float4*)&Vb[(size_t)row * HID + c];
        acc.x += w * v.x; acc.y += w * v.y; acc.z += w * v.z; acc.w += w * v.w;
    }
    *(float4*)crow = acc;
}

// ---------------- launcher ----------------
extern "C" void kernel_launch(void* const* d_in, const int* in_sizes, int n_in,
                              void* d_out, int out_size)
{
    const float* X    = (const float*)d_in[0];
    const float* mask = (const float*)d_in[1];
    const float* Wq   = (const float*)d_in[2];
    const float* bq   = (const float*)d_in[3];
    const float* Wk   = (const float*)d_in[4];
    const float* bk   = (const float*)d_in[5];
    const float* Wv   = (const float*)d_in[6];
    const float* bv   = (const float*)d_in[7];
    const float* Wo   = (const float*)d_in[8];
    const float* bo   = (const float*)d_in[9];
    const int*   li   = (const int*)d_in[10];
    const int*   nl   = (const int*)d_in[11];
    float* out = (float*)d_out;

    float *cP, *dcP, *XfP, *QfP, *KfP, *VfP, *VbP, *CbP, *acP, *twP;
    int* tiP;
    __nv_bfloat16 *chiP, *cloP, *ChiP, *CloP, *XhiP, *XloP, *XfhiP, *XfloP, *CbhiP, *CbloP;
    __nv_bfloat16 *WqhiP, *WqloP, *WkhiP, *WkloP, *WvhiP, *WvloP, *WohiP, *WoloP;
    cudaGetSymbolAddress((void**)&cP,  d_c);
    cudaGetSymbolAddress((void**)&dcP, d_dcflag);
    cudaGetSymbolAddress((void**)&XfP, d_Xf);
    cudaGetSymbolAddress((void**)&QfP, d_Qfil);
    cudaGetSymbolAddress((void**)&KfP, d_Kfil);
    cudaGetSymbolAddress((void**)&VfP, d_Vfil);
    cudaGetSymbolAddress((void**)&VbP, d_Vbuf);
    cudaGetSymbolAddress((void**)&CbP, d_Comb);
    cudaGetSymbolAddress((void**)&acP, d_ac);
    cudaGetSymbolAddress((void**)&tiP, d_topi);
    cudaGetSymbolAddress((void**)&twP, d_topw);
    cudaGetSymbolAddress((void**)&chiP, d_chi);
    cudaGetSymbolAddress((void**)&cloP, d_clo);
    cudaGetSymbolAddress((void**)&ChiP, d_Chi);
    cudaGetSymbolAddress((void**)&CloP, d_Clo);
    cudaGetSymbolAddress((void**)&XhiP, d_Xhi);
    cudaGetSymbolAddress((void**)&XloP, d_Xlo);
    cudaGetSymbolAddress((void**)&XfhiP, d_Xfhi);
    cudaGetSymbolAddress((void**)&XfloP, d_Xflo);
    cudaGetSymbolAddress((void**)&CbhiP, d_Cbhi);
    cudaGetSymbolAddress((void**)&CbloP, d_Cblo);
    cudaGetSymbolAddress((void**)&WqhiP, d_Wqhi);
    cudaGetSymbolAddress((void**)&WqloP, d_Wqlo);
    cudaGetSymbolAddress((void**)&WkhiP, d_Wkhi);
    cudaGetSymbolAddress((void**)&WkloP, d_Wklo);
    cudaGetSymbolAddress((void**)&WvhiP, d_Wvhi);
    cudaGetSymbolAddress((void**)&WvloP, d_Wvlo);
    cudaGetSymbolAddress((void**)&WohiP, d_Wohi);
    cudaGetSymbolAddress((void**)&WoloP, d_Wolo);

    const long long SH = (long long)SQ * HID;
    const int NELT = BSZ * SQ * HID;      // 4M
    const int WELT = HID * HID;           // 1M

    static bool attrs_set = false;
    if (!attrs_set) {
        cudaFuncSetAttribute(gemm_bf16_kernel, cudaFuncAttributeMaxDynamicSharedMemorySize, 75776);
        cudaFuncSetAttribute(flash_kernel,     cudaFuncAttributeMaxDynamicSharedMemorySize, 75776);
        attrs_set = true;
    }

    // 1) filter taps (+bf16) + circulant matrix (bf16 hi/lo)
    filter_kernel<<<8, 256>>>(li, nl, cP, dcP, chiP, cloP);
    cmat_kernel<<<(SQ * SQ) / 256, 256>>>(ChiP, CloP, chiP, cloP);

    // 2) split inputs
    split_kernel<<<NELT / 256, 256>>>(X, XhiP, XloP, NELT);
    split_kernel<<<WELT / 256, 256>>>(Wq, WqhiP, WqloP, WELT);
    split_kernel<<<WELT / 256, 256>>>(Wk, WkhiP, WkloP, WELT);
    split_kernel<<<WELT / 256, 256>>>(Wv, WvhiP, WvloP, WELT);
    split_kernel<<<WELT / 256, 256>>>(Wo, WohiP, WoloP, WELT);

    // 3) Xf = C @ X  (per batch), then split
    gemm_bf16_kernel<<<dim3(HID / 128, SQ / 128, BSZ), 256, 75776>>>(
        ChiP, CloP, XhiP, XloP, nullptr, nullptr, XfP, SQ, HID, SQ, 0, SH, SH);
    split_kernel<<<NELT / 256, 256>>>(XfP, XfhiP, XfloP, NELT);

    // 4) filtered projections (bias only if DC in band) + unfiltered V
    gemm_bf16_kernel<<<dim3(HID / 128, SQ / 128, BSZ), 256, 75776>>>(
        XfhiP, XfloP, WqhiP, WqloP, bq, dcP, QfP, SQ, HID, HID, SH, 0, SH);
    gemm_bf16_kernel<<<dim3(HID / 128, SQ / 128, BSZ), 256, 75776>>>(
        XfhiP, XfloP, WkhiP, WkloP, bk, dcP, KfP, SQ, HID, HID, SH, 0, SH);
    gemm_bf16_kernel<<<dim3(HID / 128, SQ / 128, BSZ), 256, 75776>>>(
        XfhiP, XfloP, WvhiP, WvloP, bv, dcP, VfP, SQ, HID, HID, SH, 0, SH);
    gemm_bf16_kernel<<<dim3(HID / 128, SQ / 128, BSZ), 256, 75776>>>(
        XhiP, XloP, WvhiP, WvloP, bv, nullptr, VbP, SQ, HID, HID, SH, 0, SH);

    // 5) flash attention + autocorrelation diag sums
    zero_kernel<<<(BSZ * NH * SQ) / 256, 256>>>(acP, BSZ * NH * SQ);
    flash_kernel<<<dim3(SQ / 64, NH, BSZ), 256, 75776>>>(QfP, KfP, VfP, mask, CbP, acP);

    // 6) top-k weights + frequency gather
    topk_kernel<<<BSZ * NH, 256>>>(acP, tiP, twP);
    freq_kernel<<<dim3(SQ, BSZ), 256>>>(VbP, tiP, twP, CbP);

    // 7) output projection
    split_kernel<<<NELT / 256, 256>>>(CbP, CbhiP, CbloP, NELT);
    gemm_bf16_kernel<<<dim3(HID / 128, (BSZ * SQ) / 128, 1), 256, 75776>>>(
        CbhiP, CbloP, WohiP, WoloP, bo, nullptr, out, BSZ * SQ, HID, HID, 0, 0, 0);
}

// round 6
// speedup vs baseline: 1.7204x; 1.1505x over previous
#include <cuda_runtime.h>
#include <cuda_bf16.h>
#include <math.h>
#include <stdint.h>

#define SQ   2048
#define HID  1024
#define NH   16
#define HD   64
#define BSZ  2
#define MFREQ (SQ/2 + 1)
#define KTOP 15

// ---------------- scratch ----------------
__device__ float d_c[SQ];
__device__ float d_dcflag;
__device__ float d_Vbuf[BSZ * SQ * HID];
__device__ float d_Comb[BSZ * SQ * HID];
__device__ float d_ac  [BSZ * NH * SQ];
__device__ int   d_topi[BSZ * NH * KTOP];
__device__ float d_topw[BSZ * NH * KTOP];

__device__ __nv_bfloat16 d_chi[SQ], d_clo[SQ];
__device__ __nv_bfloat16 d_Chi [SQ * SQ],        d_Clo [SQ * SQ];
__device__ __nv_bfloat16 d_Xhi [BSZ * SQ * HID], d_Xlo [BSZ * SQ * HID];
__device__ __nv_bfloat16 d_Xfhi[BSZ * SQ * HID], d_Xflo[BSZ * SQ * HID];
__device__ __nv_bfloat16 d_Qfhi[BSZ * SQ * HID], d_Qflo[BSZ * SQ * HID];
__device__ __nv_bfloat16 d_Kfhi[BSZ * SQ * HID], d_Kflo[BSZ * SQ * HID];
__device__ __nv_bfloat16 d_Vfhi[BSZ * SQ * HID], d_Vflo[BSZ * SQ * HID];
__device__ __nv_bfloat16 d_Cbhi[BSZ * SQ * HID], d_Cblo[BSZ * SQ * HID];
__device__ __nv_bfloat16 d_Wqhi[HID * HID], d_Wqlo[HID * HID];
__device__ __nv_bfloat16 d_Wkhi[HID * HID], d_Wklo[HID * HID];
__device__ __nv_bfloat16 d_Wvhi[HID * HID], d_Wvlo[HID * HID];
__device__ __nv_bfloat16 d_Wohi[HID * HID], d_Wolo[HID * HID];

// ---------------- cp.async helpers ----------------
__device__ __forceinline__ void cp_async16(void* smem, const void* gmem) {
    unsigned s = (unsigned)__cvta_generic_to_shared(smem);
    asm volatile("cp.async.cg.shared.global [%0], [%1], 16;" :: "r"(s), "l"(gmem));
}
__device__ __forceinline__ void cp_commit() { asm volatile("cp.async.commit_group;"); }
__device__ __forceinline__ void cp_wait0()  { asm volatile("cp.async.wait_group 0;"); }
__device__ __forceinline__ void cp_wait1()  { asm volatile("cp.async.wait_group 1;"); }

// ---------------- mma / ldmatrix helpers ----------------
__device__ __forceinline__ void mma16816(float* d, const uint32_t* a, const uint32_t* b) {
    asm volatile(
        "mma.sync.aligned.m16n8k16.row.col.f32.bf16.bf16.f32 "
        "{%0,%1,%2,%3}, {%4,%5,%6,%7}, {%8,%9}, {%0,%1,%2,%3};"
        : "+f"(d[0]), "+f"(d[1]), "+f"(d[2]), "+f"(d[3])
        : "r"(a[0]), "r"(a[1]), "r"(a[2]), "r"(a[3]), "r"(b[0]), "r"(b[1]));
}
__device__ __forceinline__ void ldsm_x4(uint32_t* r, uint32_t addr) {
    asm volatile("ldmatrix.sync.aligned.m8n8.x4.shared.b16 {%0,%1,%2,%3}, [%4];"
        : "=r"(r[0]), "=r"(r[1]), "=r"(r[2]), "=r"(r[3]) : "r"(addr));
}
__device__ __forceinline__ void ldsm_x2t(uint32_t* r, uint32_t addr) {
    asm volatile("ldmatrix.sync.aligned.m8n8.x2.trans.shared.b16 {%0,%1}, [%2];"
        : "=r"(r[0]), "=r"(r[1]) : "r"(addr));
}
__device__ __forceinline__ void ldsm_x2(uint32_t* r, uint32_t addr) {
    asm volatile("ldmatrix.sync.aligned.m8n8.x2.shared.b16 {%0,%1}, [%2];"
        : "=r"(r[0]), "=r"(r[1]) : "r"(addr));
}
__device__ __forceinline__ uint32_t pack_bf2(float a, float b) {
    __nv_bfloat162 t = __floats2bfloat162_rn(a, b);
    return *(uint32_t*)&t;
}

// ---------------- filter taps ----------------
__global__ void filter_kernel(const int* __restrict__ li_p, const int* __restrict__ nl_p,
                              float* __restrict__ c, float* __restrict__ dcflag,
                              __nv_bfloat16* __restrict__ chi, __nv_bfloat16* __restrict__ clo)
{
    int n = blockIdx.x * blockDim.x + threadIdx.x;
    if (n >= SQ) return;
    int li = *li_p;
    int nl = *nl_p;
    const double ALPHA = 0.5;
    int M = MFREQ;
    int p, q;
    if (ALPHA <= 1.0 / (double)nl) {
        p = (int)(M * (1.0 - (double)(li + 1) / (double)nl));
        q = (int)((double)p + (double)M / (double)nl);
    } else {
        p = (nl > 1) ? (int)(M * (1.0 - ALPHA) * (1.0 - (double)li / (double)(nl - 1))) : 0;
        q = (int)((double)p + ALPHA * (double)M);
    }
    p = max(0, min(p, M - 1));
    q = max(p + 1, min(q, M));

    double acc = 0.0;
    const double w2 = 2.0 / (double)SQ;
    const double w1 = 1.0 / (double)SQ;
    const double tpn = 6.283185307179586476925286766559 * (double)n / (double)SQ;
    for (int f = p; f < q; f++) {
        double wf = (f == 0 || f == M - 1) ? w1 : w2;
        acc += wf * cos(tpn * (double)f);
    }
    float cf = (float)acc;
    c[n] = cf;
    __nv_bfloat16 h = __float2bfloat16_rn(cf);
    chi[n] = h;
    clo[n] = __float2bfloat16_rn(cf - __bfloat162float(h));
    if (n == 0) *dcflag = (p == 0) ? 1.0f : 0.0f;
}

__global__ void cmat_kernel(__nv_bfloat16* __restrict__ Chi, __nv_bfloat16* __restrict__ Clo,
                            const __nv_bfloat16* __restrict__ chi, const __nv_bfloat16* __restrict__ clo)
{
    int idx = blockIdx.x * blockDim.x + threadIdx.x;
    int t = idx >> 11;
    int s = idx & (SQ - 1);
    int tau = (t - s) & (SQ - 1);
    Chi[idx] = chi[tau];
    Clo[idx] = clo[tau];
}

__global__ void split_kernel(const float* __restrict__ in,
                             __nv_bfloat16* __restrict__ hi, __nv_bfloat16* __restrict__ lo, int n)
{
    int i = blockIdx.x * blockDim.x + threadIdx.x;
    if (i >= n) return;
    float f = in[i];
    __nv_bfloat16 h = __float2bfloat16_rn(f);
    hi[i] = h;
    lo[i] = __float2bfloat16_rn(f - __bfloat162float(h));
}

__global__ void zero_kernel(float* __restrict__ p, int n)
{
    int i = blockIdx.x * blockDim.x + threadIdx.x;
    if (i < n) p[i] = 0.f;
}

// ---------------- bf16-split tensor-core GEMM ----------------
#define GA_STR 40
#define GB_STR 136
#define A_BUF_ELEMS (128 * GA_STR)
#define B_BUF_ELEMS (32 * GB_STR)
__global__ __launch_bounds__(256) void gemm_bf16_kernel(
    const __nv_bfloat16* __restrict__ Ahi, const __nv_bfloat16* __restrict__ Alo,
    const __nv_bfloat16* __restrict__ Bhi, const __nv_bfloat16* __restrict__ Blo,
    const float* __restrict__ bias, const float* __restrict__ bscalep,
    float* __restrict__ C,
    __nv_bfloat16* __restrict__ Ohi, __nv_bfloat16* __restrict__ Olo,
    int M, int N, int K,
    long long sA, long long sB, long long sC)
{
    extern __shared__ __nv_bfloat16 sm[];
    __nv_bfloat16* AsHi = sm;
    __nv_bfloat16* AsLo = sm + 2 * A_BUF_ELEMS;
    __nv_bfloat16* BsHi = sm + 4 * A_BUF_ELEMS;
    __nv_bfloat16* BsLo = sm + 4 * A_BUF_ELEMS + 2 * B_BUF_ELEMS;
    uint32_t sbase = (uint32_t)__cvta_generic_to_shared(sm);

    int z = blockIdx.z;
    Ahi += (size_t)z * sA;  Alo += (size_t)z * sA;
    Bhi += (size_t)z * sB;  Blo += (size_t)z * sB;
    if (C)   C   += (size_t)z * sC;
    if (Ohi) { Ohi += (size_t)z * sC; Olo += (size_t)z * sC; }

    int tid = threadIdx.x;
    int lane = tid & 31;
    int wid = tid >> 5;
    int mBase = (wid >> 2) * 64;
    int nBase = (wid & 3) * 32;
    int row0 = blockIdx.y * 128;
    int col0 = blockIdx.x * 128;

    float acc[4][4][4];
#pragma unroll
    for (int mf = 0; mf < 4; mf++)
#pragma unroll
        for (int nf = 0; nf < 4; nf++)
#pragma unroll
            for (int r = 0; r < 4; r++) acc[mf][nf][r] = 0.f;

    int ar = tid >> 1;
    int br = tid >> 3;
    const __nv_bfloat16* Ah0 = Ahi + (size_t)(row0 + ar) * K;
    const __nv_bfloat16* Al0 = Alo + (size_t)(row0 + ar) * K;

#define LOAD_TILES(buf, k0)                                                             \
    do {                                                                                \
        _Pragma("unroll")                                                               \
        for (int j = 0; j < 2; j++) {                                                   \
            int s = (tid & 1) * 2 + j;                                                  \
            cp_async16(&AsHi[(buf) * A_BUF_ELEMS + ar * GA_STR + s * 8],                \
                       Ah0 + (k0) + s * 8);                                             \
            cp_async16(&AsLo[(buf) * A_BUF_ELEMS + ar * GA_STR + s * 8],                \
                       Al0 + (k0) + s * 8);                                             \
            int sb = (tid & 7) * 2 + j;                                                 \
            cp_async16(&BsHi[(buf) * B_BUF_ELEMS + br * GB_STR + sb * 8],               \
                       Bhi + (size_t)((k0) + br) * N + col0 + sb * 8);                  \
            cp_async16(&BsLo[(buf) * B_BUF_ELEMS + br * GB_STR + sb * 8],               \
                       Blo + (size_t)((k0) + br) * N + col0 + sb * 8);                  \
        }                                                                               \
    } while (0)

    LOAD_TILES(0, 0);
    cp_commit();
    cp_wait0();
    __syncthreads();

    int nIter = K >> 5;
    int lr = lane & 15;
    int khalf = (lane >> 4) << 3;

    for (int it = 0; it < nIter; it++) {
        int buf = it & 1;
        if (it + 1 < nIter) {
            LOAD_TILES(buf ^ 1, (it + 1) << 5);
            cp_commit();
        }

        uint32_t aHiB = sbase + 2 * (buf * A_BUF_ELEMS);
        uint32_t aLoB = sbase + 2 * (2 * A_BUF_ELEMS + buf * A_BUF_ELEMS);
        uint32_t bHiB = sbase + 2 * (4 * A_BUF_ELEMS + buf * B_BUF_ELEMS);
        uint32_t bLoB = sbase + 2 * (4 * A_BUF_ELEMS + 2 * B_BUF_ELEMS + buf * B_BUF_ELEMS);

#pragma unroll
        for (int ks = 0; ks < 32; ks += 16) {
            uint32_t ahi[4][4], alo[4][4], bhi[4][2], blo[4][2];
#pragma unroll
            for (int mf = 0; mf < 4; mf++) {
                uint32_t off = 2 * ((mBase + mf * 16 + lr) * GA_STR + ks + khalf);
                ldsm_x4(ahi[mf], aHiB + off);
                ldsm_x4(alo[mf], aLoB + off);
            }
#pragma unroll
            for (int nf = 0; nf < 4; nf++) {
                uint32_t off = 2 * ((ks + lr) * GB_STR + nBase + nf * 8);
                ldsm_x2t(bhi[nf], bHiB + off);
                ldsm_x2t(blo[nf], bLoB + off);
            }
#pragma unroll
            for (int mf = 0; mf < 4; mf++)
#pragma unroll
                for (int nf = 0; nf < 4; nf++) {
                    mma16816(acc[mf][nf], ahi[mf], bhi[nf]);
                    mma16816(acc[mf][nf], ahi[mf], blo[nf]);
                    mma16816(acc[mf][nf], alo[mf], bhi[nf]);
                }
        }

        if (it + 1 < nIter) cp_wait0();
        __syncthreads();
    }

    float bscale = 0.f;
    if (bias) bscale = bscalep ? *bscalep : 1.f;

#pragma unroll
    for (int mf = 0; mf < 4; mf++) {
        int r0 = row0 + mBase + mf * 16 + (lane >> 2);
#pragma unroll
        for (int nf = 0; nf < 4; nf++) {
            int c0 = col0 + nBase + nf * 8 + (lane & 3) * 2;
            float b0 = 0.f, b1 = 0.f;
            if (bias) { b0 = bias[c0] * bscale; b1 = bias[c0 + 1] * bscale; }
            float v0 = acc[mf][nf][0] + b0, v1 = acc[mf][nf][1] + b1;
            float v2 = acc[mf][nf][2] + b0, v3 = acc[mf][nf][3] + b1;
            if (C) {
                float2 w0 = {v0, v1}, w1 = {v2, v3};
                *(float2*)&C[(size_t)r0 * N + c0]       = w0;
                *(float2*)&C[(size_t)(r0 + 8) * N + c0] = w1;
            }
            if (Ohi) {
                __nv_bfloat16 h0 = __float2bfloat16_rn(v0), h1 = __float2bfloat16_rn(v1);
                __nv_bfloat16 h2 = __float2bfloat16_rn(v2), h3 = __float2bfloat16_rn(v3);
                __nv_bfloat162 hv0 = {h0, h1}, hv1 = {h2, h3};
                __nv_bfloat162 lv0 = {__float2bfloat16_rn(v0 - __bfloat162float(h0)),
                                      __float2bfloat16_rn(v1 - __bfloat162float(h1))};
                __nv_bfloat162 lv1 = {__float2bfloat16_rn(v2 - __bfloat162float(h2)),
                                      __float2bfloat16_rn(v3 - __bfloat162float(h3))};
                *(__nv_bfloat162*)&Ohi[(size_t)r0 * N + c0]       = hv0;
                *(__nv_bfloat162*)&Olo[(size_t)r0 * N + c0]       = lv0;
                *(__nv_bfloat162*)&Ohi[(size_t)(r0 + 8) * N + c0] = hv1;
                *(__nv_bfloat162*)&Olo[(size_t)(r0 + 8) * N + c0] = lv1;
            }
        }
    }
}

// ---------------- tensor-core flash attention + autocorrelation ----------------
// BM=128, BN=64, 8 warps (16 rows each). Q resident in regs (3-term split QK^T),
// P packed to bf16 in-register (FA2 identity), PV 2-term split.
// smem (bf16): Qhi[128*72] Qlo[128*72] | 2 x { Khi Klo Vhi Vlo each 64*72 } | acb fp32[2048]
#define FSTR 72
#define Q_ELEMS (128 * FSTR)     // 9216
#define KV_ONE  (64 * FSTR)      // 4608
#define KV_BUF  (4 * KV_ONE)     // 18432
#define KV_BASE (2 * Q_ELEMS)    // 18432
#define ACB_BYTE (2 * (KV_BASE + 2 * KV_BUF))   // 110592
#define FLASH_SMEM (ACB_BYTE + SQ * 4)          // 118784
__global__ __launch_bounds__(256) void flash_kernel(
    const __nv_bfloat16* __restrict__ Qhi_, const __nv_bfloat16* __restrict__ Qlo_,
    const __nv_bfloat16* __restrict__ Khi_, const __nv_bfloat16* __restrict__ Klo_,
    const __nv_bfloat16* __restrict__ Vhi_, const __nv_bfloat16* __restrict__ Vlo_,
    const float* __restrict__ mask, float* __restrict__ Comb, float* __restrict__ ac)
{
    extern __shared__ __nv_bfloat16 smb[];
    float* acb = (float*)((char*)smb + ACB_BYTE);
    uint32_t sbase = (uint32_t)__cvta_generic_to_shared(smb);

    int tid = threadIdx.x;
    int lane = tid & 31, wid = tid >> 5;
    int qb = blockIdx.x, h = blockIdx.y, b = blockIdx.z;
    int t0 = qb * 128;
    int wr = wid * 16;

    size_t hoff = (size_t)b * SQ * HID + h * HD;
    const __nv_bfloat16* Qh = Qhi_ + hoff;
    const __nv_bfloat16* Ql = Qlo_ + hoff;
    const __nv_bfloat16* Kh = Khi_ + hoff;
    const __nv_bfloat16* Kl = Klo_ + hoff;
    const __nv_bfloat16* Vh = Vhi_ + hoff;
    const __nv_bfloat16* Vl = Vlo_ + hoff;
    const float* Mbase = mask + (size_t)b * SQ * SQ;
    float* acrow = ac + (size_t)(b * NH + h) * SQ;

#define LOAD_KV(bufi, kti)                                                              \
    do {                                                                                \
        int s0_ = (kti) * 64;                                                           \
        unsigned kvo_ = KV_BASE + (bufi) * KV_BUF;                                      \
        _Pragma("unroll")                                                               \
        for (int kk = 0; kk < 2; kk++) {                                                \
            int id_ = tid + kk * 256;                                                   \
            int r_ = id_ >> 3, c8_ = (id_ & 7) * 8;                                     \
            size_t src_ = (size_t)(s0_ + r_) * HID + c8_;                               \
            unsigned dst_ = kvo_ + r_ * FSTR + c8_;                                     \
            cp_async16(&smb[dst_],              Kh + src_);                             \
            cp_async16(&smb[dst_ + KV_ONE],     Kl + src_);                             \
            cp_async16(&smb[dst_ + 2 * KV_ONE], Vh + src_);                             \
            cp_async16(&smb[dst_ + 3 * KV_ONE], Vl + src_);                             \
        }                                                                               \
    } while (0)

    // Q tile (group A)
#pragma unroll
    for (int k = 0; k < 4; k++) {
        int id = tid + k * 256;
        int r = id >> 3, c8 = (id & 7) * 8;
        size_t src = (size_t)(t0 + r) * HID + c8;
        cp_async16(&smb[r * FSTR + c8],           Qh + src);
        cp_async16(&smb[Q_ELEMS + r * FSTR + c8], Ql + src);
    }
    cp_commit();
    LOAD_KV(0, 0);
    cp_commit();
    for (int i = tid; i < SQ; i += 256) acb[i] = 0.f;
    cp_wait1();          // Q done, KV0 may be in flight
    __syncthreads();

    // Q fragments (resident)
    uint32_t qhi[4][4], qlo[4][4];
    int lr = lane & 15, kh8 = (lane >> 4) * 8;
#pragma unroll
    for (int ks = 0; ks < 4; ks++) {
        uint32_t off = sbase + 2 * ((wr + lr) * FSTR + ks * 16 + kh8);
        ldsm_x4(qhi[ks], off);
        ldsm_x4(qlo[ks], off + 2 * Q_ELEMS);
    }

    float m0 = -INFINITY, m1 = -INFINITY, l0 = 0.f, l1 = 0.f;
    float o[8][4];
#pragma unroll
    for (int df = 0; df < 8; df++)
#pragma unroll
        for (int r = 0; r < 4; r++) o[df][r] = 0.f;

    int r4 = lane >> 2, c2 = (lane & 3) * 2;
    int qrow = t0 + wr + r4;
    int kr8 = lane & 7, kseg = ((lane >> 3) & 1) * 8;

    for (int kt = 0; kt < 32; kt++) {
        int s0 = kt * 64;
        if (kt + 1 < 32) { LOAD_KV((kt + 1) & 1, kt + 1); cp_commit(); cp_wait1(); }
        else cp_wait0();
        __syncthreads();
        uint32_t kvb = sbase + 2 * (KV_BASE + (kt & 1) * KV_BUF);

        // scores: S = Qhi*Khi + Qhi*Klo + Qlo*Khi  (raw, fp32 acc)
        float s[8][4];
#pragma unroll
        for (int nf = 0; nf < 8; nf++)
#pragma unroll
            for (int r = 0; r < 4; r++) s[nf][r] = 0.f;
#pragma unroll
        for (int ks = 0; ks < 4; ks++) {
#pragma unroll
            for (int nf = 0; nf < 8; nf++) {
                uint32_t ko = kvb + 2 * ((nf * 8 + kr8) * FSTR + ks * 16 + kseg);
                uint32_t bh[2], bl[2];
                ldsm_x2(bh, ko);
                ldsm_x2(bl, ko + 2 * KV_ONE);
                mma16816(s[nf], qhi[ks], bh);
                mma16816(s[nf], qhi[ks], bl);
                mma16816(s[nf], qlo[ks], bh);
            }
        }

        // autocorrelation bins from RAW scores
        {
            float bins[9][2];
#pragma unroll
            for (int bb = 0; bb < 9; bb++) { bins[bb][0] = 0.f; bins[bb][1] = 0.f; }
#pragma unroll
            for (int nf = 0; nf < 8; nf++) {
                bins[nf + 1][0] += s[nf][0];
                bins[nf + 1][1] += s[nf][1];
                bins[nf][0]     += s[nf][2];
                bins[nf][1]     += s[nf][3];
            }
            int base = qrow - s0 - c2;
#pragma unroll
            for (int bb = 0; bb < 9; bb++) {
                int tau = base - 8 * (bb - 1);
                atomicAdd(&acb[tau & (SQ - 1)],       bins[bb][0] * (1.f / 64.f));
                atomicAdd(&acb[(tau - 1) & (SQ - 1)], bins[bb][1] * (1.f / 64.f));
            }
        }

        // scale + mask + row max
        const float* mrow0 = Mbase + (size_t)qrow * SQ + s0 + c2;
        const float* mrow1 = mrow0 + 8 * SQ;
        float mx0 = -INFINITY, mx1 = -INFINITY;
#pragma unroll
        for (int nf = 0; nf < 8; nf++) {
            float2 ma = *(const float2*)(mrow0 + nf * 8);
            float2 mb = *(const float2*)(mrow1 + nf * 8);
            s[nf][0] = s[nf][0] * 0.125f + ma.x;
            s[nf][1] = s[nf][1] * 0.125f + ma.y;
            s[nf][2] = s[nf][2] * 0.125f + mb.x;
            s[nf][3] = s[nf][3] * 0.125f + mb.y;
            mx0 = fmaxf(mx0, fmaxf(s[nf][0], s[nf][1]));
            mx1 = fmaxf(mx1, fmaxf(s[nf][2], s[nf][3]));
        }
        mx0 = fmaxf(mx0, __shfl_xor_sync(0xffffffffu, mx0, 1));
        mx0 = fmaxf(mx0, __shfl_xor_sync(0xffffffffu, mx0, 2));
        mx1 = fmaxf(mx1, __shfl_xor_sync(0xffffffffu, mx1, 1));
        mx1 = fmaxf(mx1, __shfl_xor_sync(0xffffffffu, mx1, 2));
        float nm0 = fmaxf(m0, mx0), nm1 = fmaxf(m1, mx1);
        float cor0 = __expf(m0 - nm0), cor1 = __expf(m1 - nm1);
        m0 = nm0; m1 = nm1;

        // exp -> bf16 P (a-frag packing), consistent row sums from bf16 values
        uint32_t pa[4][4];
        float rs0 = 0.f, rs1 = 0.f;
#pragma unroll
        for (int kc = 0; kc < 4; kc++) {
            int n0 = 2 * kc, n1 = 2 * kc + 1;
            pa[kc][0] = pack_bf2(__expf(s[n0][0] - nm0), __expf(s[n0][1] - nm0));
            pa[kc][1] = pack_bf2(__expf(s[n0][2] - nm1), __expf(s[n0][3] - nm1));
            pa[kc][2] = pack_bf2(__expf(s[n1][0] - nm0), __expf(s[n1][1] - nm0));
            pa[kc][3] = pack_bf2(__expf(s[n1][2] - nm1), __expf(s[n1][3] - nm1));
            float2 u;
            u = __bfloat1622float2(*(__nv_bfloat162*)&pa[kc][0]); rs0 += u.x + u.y;
            u = __bfloat1622float2(*(__nv_bfloat162*)&pa[kc][2]); rs0 += u.x + u.y;
            u = __bfloat1622float2(*(__nv_bfloat162*)&pa[kc][1]); rs1 += u.x + u.y;
            u = __bfloat1622float2(*(__nv_bfloat162*)&pa[kc][3]); rs1 += u.x + u.y;
        }
        rs0 += __shfl_xor_sync(0xffffffffu, rs0, 1);
        rs0 += __shfl_xor_sync(0xffffffffu, rs0, 2);
        rs1 += __shfl_xor_sync(0xffffffffu, rs1, 1);
        rs1 += __shfl_xor_sync(0xffffffffu, rs1, 2);
        l0 = l0 * cor0 + rs0;
        l1 = l1 * cor1 + rs1;
#pragma unroll
        for (int df = 0; df < 8; df++) {
            o[df][0] *= cor0; o[df][1] *= cor0;
            o[df][2] *= cor1; o[df][3] *= cor1;
        }

        // O += P @ (Vhi + Vlo)
#pragma unroll
        for (int kc = 0; kc < 4; kc++) {
#pragma unroll
            for (int df = 0; df < 8; df++) {
                uint32_t vo = kvb + 2 * (2 * KV_ONE + (kc * 16 + lr) * FSTR + df * 8);
                uint32_t vh[2], vl[2];
                ldsm_x2t(vh, vo);
                ldsm_x2t(vl, vo + 2 * KV_ONE);
                mma16816(o[df], pa[kc], vh);
                mma16816(o[df], pa[kc], vl);
            }
        }
        __syncthreads();
    }

    // flush tau bins
    for (int i = tid; i < SQ; i += 256)
        atomicAdd(&acrow[i], acb[i]);

    // epilogue: Comb = 0.5 * ctx
    float inv0 = 0.5f / l0, inv1 = 0.5f / l1;
    float* C0 = Comb + (size_t)b * SQ * HID + (size_t)qrow * HID + h * HD + c2;
#pragma unroll
    for (int df = 0; df < 8; df++) {
        float2 va = { o[df][0] * inv0, o[df][1] * inv0 };
        float2 vb = { o[df][2] * inv1, o[df][3] * inv1 };
        *(float2*)(C0 + df * 8)            = va;
        *(float2*)(C0 + 8 * HID + df * 8)  = vb;
    }
}

// ---------------- top-k (k=15) + softmax weights ----------------
__global__ __launch_bounds__(256) void topk_kernel(
    const float* __restrict__ ac, int* __restrict__ topi, float* __restrict__ topw)
{
    int bh = blockIdx.x;
    __shared__ float svv[SQ];
    __shared__ float rv[256];
    __shared__ int ri[256];
    __shared__ float tvals[KTOP];
    __shared__ int tidxs[KTOP];
    int tid = threadIdx.x;

    for (int i = tid; i < SQ; i += 256)
        svv[i] = ac[(size_t)bh * SQ + i];
    __syncthreads();

    for (int t = 0; t < KTOP; t++) {
        float bv = -INFINITY;
        int bi = 0;
        for (int i = tid; i < SQ; i += 256) {
            float v = svv[i];
            if (v > bv || (v == bv && i < bi)) { bv = v; bi = i; }
        }
        rv[tid] = bv; ri[tid] = bi;
        __syncthreads();
        for (int st = 128; st > 0; st >>= 1) {
            if (tid < st) {
                float v2 = rv[tid + st]; int i2 = ri[tid + st];
                if (v2 > rv[tid] || (v2 == rv[tid] && i2 < ri[tid])) { rv[tid] = v2; ri[tid] = i2; }
            }
            __syncthreads();
        }
        if (tid == 0) {
            tvals[t] = rv[0]; tidxs[t] = ri[0];
            svv[ri[0]] = -INFINITY;
        }
        __syncthreads();
    }

    if (tid == 0) {
        float mx = tvals[0];
        float e[KTOP], ssum = 0.f;
#pragma unroll
        for (int t = 0; t < KTOP; t++) { e[t] = __expf(tvals[t] - mx); ssum += e[t]; }
        float inv = 1.f / ssum;
#pragma unroll
        for (int t = 0; t < KTOP; t++) {
            topw[bh * KTOP + t] = e[t] * inv;
            topi[bh * KTOP + t] = tidxs[t];
        }
    }
}

// ---------------- frequency branch gather ----------------
__global__ __launch_bounds__(256) void freq_kernel(
    const float* __restrict__ V, const int* __restrict__ topi,
    const float* __restrict__ topw, float* __restrict__ Comb)
{
    int t = blockIdx.x, b = blockIdx.y;
    __shared__ int si[NH * KTOP];
    __shared__ float sw[NH * KTOP];
    int tid = threadIdx.x;
    if (tid < NH * KTOP) {
        si[tid] = topi[b * NH * KTOP + tid];
        sw[tid] = topw[b * NH * KTOP + tid];
    }
    __syncthreads();

    int c = tid * 4;
    int h = c >> 6;
    float* crow = Comb + ((size_t)b * SQ + t) * HID + c;
    float4 acc = *(float4*)crow;
    const float* Vb = V + (size_t)b * SQ * HID;
#pragma unroll
    for (int j = 0; j < KTOP; j++) {
        int row = (t + si[h * KTOP + j]) & (SQ - 1);
        float w = 0.5f * sw[h * KTOP + j];
        float4 v = *(const float4*)&Vb[(size_t)row * HID + c];
        acc.x += w * v.x; acc.y += w * v.y; acc.z += w * v.z; acc.w += w * v.w;
    }
    *(float4*)crow = acc;
}

// ---------------- launcher ----------------
extern "C" void kernel_launch(void* const* d_in, const int* in_sizes, int n_in,
                              void* d_out, int out_size)
{
    const float* X    = (const float*)d_in[0];
    const float* mask = (const float*)d_in[1];
    const float* Wq   = (const float*)d_in[2];
    const float* bq   = (const float*)d_in[3];
    const float* Wk   = (const float*)d_in[4];
    const float* bk   = (const float*)d_in[5];
    const float* Wv   = (const float*)d_in[6];
    const float* bv   = (const float*)d_in[7];
    const float* Wo   = (const float*)d_in[8];
    const float* bo   = (const float*)d_in[9];
    const int*   li   = (const int*)d_in[10];
    const int*   nl   = (const int*)d_in[11];
    float* out = (float*)d_out;

    float *cP, *dcP, *VbP, *CbP, *acP, *twP;
    int* tiP;
    __nv_bfloat16 *chiP, *cloP, *ChiP, *CloP, *XhiP, *XloP, *XfhiP, *XfloP, *CbhiP, *CbloP;
    __nv_bfloat16 *QfhiP, *QfloP, *KfhiP, *KfloP, *VfhiP, *VfloP;
    __nv_bfloat16 *WqhiP, *WqloP, *WkhiP, *WkloP, *WvhiP, *WvloP, *WohiP, *WoloP;
    cudaGetSymbolAddress((void**)&cP,  d_c);
    cudaGetSymbolAddress((void**)&dcP, d_dcflag);
    cudaGetSymbolAddress((void**)&VbP, d_Vbuf);
    cudaGetSymbolAddress((void**)&CbP, d_Comb);
    cudaGetSymbolAddress((void**)&acP, d_ac);
    cudaGetSymbolAddress((void**)&tiP, d_topi);
    cudaGetSymbolAddress((void**)&twP, d_topw);
    cudaGetSymbolAddress((void**)&chiP, d_chi);
    cudaGetSymbolAddress((void**)&cloP, d_clo);
    cudaGetSymbolAddress((void**)&ChiP, d_Chi);
    cudaGetSymbolAddress((void**)&CloP, d_Clo);
    cudaGetSymbolAddress((void**)&XhiP, d_Xhi);
    cudaGetSymbolAddress((void**)&XloP, d_Xlo);
    cudaGetSymbolAddress((void**)&XfhiP, d_Xfhi);
    cudaGetSymbolAddress((void**)&XfloP, d_Xflo);
    cudaGetSymbolAddress((void**)&QfhiP, d_Qfhi);
    cudaGetSymbolAddress((void**)&QfloP, d_Qflo);
    cudaGetSymbolAddress((void**)&KfhiP, d_Kfhi);
    cudaGetSymbolAddress((void**)&KfloP, d_Kflo);
    cudaGetSymbolAddress((void**)&VfhiP, d_Vfhi);
    cudaGetSymbolAddress((void**)&VfloP, d_Vflo);
    cudaGetSymbolAddress((void**)&CbhiP, d_Cbhi);
    cudaGetSymbolAddress((void**)&CbloP, d_Cblo);
    cudaGetSymbolAddress((void**)&WqhiP, d_Wqhi);
    cudaGetSymbolAddress((void**)&WqloP, d_Wqlo);
    cudaGetSymbolAddress((void**)&WkhiP, d_Wkhi);
    cudaGetSymbolAddress((void**)&WkloP, d_Wklo);
    cudaGetSymbolAddress((void**)&WvhiP, d_Wvhi);
    cudaGetSymbolAddress((void**)&WvloP, d_Wvlo);
    cudaGetSymbolAddress((void**)&WohiP, d_Wohi);
    cudaGetSymbolAddress((void**)&WoloP, d_Wolo);

    const long long SH = (long long)SQ * HID;
    const int NELT = BSZ * SQ * HID;
    const int WELT = HID * HID;

    static bool attrs_set = false;
    if (!attrs_set) {
        cudaFuncSetAttribute(gemm_bf16_kernel, cudaFuncAttributeMaxDynamicSharedMemorySize, 75776);
        cudaFuncSetAttribute(flash_kernel,     cudaFuncAttributeMaxDynamicSharedMemorySize, FLASH_SMEM);
        attrs_set = true;
    }

    // 1) filter taps + circulant (bf16)
    filter_kernel<<<8, 256>>>(li, nl, cP, dcP, chiP, cloP);
    cmat_kernel<<<(SQ * SQ) / 256, 256>>>(ChiP, CloP, chiP, cloP);

    // 2) split inputs
    split_kernel<<<NELT / 256, 256>>>(X, XhiP, XloP, NELT);
    split_kernel<<<WELT / 256, 256>>>(Wq, WqhiP, WqloP, WELT);
    split_kernel<<<WELT / 256, 256>>>(Wk, WkhiP, WkloP, WELT);
    split_kernel<<<WELT / 256, 256>>>(Wv, WvhiP, WvloP, WELT);
    split_kernel<<<WELT / 256, 256>>>(Wo, WohiP, WoloP, WELT);

    // 3) Xf = C @ X  -> bf16 hi/lo directly
    gemm_bf16_kernel<<<dim3(HID / 128, SQ / 128, BSZ), 256, 75776>>>(
        ChiP, CloP, XhiP, XloP, nullptr, nullptr, nullptr, XfhiP, XfloP, SQ, HID, SQ, 0, SH, SH);

    // 4) projections -> bf16 hi/lo for flash; Vbuf fp32 for freq branch
    gemm_bf16_kernel<<<dim3(HID / 128, SQ / 128, BSZ), 256, 75776>>>(
        XfhiP, XfloP, WqhiP, WqloP, bq, dcP, nullptr, QfhiP, QfloP, SQ, HID, HID, SH, 0, SH);
    gemm_bf16_kernel<<<dim3(HID / 128, SQ / 128, BSZ), 256, 75776>>>(
        XfhiP, XfloP, WkhiP, WkloP, bk, dcP, nullptr, KfhiP, KfloP, SQ, HID, HID, SH, 0, SH);
    gemm_bf16_kernel<<<dim3(HID / 128, SQ / 128, BSZ), 256, 75776>>>(
        XfhiP, XfloP, WvhiP, WvloP, bv, dcP, nullptr, VfhiP, VfloP, SQ, HID, HID, SH, 0, SH);
    gemm_bf16_kernel<<<dim3(HID / 128, SQ / 128, BSZ), 256, 75776>>>(
        XhiP, XloP, WvhiP, WvloP, bv, nullptr, VbP, nullptr, nullptr, SQ, HID, HID, SH, 0, SH);

    // 5) flash attention (tensor cores) + autocorrelation
    zero_kernel<<<(BSZ * NH * SQ) / 256, 256>>>(acP, BSZ * NH * SQ);
    flash_kernel<<<dim3(SQ / 128, NH, BSZ), 256, FLASH_SMEM>>>(
        QfhiP, QfloP, KfhiP, KfloP, VfhiP, VfloP, mask, CbP, acP);

    // 6) top-k + frequency gather
    topk_kernel<<<BSZ * NH, 256>>>(acP, tiP, twP);
    freq_kernel<<<dim3(SQ, BSZ), 256>>>(VbP, tiP, twP, CbP);

    // 7) output projection
    split_kernel<<<NELT / 256, 256>>>(CbP, CbhiP, CbloP, NELT);
    gemm_bf16_kernel<<<dim3(HID / 128, (BSZ * SQ) / 128, 1), 256, 75776>>>(
        CbhiP, CbloP, WohiP, WoloP, bo, nullptr, out, nullptr, nullptr, BSZ * SQ, HID, HID, 0, 0, 0);
}

// round 7
// speedup vs baseline: 2.0299x; 1.1799x over previous
#include <cuda_runtime.h>
#include <cuda_bf16.h>
#include <math.h>
#include <stdint.h>

#define SQ   2048
#define HID  1024
#define NH   16
#define HD   64
#define BSZ  2
#define MFREQ (SQ/2 + 1)
#define KTOP 15

// ---------------- scratch ----------------
__device__ float d_c[SQ];
__device__ float d_dcflag;
__device__ float d_Vbuf[BSZ * SQ * HID];
__device__ float d_Comb[BSZ * SQ * HID];
__device__ float d_ac  [BSZ * NH * SQ];
__device__ int   d_topi[BSZ * NH * KTOP];
__device__ float d_topw[BSZ * NH * KTOP];

__device__ __nv_bfloat16 d_chi[SQ], d_clo[SQ];
__device__ __nv_bfloat16 d_Chi [SQ * SQ],        d_Clo [SQ * SQ];
__device__ __nv_bfloat16 d_Xhi [BSZ * SQ * HID], d_Xlo [BSZ * SQ * HID];
__device__ __nv_bfloat16 d_Xfhi[BSZ * SQ * HID], d_Xflo[BSZ * SQ * HID];
__device__ __nv_bfloat16 d_Qfhi[BSZ * SQ * HID], d_Qflo[BSZ * SQ * HID];
__device__ __nv_bfloat16 d_Kfhi[BSZ * SQ * HID], d_Kflo[BSZ * SQ * HID];
__device__ __nv_bfloat16 d_Vfhi[BSZ * SQ * HID], d_Vflo[BSZ * SQ * HID];
__device__ __nv_bfloat16 d_Cbhi[BSZ * SQ * HID], d_Cblo[BSZ * SQ * HID];
__device__ __nv_bfloat16 d_Wqhi[HID * HID], d_Wqlo[HID * HID];
__device__ __nv_bfloat16 d_Wkhi[HID * HID], d_Wklo[HID * HID];
__device__ __nv_bfloat16 d_Wvhi[HID * HID], d_Wvlo[HID * HID];
__device__ __nv_bfloat16 d_Wohi[HID * HID], d_Wolo[HID * HID];

// ---------------- cp.async helpers ----------------
__device__ __forceinline__ void cp_async16(void* smem, const void* gmem) {
    unsigned s = (unsigned)__cvta_generic_to_shared(smem);
    asm volatile("cp.async.cg.shared.global [%0], [%1], 16;" :: "r"(s), "l"(gmem));
}
__device__ __forceinline__ void cp_commit() { asm volatile("cp.async.commit_group;"); }
__device__ __forceinline__ void cp_wait0()  { asm volatile("cp.async.wait_group 0;"); }
__device__ __forceinline__ void cp_wait1()  { asm volatile("cp.async.wait_group 1;"); }

// ---------------- mma / ldmatrix helpers ----------------
__device__ __forceinline__ void mma16816(float* d, const uint32_t* a, const uint32_t* b) {
    asm volatile(
        "mma.sync.aligned.m16n8k16.row.col.f32.bf16.bf16.f32 "
        "{%0,%1,%2,%3}, {%4,%5,%6,%7}, {%8,%9}, {%0,%1,%2,%3};"
        : "+f"(d[0]), "+f"(d[1]), "+f"(d[2]), "+f"(d[3])
        : "r"(a[0]), "r"(a[1]), "r"(a[2]), "r"(a[3]), "r"(b[0]), "r"(b[1]));
}
__device__ __forceinline__ void ldsm_x4(uint32_t* r, uint32_t addr) {
    asm volatile("ldmatrix.sync.aligned.m8n8.x4.shared.b16 {%0,%1,%2,%3}, [%4];"
        : "=r"(r[0]), "=r"(r[1]), "=r"(r[2]), "=r"(r[3]) : "r"(addr));
}
__device__ __forceinline__ void ldsm_x2t(uint32_t* r, uint32_t addr) {
    asm volatile("ldmatrix.sync.aligned.m8n8.x2.trans.shared.b16 {%0,%1}, [%2];"
        : "=r"(r[0]), "=r"(r[1]) : "r"(addr));
}
__device__ __forceinline__ void ldsm_x2(uint32_t* r, uint32_t addr) {
    asm volatile("ldmatrix.sync.aligned.m8n8.x2.shared.b16 {%0,%1}, [%2];"
        : "=r"(r[0]), "=r"(r[1]) : "r"(addr));
}
__device__ __forceinline__ uint32_t pack_bf2(float a, float b) {
    __nv_bfloat162 t = __floats2bfloat162_rn(a, b);
    return *(uint32_t*)&t;
}

// ---------------- filter taps ----------------
__global__ void filter_kernel(const int* __restrict__ li_p, const int* __restrict__ nl_p,
                              float* __restrict__ c, float* __restrict__ dcflag,
                              __nv_bfloat16* __restrict__ chi, __nv_bfloat16* __restrict__ clo)
{
    int n = blockIdx.x * blockDim.x + threadIdx.x;
    if (n >= SQ) return;
    int li = *li_p;
    int nl = *nl_p;
    const double ALPHA = 0.5;
    int M = MFREQ;
    int p, q;
    if (ALPHA <= 1.0 / (double)nl) {
        p = (int)(M * (1.0 - (double)(li + 1) / (double)nl));
        q = (int)((double)p + (double)M / (double)nl);
    } else {
        p = (nl > 1) ? (int)(M * (1.0 - ALPHA) * (1.0 - (double)li / (double)(nl - 1))) : 0;
        q = (int)((double)p + ALPHA * (double)M);
    }
    p = max(0, min(p, M - 1));
    q = max(p + 1, min(q, M));

    double acc = 0.0;
    const double w2 = 2.0 / (double)SQ;
    const double w1 = 1.0 / (double)SQ;
    const double tpn = 6.283185307179586476925286766559 * (double)n / (double)SQ;
    for (int f = p; f < q; f++) {
        double wf = (f == 0 || f == M - 1) ? w1 : w2;
        acc += wf * cos(tpn * (double)f);
    }
    float cf = (float)acc;
    c[n] = cf;
    __nv_bfloat16 h = __float2bfloat16_rn(cf);
    chi[n] = h;
    clo[n] = __float2bfloat16_rn(cf - __bfloat162float(h));
    if (n == 0) *dcflag = (p == 0) ? 1.0f : 0.0f;
}

__global__ void cmat_kernel(__nv_bfloat16* __restrict__ Chi, __nv_bfloat16* __restrict__ Clo,
                            const __nv_bfloat16* __restrict__ chi, const __nv_bfloat16* __restrict__ clo)
{
    int idx = blockIdx.x * blockDim.x + threadIdx.x;
    int t = idx >> 11;
    int s = idx & (SQ - 1);
    int tau = (t - s) & (SQ - 1);
    Chi[idx] = chi[tau];
    Clo[idx] = clo[tau];
}

__global__ void split_kernel(const float* __restrict__ in,
                             __nv_bfloat16* __restrict__ hi, __nv_bfloat16* __restrict__ lo, int n)
{
    int i = blockIdx.x * blockDim.x + threadIdx.x;
    if (i >= n) return;
    float f = in[i];
    __nv_bfloat16 h = __float2bfloat16_rn(f);
    hi[i] = h;
    lo[i] = __float2bfloat16_rn(f - __bfloat162float(h));
}

__global__ void zero_kernel(float* __restrict__ p, int n)
{
    int i = blockIdx.x * blockDim.x + threadIdx.x;
    if (i < n) p[i] = 0.f;
}

// ---------------- bf16-split tensor-core GEMM ----------------
#define GA_STR 40
#define GB_STR 136
#define A_BUF_ELEMS (128 * GA_STR)
#define B_BUF_ELEMS (32 * GB_STR)
__global__ __launch_bounds__(256) void gemm_bf16_kernel(
    const __nv_bfloat16* __restrict__ Ahi, const __nv_bfloat16* __restrict__ Alo,
    const __nv_bfloat16* __restrict__ Bhi, const __nv_bfloat16* __restrict__ Blo,
    const float* __restrict__ bias, const float* __restrict__ bscalep,
    float* __restrict__ C,
    __nv_bfloat16* __restrict__ Ohi, __nv_bfloat16* __restrict__ Olo,
    int M, int N, int K,
    long long sA, long long sB, long long sC)
{
    extern __shared__ __nv_bfloat16 sm[];
    __nv_bfloat16* AsHi = sm;
    __nv_bfloat16* AsLo = sm + 2 * A_BUF_ELEMS;
    __nv_bfloat16* BsHi = sm + 4 * A_BUF_ELEMS;
    __nv_bfloat16* BsLo = sm + 4 * A_BUF_ELEMS + 2 * B_BUF_ELEMS;
    uint32_t sbase = (uint32_t)__cvta_generic_to_shared(sm);

    int z = blockIdx.z;
    Ahi += (size_t)z * sA;  Alo += (size_t)z * sA;
    Bhi += (size_t)z * sB;  Blo += (size_t)z * sB;
    if (C)   C   += (size_t)z * sC;
    if (Ohi) { Ohi += (size_t)z * sC; Olo += (size_t)z * sC; }

    int tid = threadIdx.x;
    int lane = tid & 31;
    int wid = tid >> 5;
    int mBase = (wid >> 2) * 64;
    int nBase = (wid & 3) * 32;
    int row0 = blockIdx.y * 128;
    int col0 = blockIdx.x * 128;

    float acc[4][4][4];
#pragma unroll
    for (int mf = 0; mf < 4; mf++)
#pragma unroll
        for (int nf = 0; nf < 4; nf++)
#pragma unroll
            for (int r = 0; r < 4; r++) acc[mf][nf][r] = 0.f;

    int ar = tid >> 1;
    int br = tid >> 3;
    const __nv_bfloat16* Ah0 = Ahi + (size_t)(row0 + ar) * K;
    const __nv_bfloat16* Al0 = Alo + (size_t)(row0 + ar) * K;

#define LOAD_TILES(buf, k0)                                                             \
    do {                                                                                \
        _Pragma("unroll")                                                               \
        for (int j = 0; j < 2; j++) {                                                   \
            int s = (tid & 1) * 2 + j;                                                  \
            cp_async16(&AsHi[(buf) * A_BUF_ELEMS + ar * GA_STR + s * 8],                \
                       Ah0 + (k0) + s * 8);                                             \
            cp_async16(&AsLo[(buf) * A_BUF_ELEMS + ar * GA_STR + s * 8],                \
                       Al0 + (k0) + s * 8);                                             \
            int sb = (tid & 7) * 2 + j;                                                 \
            cp_async16(&BsHi[(buf) * B_BUF_ELEMS + br * GB_STR + sb * 8],               \
                       Bhi + (size_t)((k0) + br) * N + col0 + sb * 8);                  \
            cp_async16(&BsLo[(buf) * B_BUF_ELEMS + br * GB_STR + sb * 8],               \
                       Blo + (size_t)((k0) + br) * N + col0 + sb * 8);                  \
        }                                                                               \
    } while (0)

    LOAD_TILES(0, 0);
    cp_commit();
    cp_wait0();
    __syncthreads();

    int nIter = K >> 5;
    int lr = lane & 15;
    int khalf = (lane >> 4) << 3;

    for (int it = 0; it < nIter; it++) {
        int buf = it & 1;
        if (it + 1 < nIter) {
            LOAD_TILES(buf ^ 1, (it + 1) << 5);
            cp_commit();
        }

        uint32_t aHiB = sbase + 2 * (buf * A_BUF_ELEMS);
        uint32_t aLoB = sbase + 2 * (2 * A_BUF_ELEMS + buf * A_BUF_ELEMS);
        uint32_t bHiB = sbase + 2 * (4 * A_BUF_ELEMS + buf * B_BUF_ELEMS);
        uint32_t bLoB = sbase + 2 * (4 * A_BUF_ELEMS + 2 * B_BUF_ELEMS + buf * B_BUF_ELEMS);

#pragma unroll
        for (int ks = 0; ks < 32; ks += 16) {
            uint32_t ahi[4][4], alo[4][4], bhi[4][2], blo[4][2];
#pragma unroll
            for (int mf = 0; mf < 4; mf++) {
                uint32_t off = 2 * ((mBase + mf * 16 + lr) * GA_STR + ks + khalf);
                ldsm_x4(ahi[mf], aHiB + off);
                ldsm_x4(alo[mf], aLoB + off);
            }
#pragma unroll
            for (int nf = 0; nf < 4; nf++) {
                uint32_t off = 2 * ((ks + lr) * GB_STR + nBase + nf * 8);
                ldsm_x2t(bhi[nf], bHiB + off);
                ldsm_x2t(blo[nf], bLoB + off);
            }
#pragma unroll
            for (int mf = 0; mf < 4; mf++)
#pragma unroll
                for (int nf = 0; nf < 4; nf++) {
                    mma16816(acc[mf][nf], ahi[mf], bhi[nf]);
                    mma16816(acc[mf][nf], ahi[mf], blo[nf]);
                    mma16816(acc[mf][nf], alo[mf], bhi[nf]);
                }
        }

        if (it + 1 < nIter) cp_wait0();
        __syncthreads();
    }

    float bscale = 0.f;
    if (bias) bscale = bscalep ? *bscalep : 1.f;

#pragma unroll
    for (int mf = 0; mf < 4; mf++) {
        int r0 = row0 + mBase + mf * 16 + (lane >> 2);
#pragma unroll
        for (int nf = 0; nf < 4; nf++) {
            int c0 = col0 + nBase + nf * 8 + (lane & 3) * 2;
            float b0 = 0.f, b1 = 0.f;
            if (bias) { b0 = bias[c0] * bscale; b1 = bias[c0 + 1] * bscale; }
            float v0 = acc[mf][nf][0] + b0, v1 = acc[mf][nf][1] + b1;
            float v2 = acc[mf][nf][2] + b0, v3 = acc[mf][nf][3] + b1;
            if (C) {
                float2 w0 = {v0, v1}, w1 = {v2, v3};
                *(float2*)&C[(size_t)r0 * N + c0]       = w0;
                *(float2*)&C[(size_t)(r0 + 8) * N + c0] = w1;
            }
            if (Ohi) {
                __nv_bfloat16 h0 = __float2bfloat16_rn(v0), h1 = __float2bfloat16_rn(v1);
                __nv_bfloat16 h2 = __float2bfloat16_rn(v2), h3 = __float2bfloat16_rn(v3);
                __nv_bfloat162 hv0 = {h0, h1}, hv1 = {h2, h3};
                __nv_bfloat162 lv0 = {__float2bfloat16_rn(v0 - __bfloat162float(h0)),
                                      __float2bfloat16_rn(v1 - __bfloat162float(h1))};
                __nv_bfloat162 lv1 = {__float2bfloat16_rn(v2 - __bfloat162float(h2)),
                                      __float2bfloat16_rn(v3 - __bfloat162float(h3))};
                *(__nv_bfloat162*)&Ohi[(size_t)r0 * N + c0]       = hv0;
                *(__nv_bfloat162*)&Olo[(size_t)r0 * N + c0]       = lv0;
                *(__nv_bfloat162*)&Ohi[(size_t)(r0 + 8) * N + c0] = hv1;
                *(__nv_bfloat162*)&Olo[(size_t)(r0 + 8) * N + c0] = lv1;
            }
        }
    }
}

// ---------------- tensor-core flash attention + diag-sum autocorrelation ----------------
// BM=128, BN=64, 8 warps. Raw scores are staged to a smem tile; a 191-thread
// diagonal-reduction phase (one thread per tau, NO atomics) accumulates ac bins.
#define FSTR 72
#define Q_ELEMS (128 * FSTR)
#define KV_ONE  (64 * FSTR)
#define KV_BUF  (4 * KV_ONE)
#define KV_BASE (2 * Q_ELEMS)
#define ACB_BYTE (2 * (KV_BASE + 2 * KV_BUF))   // 110592
#define SCS 66
#define FLASH_SMEM (ACB_BYTE + SQ * 4 + 128 * SCS * 4)   // 152576
__global__ __launch_bounds__(256) void flash_kernel(
    const __nv_bfloat16* __restrict__ Qhi_, const __nv_bfloat16* __restrict__ Qlo_,
    const __nv_bfloat16* __restrict__ Khi_, const __nv_bfloat16* __restrict__ Klo_,
    const __nv_bfloat16* __restrict__ Vhi_, const __nv_bfloat16* __restrict__ Vlo_,
    const float* __restrict__ mask, float* __restrict__ Comb, float* __restrict__ ac)
{
    extern __shared__ __nv_bfloat16 smb[];
    float* acb   = (float*)((char*)smb + ACB_BYTE);
    float* Stile = acb + SQ;                     // [128][SCS] raw score tile
    uint32_t sbase = (uint32_t)__cvta_generic_to_shared(smb);

    int tid = threadIdx.x;
    int lane = tid & 31, wid = tid >> 5;
    int qb = blockIdx.x, h = blockIdx.y, b = blockIdx.z;
    int t0 = qb * 128;
    int wr = wid * 16;

    size_t hoff = (size_t)b * SQ * HID + h * HD;
    const __nv_bfloat16* Qh = Qhi_ + hoff;
    const __nv_bfloat16* Ql = Qlo_ + hoff;
    const __nv_bfloat16* Kh = Khi_ + hoff;
    const __nv_bfloat16* Kl = Klo_ + hoff;
    const __nv_bfloat16* Vh = Vhi_ + hoff;
    const __nv_bfloat16* Vl = Vlo_ + hoff;
    const float* Mbase = mask + (size_t)b * SQ * SQ;
    float* acrow = ac + (size_t)(b * NH + h) * SQ;

#define LOAD_KV(bufi, kti)                                                              \
    do {                                                                                \
        int s0_ = (kti) * 64;                                                           \
        unsigned kvo_ = KV_BASE + (bufi) * KV_BUF;                                      \
        _Pragma("unroll")                                                               \
        for (int kk = 0; kk < 2; kk++) {                                                \
            int id_ = tid + kk * 256;                                                   \
            int r_ = id_ >> 3, c8_ = (id_ & 7) * 8;                                     \
            size_t src_ = (size_t)(s0_ + r_) * HID + c8_;                               \
            unsigned dst_ = kvo_ + r_ * FSTR + c8_;                                     \
            cp_async16(&smb[dst_],              Kh + src_);                             \
            cp_async16(&smb[dst_ + KV_ONE],     Kl + src_);                             \
            cp_async16(&smb[dst_ + 2 * KV_ONE], Vh + src_);                             \
            cp_async16(&smb[dst_ + 3 * KV_ONE], Vl + src_);                             \
        }                                                                               \
    } while (0)

    // Q tile
#pragma unroll
    for (int k = 0; k < 4; k++) {
        int id = tid + k * 256;
        int r = id >> 3, c8 = (id & 7) * 8;
        size_t src = (size_t)(t0 + r) * HID + c8;
        cp_async16(&smb[r * FSTR + c8],           Qh + src);
        cp_async16(&smb[Q_ELEMS + r * FSTR + c8], Ql + src);
    }
    cp_commit();
    LOAD_KV(0, 0);
    cp_commit();
    for (int i = tid; i < SQ; i += 256) acb[i] = 0.f;
    cp_wait1();
    __syncthreads();

    // Q fragments (resident)
    uint32_t qhi[4][4], qlo[4][4];
    int lr = lane & 15, kh8 = (lane >> 4) * 8;
#pragma unroll
    for (int ks = 0; ks < 4; ks++) {
        uint32_t off = sbase + 2 * ((wr + lr) * FSTR + ks * 16 + kh8);
        ldsm_x4(qhi[ks], off);
        ldsm_x4(qlo[ks], off + 2 * Q_ELEMS);
    }

    float m0 = -INFINITY, m1 = -INFINITY, l0 = 0.f, l1 = 0.f;
    float o[8][4];
#pragma unroll
    for (int df = 0; df < 8; df++)
#pragma unroll
        for (int r = 0; r < 4; r++) o[df][r] = 0.f;

    int r4 = lane >> 2, c2 = (lane & 3) * 2;
    int qrow = t0 + wr + r4;
    int kr8 = lane & 7, kseg = ((lane >> 3) & 1) * 8;

    // diag-phase constants (one thread per tau)
    int du = tid - 63;                       // u = r - c in [-63, 127]
    int drlo = du > 0 ? du : 0;
    int drhi = (du + 64 < 128) ? du + 64 : 128;
    const float* dbase = Stile - du;         // addr = r*SCS + (r-u) = r*(SCS+1) - u

    for (int kt = 0; kt < 32; kt++) {
        int s0 = kt * 64;
        if (kt + 1 < 32) { LOAD_KV((kt + 1) & 1, kt + 1); cp_commit(); cp_wait1(); }
        else cp_wait0();
        __syncthreads();                     // KV ready; prev diag done (Stile free)
        uint32_t kvb = sbase + 2 * (KV_BASE + (kt & 1) * KV_BUF);

        // scores: S = Qhi*Khi + Qhi*Klo + Qlo*Khi  (raw, fp32 acc)
        float s[8][4];
#pragma unroll
        for (int nf = 0; nf < 8; nf++)
#pragma unroll
            for (int r = 0; r < 4; r++) s[nf][r] = 0.f;
#pragma unroll
        for (int ks = 0; ks < 4; ks++) {
#pragma unroll
            for (int nf = 0; nf < 8; nf++) {
                uint32_t ko = kvb + 2 * ((nf * 8 + kr8) * FSTR + ks * 16 + kseg);
                uint32_t bh[2], bl[2];
                ldsm_x2(bh, ko);
                ldsm_x2(bl, ko + 2 * KV_ONE);
                mma16816(s[nf], qhi[ks], bh);
                mma16816(s[nf], qhi[ks], bl);
                mma16816(s[nf], qlo[ks], bh);
            }
        }

        // stage RAW scores for the diag-reduction phase
        {
            float* Sw0 = Stile + (wr + r4) * SCS + c2;
            float* Sw1 = Sw0 + 8 * SCS;
#pragma unroll
            for (int nf = 0; nf < 8; nf++) {
                float2 w0 = { s[nf][0], s[nf][1] };
                float2 w1 = { s[nf][2], s[nf][3] };
                *(float2*)(Sw0 + nf * 8) = w0;
                *(float2*)(Sw1 + nf * 8) = w1;
            }
        }

        // scale + mask + row max
        const float* mrow0 = Mbase + (size_t)qrow * SQ + s0 + c2;
        const float* mrow1 = mrow0 + 8 * SQ;
        float mx0 = -INFINITY, mx1 = -INFINITY;
#pragma unroll
        for (int nf = 0; nf < 8; nf++) {
            float2 ma = *(const float2*)(mrow0 + nf * 8);
            float2 mb = *(const float2*)(mrow1 + nf * 8);
            s[nf][0] = s[nf][0] * 0.125f + ma.x;
            s[nf][1] = s[nf][1] * 0.125f + ma.y;
            s[nf][2] = s[nf][2] * 0.125f + mb.x;
            s[nf][3] = s[nf][3] * 0.125f + mb.y;
            mx0 = fmaxf(mx0, fmaxf(s[nf][0], s[nf][1]));
            mx1 = fmaxf(mx1, fmaxf(s[nf][2], s[nf][3]));
        }
        mx0 = fmaxf(mx0, __shfl_xor_sync(0xffffffffu, mx0, 1));
        mx0 = fmaxf(mx0, __shfl_xor_sync(0xffffffffu, mx0, 2));
        mx1 = fmaxf(mx1, __shfl_xor_sync(0xffffffffu, mx1, 1));
        mx1 = fmaxf(mx1, __shfl_xor_sync(0xffffffffu, mx1, 2));
        float nm0 = fmaxf(m0, mx0), nm1 = fmaxf(m1, mx1);
        float cor0 = __expf(m0 - nm0), cor1 = __expf(m1 - nm1);
        m0 = nm0; m1 = nm1;

        // exp -> bf16 P (a-frag packing), row sums from bf16 values
        uint32_t pa[4][4];
        float rs0 = 0.f, rs1 = 0.f;
#pragma unroll
        for (int kc = 0; kc < 4; kc++) {
            int n0 = 2 * kc, n1 = 2 * kc + 1;
            pa[kc][0] = pack_bf2(__expf(s[n0][0] - nm0), __expf(s[n0][1] - nm0));
            pa[kc][1] = pack_bf2(__expf(s[n0][2] - nm1), __expf(s[n0][3] - nm1));
            pa[kc][2] = pack_bf2(__expf(s[n1][0] - nm0), __expf(s[n1][1] - nm0));
            pa[kc][3] = pack_bf2(__expf(s[n1][2] - nm1), __expf(s[n1][3] - nm1));
            float2 u;
            u = __bfloat1622float2(*(__nv_bfloat162*)&pa[kc][0]); rs0 += u.x + u.y;
            u = __bfloat1622float2(*(__nv_bfloat162*)&pa[kc][2]); rs0 += u.x + u.y;
            u = __bfloat1622float2(*(__nv_bfloat162*)&pa[kc][1]); rs1 += u.x + u.y;
            u = __bfloat1622float2(*(__nv_bfloat162*)&pa[kc][3]); rs1 += u.x + u.y;
        }
        rs0 += __shfl_xor_sync(0xffffffffu, rs0, 1);
        rs0 += __shfl_xor_sync(0xffffffffu, rs0, 2);
        rs1 += __shfl_xor_sync(0xffffffffu, rs1, 1);
        rs1 += __shfl_xor_sync(0xffffffffu, rs1, 2);
        l0 = l0 * cor0 + rs0;
        l1 = l1 * cor1 + rs1;
#pragma unroll
        for (int df = 0; df < 8; df++) {
            o[df][0] *= cor0; o[df][1] *= cor0;
            o[df][2] *= cor1; o[df][3] *= cor1;
        }

        // O += P @ (Vhi + Vlo)
#pragma unroll
        for (int kc = 0; kc < 4; kc++) {
#pragma unroll
            for (int df = 0; df < 8; df++) {
                uint32_t vo = kvb + 2 * (2 * KV_ONE + (kc * 16 + lr) * FSTR + df * 8);
                uint32_t vh[2], vl[2];
                ldsm_x2t(vh, vo);
                ldsm_x2t(vl, vo + 2 * KV_ONE);
                mma16816(o[df], pa[kc], vh);
                mma16816(o[df], pa[kc], vl);
            }
        }
        __syncthreads();                     // Stile fully written; KV buf reads done

        // diagonal reduction: one thread per tau, NO atomics
        if (tid < 191) {
            float sa = 0.f, sb = 0.f;
            int r = drlo;
            for (; r + 1 < drhi; r += 2) {
                sa += dbase[r * (SCS + 1)];
                sb += dbase[r * (SCS + 1) + (SCS + 1)];
            }
            if (r < drhi) sa += dbase[r * (SCS + 1)];
            int tau = (t0 - s0 + du) & (SQ - 1);
            acb[tau] += (sa + sb) * (1.f / 64.f);
        }
    }

    // flush tau bins
    __syncthreads();
    for (int i = tid; i < SQ; i += 256)
        atomicAdd(&acrow[i], acb[i]);

    // epilogue: Comb = 0.5 * ctx
    float inv0 = 0.5f / l0, inv1 = 0.5f / l1;
    float* C0 = Comb + (size_t)b * SQ * HID + (size_t)qrow * HID + h * HD + c2;
#pragma unroll
    for (int df = 0; df < 8; df++) {
        float2 va = { o[df][0] * inv0, o[df][1] * inv0 };
        float2 vb = { o[df][2] * inv1, o[df][3] * inv1 };
        *(float2*)(C0 + df * 8)            = va;
        *(float2*)(C0 + 8 * HID + df * 8)  = vb;
    }
}

// ---------------- top-k (k=15) + softmax weights ----------------
__global__ __launch_bounds__(256) void topk_kernel(
    const float* __restrict__ ac, int* __restrict__ topi, float* __restrict__ topw)
{
    int bh = blockIdx.x;
    __shared__ float svv[SQ];
    __shared__ float rv[256];
    __shared__ int ri[256];
    __shared__ float tvals[KTOP];
    __shared__ int tidxs[KTOP];
    int tid = threadIdx.x;

    for (int i = tid; i < SQ; i += 256)
        svv[i] = ac[(size_t)bh * SQ + i];
    __syncthreads();

    for (int t = 0; t < KTOP; t++) {
        float bv = -INFINITY;
        int bi = 0;
        for (int i = tid; i < SQ; i += 256) {
            float v = svv[i];
            if (v > bv || (v == bv && i < bi)) { bv = v; bi = i; }
        }
        rv[tid] = bv; ri[tid] = bi;
        __syncthreads();
        for (int st = 128; st > 0; st >>= 1) {
            if (tid < st) {
                float v2 = rv[tid + st]; int i2 = ri[tid + st];
                if (v2 > rv[tid] || (v2 == rv[tid] && i2 < ri[tid])) { rv[tid] = v2; ri[tid] = i2; }
            }
            __syncthreads();
        }
        if (tid == 0) {
            tvals[t] = rv[0]; tidxs[t] = ri[0];
            svv[ri[0]] = -INFINITY;
        }
        __syncthreads();
    }

    if (tid == 0) {
        float mx = tvals[0];
        float e[KTOP], ssum = 0.f;
#pragma unroll
        for (int t = 0; t < KTOP; t++) { e[t] = __expf(tvals[t] - mx); ssum += e[t]; }
        float inv = 1.f / ssum;
#pragma unroll
        for (int t = 0; t < KTOP; t++) {
            topw[bh * KTOP + t] = e[t] * inv;
            topi[bh * KTOP + t] = tidxs[t];
        }
    }
}

// ---------------- frequency branch gather ----------------
__global__ __launch_bounds__(256) void freq_kernel(
    const float* __restrict__ V, const int* __restrict__ topi,
    const float* __restrict__ topw, float* __restrict__ Comb)
{
    int t = blockIdx.x, b = blockIdx.y;
    __shared__ int si[NH * KTOP];
    __shared__ float sw[NH * KTOP];
    int tid = threadIdx.x;
    if (tid < NH * KTOP) {
        si[tid] = topi[b * NH * KTOP + tid];
        sw[tid] = topw[b * NH * KTOP + tid];
    }
    __syncthreads();

    int c = tid * 4;
    int h = c >> 6;
    float* crow = Comb + ((size_t)b * SQ + t) * HID + c;
    float4 acc = *(float4*)crow;
    const float* Vb = V + (size_t)b * SQ * HID;
#pragma unroll
    for (int j = 0; j < KTOP; j++) {
        int row = (t + si[h * KTOP + j]) & (SQ - 1);
        float w = 0.5f * sw[h * KTOP + j];
        float4 v = *(const float4*)&Vb[(size_t)row * HID + c];
        acc.x += w * v.x; acc.y += w * v.y; acc.z += w * v.z; acc.w += w * v.w;
    }
    *(float4*)crow = acc;
}

// ---------------- launcher ----------------
extern "C" void kernel_launch(void* const* d_in, const int* in_sizes, int n_in,
                              void* d_out, int out_size)
{
    const float* X    = (const float*)d_in[0];
    const float* mask = (const float*)d_in[1];
    const float* Wq   = (const float*)d_in[2];
    const float* bq   = (const float*)d_in[3];
    const float* Wk   = (const float*)d_in[4];
    const float* bk   = (const float*)d_in[5];
    const float* Wv   = (const float*)d_in[6];
    const float* bv   = (const float*)d_in[7];
    const float* Wo   = (const float*)d_in[8];
    const float* bo   = (const float*)d_in[9];
    const int*   li   = (const int*)d_in[10];
    const int*   nl   = (const int*)d_in[11];
    float* out = (float*)d_out;

    float *cP, *dcP, *VbP, *CbP, *acP, *twP;
    int* tiP;
    __nv_bfloat16 *chiP, *cloP, *ChiP, *CloP, *XhiP, *XloP, *XfhiP, *XfloP, *CbhiP, *CbloP;
    __nv_bfloat16 *QfhiP, *QfloP, *KfhiP, *KfloP, *VfhiP, *VfloP;
    __nv_bfloat16 *WqhiP, *WqloP, *WkhiP, *WkloP, *WvhiP, *WvloP, *WohiP, *WoloP;
    cudaGetSymbolAddress((void**)&cP,  d_c);
    cudaGetSymbolAddress((void**)&dcP, d_dcflag);
    cudaGetSymbolAddress((void**)&VbP, d_Vbuf);
    cudaGetSymbolAddress((void**)&CbP, d_Comb);
    cudaGetSymbolAddress((void**)&acP, d_ac);
    cudaGetSymbolAddress((void**)&tiP, d_topi);
    cudaGetSymbolAddress((void**)&twP, d_topw);
    cudaGetSymbolAddress((void**)&chiP, d_chi);
    cudaGetSymbolAddress((void**)&cloP, d_clo);
    cudaGetSymbolAddress((void**)&ChiP, d_Chi);
    cudaGetSymbolAddress((void**)&CloP, d_Clo);
    cudaGetSymbolAddress((void**)&XhiP, d_Xhi);
    cudaGetSymbolAddress((void**)&XloP, d_Xlo);
    cudaGetSymbolAddress((void**)&XfhiP, d_Xfhi);
    cudaGetSymbolAddress((void**)&XfloP, d_Xflo);
    cudaGetSymbolAddress((void**)&QfhiP, d_Qfhi);
    cudaGetSymbolAddress((void**)&QfloP, d_Qflo);
    cudaGetSymbolAddress((void**)&KfhiP, d_Kfhi);
    cudaGetSymbolAddress((void**)&KfloP, d_Kflo);
    cudaGetSymbolAddress((void**)&VfhiP, d_Vfhi);
    cudaGetSymbolAddress((void**)&VfloP, d_Vflo);
    cudaGetSymbolAddress((void**)&CbhiP, d_Cbhi);
    cudaGetSymbolAddress((void**)&CbloP, d_Cblo);
    cudaGetSymbolAddress((void**)&WqhiP, d_Wqhi);
    cudaGetSymbolAddress((void**)&WqloP, d_Wqlo);
    cudaGetSymbolAddress((void**)&WkhiP, d_Wkhi);
    cudaGetSymbolAddress((void**)&WkloP, d_Wklo);
    cudaGetSymbolAddress((void**)&WvhiP, d_Wvhi);
    cudaGetSymbolAddress((void**)&WvloP, d_Wvlo);
    cudaGetSymbolAddress((void**)&WohiP, d_Wohi);
    cudaGetSymbolAddress((void**)&WoloP, d_Wolo);

    const long long SH = (long long)SQ * HID;
    const int NELT = BSZ * SQ * HID;
    const int WELT = HID * HID;

    static bool attrs_set = false;
    if (!attrs_set) {
        cudaFuncSetAttribute(gemm_bf16_kernel, cudaFuncAttributeMaxDynamicSharedMemorySize, 75776);
        cudaFuncSetAttribute(flash_kernel,     cudaFuncAttributeMaxDynamicSharedMemorySize, FLASH_SMEM);
        attrs_set = true;
    }

    // 1) filter taps + circulant (bf16)
    filter_kernel<<<8, 256>>>(li, nl, cP, dcP, chiP, cloP);
    cmat_kernel<<<(SQ * SQ) / 256, 256>>>(ChiP, CloP, chiP, cloP);

    // 2) split inputs
    split_kernel<<<NELT / 256, 256>>>(X, XhiP, XloP, NELT);
    split_kernel<<<WELT / 256, 256>>>(Wq, WqhiP, WqloP, WELT);
    split_kernel<<<WELT / 256, 256>>>(Wk, WkhiP, WkloP, WELT);
    split_kernel<<<WELT / 256, 256>>>(Wv, WvhiP, WvloP, WELT);
    split_kernel<<<WELT / 256, 256>>>(Wo, WohiP, WoloP, WELT);

    // 3) Xf = C @ X  -> bf16 hi/lo directly
    gemm_bf16_kernel<<<dim3(HID / 128, SQ / 128, BSZ), 256, 75776>>>(
        ChiP, CloP, XhiP, XloP, nullptr, nullptr, nullptr, XfhiP, XfloP, SQ, HID, SQ, 0, SH, SH);

    // 4) projections -> bf16 hi/lo for flash; Vbuf fp32 for freq branch
    gemm_bf16_kernel<<<dim3(HID / 128, SQ / 128, BSZ), 256, 75776>>>(
        XfhiP, XfloP, WqhiP, WqloP, bq, dcP, nullptr, QfhiP, QfloP, SQ, HID, HID, SH, 0, SH);
    gemm_bf16_kernel<<<dim3(HID / 128, SQ / 128, BSZ), 256, 75776>>>(
        XfhiP, XfloP, WkhiP, WkloP, bk, dcP, nullptr, KfhiP, KfloP, SQ, HID, HID, SH, 0, SH);
    gemm_bf16_kernel<<<dim3(HID / 128, SQ / 128, BSZ), 256, 75776>>>(
        XfhiP, XfloP, WvhiP, WvloP, bv, dcP, nullptr, VfhiP, VfloP, SQ, HID, HID, SH, 0, SH);
    gemm_bf16_kernel<<<dim3(HID / 128, SQ / 128, BSZ), 256, 75776>>>(
        XhiP, XloP, WvhiP, WvloP, bv, nullptr, VbP, nullptr, nullptr, SQ, HID, HID, SH, 0, SH);

    // 5) flash attention (tensor cores) + diag-sum autocorrelation
    zero_kernel<<<(BSZ * NH * SQ) / 256, 256>>>(acP, BSZ * NH * SQ);
    flash_kernel<<<dim3(SQ / 128, NH, BSZ), 256, FLASH_SMEM>>>(
        QfhiP, QfloP, KfhiP, KfloP, VfhiP, VfloP, mask, CbP, acP);

    // 6) top-k + frequency gather
    topk_kernel<<<BSZ * NH, 256>>>(acP, tiP, twP);
    freq_kernel<<<dim3(SQ, BSZ), 256>>>(VbP, tiP, twP, CbP);

    // 7) output projection
    split_kernel<<<NELT / 256, 256>>>(CbP, CbhiP, CbloP, NELT);
    gemm_bf16_kernel<<<dim3(HID / 128, (BSZ * SQ) / 128, 1), 256, 75776>>>(
        CbhiP, CbloP, WohiP, WoloP, bo, nullptr, out, nullptr, nullptr, BSZ * SQ, HID, HID, 0, 0, 0);
}

// round 8
// speedup vs baseline: 2.0753x; 1.0223x over previous
#include <cuda_runtime.h>
#include <cuda_bf16.h>
#include <math.h>
#include <stdint.h>

#define SQ   2048
#define HID  1024
#define NH   16
#define HD   64
#define BSZ  2
#define MFREQ (SQ/2 + 1)
#define KTOP 15

// ---------------- scratch ----------------
__device__ float d_c[SQ];
__device__ float d_dcflag;
__device__ float d_Vbuf[BSZ * SQ * HID];
__device__ float d_Comb[BSZ * SQ * HID];
__device__ float d_ac  [BSZ * NH * SQ];
__device__ int   d_topi[BSZ * NH * KTOP];
__device__ float d_topw[BSZ * NH * KTOP];

__device__ __nv_bfloat16 d_chi[SQ], d_clo[SQ];
__device__ __nv_bfloat16 d_Chi [SQ * SQ],        d_Clo [SQ * SQ];
__device__ __nv_bfloat16 d_Xhi [BSZ * SQ * HID], d_Xlo [BSZ * SQ * HID];
__device__ __nv_bfloat16 d_Xfhi[BSZ * SQ * HID], d_Xflo[BSZ * SQ * HID];
__device__ __nv_bfloat16 d_Qfhi[BSZ * SQ * HID], d_Qflo[BSZ * SQ * HID];
__device__ __nv_bfloat16 d_Kfhi[BSZ * SQ * HID], d_Kflo[BSZ * SQ * HID];
__device__ __nv_bfloat16 d_Vfhi[BSZ * SQ * HID], d_Vflo[BSZ * SQ * HID];
__device__ __nv_bfloat16 d_Cbhi[BSZ * SQ * HID], d_Cblo[BSZ * SQ * HID];
__device__ __nv_bfloat16 d_Wqhi[HID * HID], d_Wqlo[HID * HID];
__device__ __nv_bfloat16 d_Wkhi[HID * HID], d_Wklo[HID * HID];
__device__ __nv_bfloat16 d_Wvhi[HID * HID], d_Wvlo[HID * HID];
__device__ __nv_bfloat16 d_Wohi[HID * HID], d_Wolo[HID * HID];

// ---------------- cp.async helpers ----------------
__device__ __forceinline__ void cp_async16(void* smem, const void* gmem) {
    unsigned s = (unsigned)__cvta_generic_to_shared(smem);
    asm volatile("cp.async.cg.shared.global [%0], [%1], 16;" :: "r"(s), "l"(gmem));
}
__device__ __forceinline__ void cp_commit() { asm volatile("cp.async.commit_group;"); }
__device__ __forceinline__ void cp_wait0()  { asm volatile("cp.async.wait_group 0;"); }
__device__ __forceinline__ void cp_wait1()  { asm volatile("cp.async.wait_group 1;"); }

// ---------------- mma / ldmatrix helpers ----------------
__device__ __forceinline__ void mma16816(float* d, const uint32_t* a, const uint32_t* b) {
    asm volatile(
        "mma.sync.aligned.m16n8k16.row.col.f32.bf16.bf16.f32 "
        "{%0,%1,%2,%3}, {%4,%5,%6,%7}, {%8,%9}, {%0,%1,%2,%3};"
        : "+f"(d[0]), "+f"(d[1]), "+f"(d[2]), "+f"(d[3])
        : "r"(a[0]), "r"(a[1]), "r"(a[2]), "r"(a[3]), "r"(b[0]), "r"(b[1]));
}
__device__ __forceinline__ void ldsm_x4(uint32_t* r, uint32_t addr) {
    asm volatile("ldmatrix.sync.aligned.m8n8.x4.shared.b16 {%0,%1,%2,%3}, [%4];"
        : "=r"(r[0]), "=r"(r[1]), "=r"(r[2]), "=r"(r[3]) : "r"(addr));
}
__device__ __forceinline__ void ldsm_x4t(uint32_t* r, uint32_t addr) {
    asm volatile("ldmatrix.sync.aligned.m8n8.x4.trans.shared.b16 {%0,%1,%2,%3}, [%4];"
        : "=r"(r[0]), "=r"(r[1]), "=r"(r[2]), "=r"(r[3]) : "r"(addr));
}
__device__ __forceinline__ void ldsm_x2t(uint32_t* r, uint32_t addr) {
    asm volatile("ldmatrix.sync.aligned.m8n8.x2.trans.shared.b16 {%0,%1}, [%2];"
        : "=r"(r[0]), "=r"(r[1]) : "r"(addr));
}
__device__ __forceinline__ uint32_t pack_bf2(float a, float b) {
    __nv_bfloat162 t = __floats2bfloat162_rn(a, b);
    return *(uint32_t*)&t;
}

// ---------------- filter taps ----------------
__global__ void filter_kernel(const int* __restrict__ li_p, const int* __restrict__ nl_p,
                              float* __restrict__ c, float* __restrict__ dcflag,
                              __nv_bfloat16* __restrict__ chi, __nv_bfloat16* __restrict__ clo)
{
    int n = blockIdx.x * blockDim.x + threadIdx.x;
    if (n >= SQ) return;
    int li = *li_p;
    int nl = *nl_p;
    const double ALPHA = 0.5;
    int M = MFREQ;
    int p, q;
    if (ALPHA <= 1.0 / (double)nl) {
        p = (int)(M * (1.0 - (double)(li + 1) / (double)nl));
        q = (int)((double)p + (double)M / (double)nl);
    } else {
        p = (nl > 1) ? (int)(M * (1.0 - ALPHA) * (1.0 - (double)li / (double)(nl - 1))) : 0;
        q = (int)((double)p + ALPHA * (double)M);
    }
    p = max(0, min(p, M - 1));
    q = max(p + 1, min(q, M));

    double acc = 0.0;
    const double w2 = 2.0 / (double)SQ;
    const double w1 = 1.0 / (double)SQ;
    const double tpn = 6.283185307179586476925286766559 * (double)n / (double)SQ;
    for (int f = p; f < q; f++) {
        double wf = (f == 0 || f == M - 1) ? w1 : w2;
        acc += wf * cos(tpn * (double)f);
    }
    float cf = (float)acc;
    c[n] = cf;
    __nv_bfloat16 h = __float2bfloat16_rn(cf);
    chi[n] = h;
    clo[n] = __float2bfloat16_rn(cf - __bfloat162float(h));
    if (n == 0) *dcflag = (p == 0) ? 1.0f : 0.0f;
}

__global__ void cmat_kernel(__nv_bfloat16* __restrict__ Chi, __nv_bfloat16* __restrict__ Clo,
                            const __nv_bfloat16* __restrict__ chi, const __nv_bfloat16* __restrict__ clo)
{
    int idx = blockIdx.x * blockDim.x + threadIdx.x;
    int t = idx >> 11;
    int s = idx & (SQ - 1);
    int tau = (t - s) & (SQ - 1);
    Chi[idx] = chi[tau];
    Clo[idx] = clo[tau];
}

__global__ void split_kernel(const float* __restrict__ in,
                             __nv_bfloat16* __restrict__ hi, __nv_bfloat16* __restrict__ lo, int n)
{
    int i = blockIdx.x * blockDim.x + threadIdx.x;
    if (i >= n) return;
    float f = in[i];
    __nv_bfloat16 h = __float2bfloat16_rn(f);
    hi[i] = h;
    lo[i] = __float2bfloat16_rn(f - __bfloat162float(h));
}

__global__ void zero_kernel(float* __restrict__ p, int n)
{
    int i = blockIdx.x * blockDim.x + threadIdx.x;
    if (i < n) p[i] = 0.f;
}

// ---------------- bf16-split tensor-core GEMM ----------------
#define GA_STR 40
#define GB_STR 136
#define A_BUF_ELEMS (128 * GA_STR)
#define B_BUF_ELEMS (32 * GB_STR)
__global__ __launch_bounds__(256) void gemm_bf16_kernel(
    const __nv_bfloat16* __restrict__ Ahi, const __nv_bfloat16* __restrict__ Alo,
    const __nv_bfloat16* __restrict__ Bhi, const __nv_bfloat16* __restrict__ Blo,
    const float* __restrict__ bias, const float* __restrict__ bscalep,
    float* __restrict__ C,
    __nv_bfloat16* __restrict__ Ohi, __nv_bfloat16* __restrict__ Olo,
    int M, int N, int K,
    long long sA, long long sB, long long sC)
{
    extern __shared__ __nv_bfloat16 sm[];
    __nv_bfloat16* AsHi = sm;
    __nv_bfloat16* AsLo = sm + 2 * A_BUF_ELEMS;
    __nv_bfloat16* BsHi = sm + 4 * A_BUF_ELEMS;
    __nv_bfloat16* BsLo = sm + 4 * A_BUF_ELEMS + 2 * B_BUF_ELEMS;
    uint32_t sbase = (uint32_t)__cvta_generic_to_shared(sm);

    int z = blockIdx.z;
    Ahi += (size_t)z * sA;  Alo += (size_t)z * sA;
    Bhi += (size_t)z * sB;  Blo += (size_t)z * sB;
    if (C)   C   += (size_t)z * sC;
    if (Ohi) { Ohi += (size_t)z * sC; Olo += (size_t)z * sC; }

    int tid = threadIdx.x;
    int lane = tid & 31;
    int wid = tid >> 5;
    int mBase = (wid >> 2) * 64;
    int nBase = (wid & 3) * 32;
    int row0 = blockIdx.y * 128;
    int col0 = blockIdx.x * 128;

    float acc[4][4][4];
#pragma unroll
    for (int mf = 0; mf < 4; mf++)
#pragma unroll
        for (int nf = 0; nf < 4; nf++)
#pragma unroll
            for (int r = 0; r < 4; r++) acc[mf][nf][r] = 0.f;

    int ar = tid >> 1;
    int br = tid >> 3;
    const __nv_bfloat16* Ah0 = Ahi + (size_t)(row0 + ar) * K;
    const __nv_bfloat16* Al0 = Alo + (size_t)(row0 + ar) * K;

#define LOAD_TILES(buf, k0)                                                             \
    do {                                                                                \
        _Pragma("unroll")                                                               \
        for (int j = 0; j < 2; j++) {                                                   \
            int s = (tid & 1) * 2 + j;                                                  \
            cp_async16(&AsHi[(buf) * A_BUF_ELEMS + ar * GA_STR + s * 8],                \
                       Ah0 + (k0) + s * 8);                                             \
            cp_async16(&AsLo[(buf) * A_BUF_ELEMS + ar * GA_STR + s * 8],                \
                       Al0 + (k0) + s * 8);                                             \
            int sb = (tid & 7) * 2 + j;                                                 \
            cp_async16(&BsHi[(buf) * B_BUF_ELEMS + br * GB_STR + sb * 8],               \
                       Bhi + (size_t)((k0) + br) * N + col0 + sb * 8);                  \
            cp_async16(&BsLo[(buf) * B_BUF_ELEMS + br * GB_STR + sb * 8],               \
                       Blo + (size_t)((k0) + br) * N + col0 + sb * 8);                  \
        }                                                                               \
    } while (0)

    LOAD_TILES(0, 0);
    cp_commit();
    cp_wait0();
    __syncthreads();

    int nIter = K >> 5;
    int lr = lane & 15;
    int khalf = (lane >> 4) << 3;

    for (int it = 0; it < nIter; it++) {
        int buf = it & 1;
        if (it + 1 < nIter) {
            LOAD_TILES(buf ^ 1, (it + 1) << 5);
            cp_commit();
        }

        uint32_t aHiB = sbase + 2 * (buf * A_BUF_ELEMS);
        uint32_t aLoB = sbase + 2 * (2 * A_BUF_ELEMS + buf * A_BUF_ELEMS);
        uint32_t bHiB = sbase + 2 * (4 * A_BUF_ELEMS + buf * B_BUF_ELEMS);
        uint32_t bLoB = sbase + 2 * (4 * A_BUF_ELEMS + 2 * B_BUF_ELEMS + buf * B_BUF_ELEMS);

#pragma unroll
        for (int ks = 0; ks < 32; ks += 16) {
            uint32_t ahi[4][4], alo[4][4], bhi[4][2], blo[4][2];
#pragma unroll
            for (int mf = 0; mf < 4; mf++) {
                uint32_t off = 2 * ((mBase + mf * 16 + lr) * GA_STR + ks + khalf);
                ldsm_x4(ahi[mf], aHiB + off);
                ldsm_x4(alo[mf], aLoB + off);
            }
#pragma unroll
            for (int nf = 0; nf < 4; nf++) {
                uint32_t off = 2 * ((ks + lr) * GB_STR + nBase + nf * 8);
                ldsm_x2t(bhi[nf], bHiB + off);
                ldsm_x2t(blo[nf], bLoB + off);
            }
#pragma unroll
            for (int mf = 0; mf < 4; mf++)
#pragma unroll
                for (int nf = 0; nf < 4; nf++) {
                    mma16816(acc[mf][nf], ahi[mf], bhi[nf]);
                    mma16816(acc[mf][nf], ahi[mf], blo[nf]);
                    mma16816(acc[mf][nf], alo[mf], bhi[nf]);
                }
        }

        if (it + 1 < nIter) cp_wait0();
        __syncthreads();
    }

    float bscale = 0.f;
    if (bias) bscale = bscalep ? *bscalep : 1.f;

#pragma unroll
    for (int mf = 0; mf < 4; mf++) {
        int r0 = row0 + mBase + mf * 16 + (lane >> 2);
#pragma unroll
        for (int nf = 0; nf < 4; nf++) {
            int c0 = col0 + nBase + nf * 8 + (lane & 3) * 2;
            float b0 = 0.f, b1 = 0.f;
            if (bias) { b0 = bias[c0] * bscale; b1 = bias[c0 + 1] * bscale; }
            float v0 = acc[mf][nf][0] + b0, v1 = acc[mf][nf][1] + b1;
            float v2 = acc[mf][nf][2] + b0, v3 = acc[mf][nf][3] + b1;
            if (C) {
                float2 w0 = {v0, v1}, w1 = {v2, v3};
                *(float2*)&C[(size_t)r0 * N + c0]       = w0;
                *(float2*)&C[(size_t)(r0 + 8) * N + c0] = w1;
            }
            if (Ohi) {
                __nv_bfloat16 h0 = __float2bfloat16_rn(v0), h1 = __float2bfloat16_rn(v1);
                __nv_bfloat16 h2 = __float2bfloat16_rn(v2), h3 = __float2bfloat16_rn(v3);
                __nv_bfloat162 hv0 = {h0, h1}, hv1 = {h2, h3};
                __nv_bfloat162 lv0 = {__float2bfloat16_rn(v0 - __bfloat162float(h0)),
                                      __float2bfloat16_rn(v1 - __bfloat162float(h1))};
                __nv_bfloat162 lv1 = {__float2bfloat16_rn(v2 - __bfloat162float(h2)),
                                      __float2bfloat16_rn(v3 - __bfloat162float(h3))};
                *(__nv_bfloat162*)&Ohi[(size_t)r0 * N + c0]       = hv0;
                *(__nv_bfloat162*)&Olo[(size_t)r0 * N + c0]       = lv0;
                *(__nv_bfloat162*)&Ohi[(size_t)(r0 + 8) * N + c0] = hv1;
                *(__nv_bfloat162*)&Olo[(size_t)(r0 + 8) * N + c0] = lv1;
            }
        }
    }
}

// ---------------- tensor-core flash attention (2 blocks/SM) ----------------
// BM=128, BN=64, 8 warps, 80 KB smem -> occupancy 2. Single KV buffer: the
// co-resident block hides the load latency. Q lives in registers; its smem
// region is reused as the raw-score tile for the atomic-free diag reduction.
#define FSTR 72
#define Q_ELEMS (128 * FSTR)          // 9216 elems (hi); lo at +Q_ELEMS
#define KV_BASE (2 * Q_ELEMS)         // 18432 elems = 36864 B
#define KV_ONE  (64 * FSTR)           // 4608 elems
#define SCS 66
#define ACB_OFF (2 * (KV_BASE + 4 * KV_ONE))   // 73728 bytes
#define FLASH_SMEM (ACB_OFF + SQ * 4)          // 81920 bytes
__global__ __launch_bounds__(256, 2) void flash_kernel(
    const __nv_bfloat16* __restrict__ Qhi_, const __nv_bfloat16* __restrict__ Qlo_,
    const __nv_bfloat16* __restrict__ Khi_, const __nv_bfloat16* __restrict__ Klo_,
    const __nv_bfloat16* __restrict__ Vhi_, const __nv_bfloat16* __restrict__ Vlo_,
    const float* __restrict__ mask, float* __restrict__ Comb, float* __restrict__ ac)
{
    extern __shared__ __nv_bfloat16 smb[];
    float* Stile = (float*)smb;                      // aliases Q region after prologue
    float* acb   = (float*)((char*)smb + ACB_OFF);
    uint32_t sbase = (uint32_t)__cvta_generic_to_shared(smb);

    int tid = threadIdx.x;
    int lane = tid & 31, wid = tid >> 5;
    int qb = blockIdx.x, h = blockIdx.y, b = blockIdx.z;
    int t0 = qb * 128;
    int wr = wid * 16;

    size_t hoff = (size_t)b * SQ * HID + h * HD;
    const __nv_bfloat16* Qh = Qhi_ + hoff;
    const __nv_bfloat16* Ql = Qlo_ + hoff;
    const __nv_bfloat16* Kh = Khi_ + hoff;
    const __nv_bfloat16* Kl = Klo_ + hoff;
    const __nv_bfloat16* Vh = Vhi_ + hoff;
    const __nv_bfloat16* Vl = Vlo_ + hoff;
    const float* Mbase = mask + (size_t)b * SQ * SQ;
    float* acrow = ac + (size_t)(b * NH + h) * SQ;

#define LOAD_KV(kti)                                                                    \
    do {                                                                                \
        int s0_ = (kti) * 64;                                                           \
        _Pragma("unroll")                                                               \
        for (int kk = 0; kk < 2; kk++) {                                                \
            int id_ = tid + kk * 256;                                                   \
            int r_ = id_ >> 3, c8_ = (id_ & 7) * 8;                                     \
            size_t src_ = (size_t)(s0_ + r_) * HID + c8_;                               \
            unsigned dst_ = KV_BASE + r_ * FSTR + c8_;                                  \
            cp_async16(&smb[dst_],              Kh + src_);                             \
            cp_async16(&smb[dst_ + KV_ONE],     Kl + src_);                             \
            cp_async16(&smb[dst_ + 2 * KV_ONE], Vh + src_);                             \
            cp_async16(&smb[dst_ + 3 * KV_ONE], Vl + src_);                             \
        }                                                                               \
    } while (0)

    // prologue: Q tile + KV0 in flight
#pragma unroll
    for (int k = 0; k < 4; k++) {
        int id = tid + k * 256;
        int r = id >> 3, c8 = (id & 7) * 8;
        size_t src = (size_t)(t0 + r) * HID + c8;
        cp_async16(&smb[r * FSTR + c8],           Qh + src);
        cp_async16(&smb[Q_ELEMS + r * FSTR + c8], Ql + src);
    }
    cp_commit();
    LOAD_KV(0);
    cp_commit();
    for (int i = tid; i < SQ; i += 256) acb[i] = 0.f;
    cp_wait1();          // Q arrived
    __syncthreads();

    // Q fragments (resident); Q smem region is dead after this point
    uint32_t qhi[4][4], qlo[4][4];
    int lr = lane & 15, kh8 = (lane >> 4) * 8;
#pragma unroll
    for (int ks = 0; ks < 4; ks++) {
        uint32_t off = sbase + 2 * ((wr + lr) * FSTR + ks * 16 + kh8);
        ldsm_x4(qhi[ks], off);
        ldsm_x4(qlo[ks], off + 2 * Q_ELEMS);
    }

    float m0 = -INFINITY, m1 = -INFINITY, l0 = 0.f, l1 = 0.f;
    float o[8][4];
#pragma unroll
    for (int df = 0; df < 8; df++)
#pragma unroll
        for (int r = 0; r < 4; r++) o[df][r] = 0.f;

    int r4 = lane >> 2, c2 = (lane & 3) * 2;
    int qrow = t0 + wr + r4;
    // K x4 lane mapping: groups 0/1 -> nf (d 0-7 / 8-15), groups 2/3 -> nf+1
    int krL = ((lane >> 4) << 3) | (lane & 7);
    int kdL = ((lane >> 3) & 1) << 3;
    // V x4t lane mapping: lanes 0-15 -> df columns, 16-31 -> df+1 columns
    int vRow = lane & 15;
    int vSel = lane >> 4;

    // diag-phase constants (one thread per tau)
    int du = tid - 63;
    int drlo = du > 0 ? du : 0;
    int drhi = (du + 64 < 128) ? du + 64 : 128;
    const float* dbase = Stile - du;

    for (int kt = 0; kt < 32; kt++) {
        int s0 = kt * 64;
        if (kt > 0) {
            __syncthreads();             // prev diag (Stile) + prev PV (KV) reads done
            LOAD_KV(kt);
            cp_commit();
        }
        cp_wait0();
        __syncthreads();                 // KV visible to all

        uint32_t kvbK = sbase + 2 * KV_BASE;
        uint32_t kvbV = sbase + 2 * (KV_BASE + 2 * KV_ONE);

        // scores: S = Qhi*Khi + Qhi*Klo + Qlo*Khi  (raw, fp32 acc)
        float s[8][4];
#pragma unroll
        for (int nf = 0; nf < 8; nf++)
#pragma unroll
            for (int r = 0; r < 4; r++) s[nf][r] = 0.f;
#pragma unroll
        for (int ks = 0; ks < 4; ks++) {
#pragma unroll
            for (int nf2 = 0; nf2 < 8; nf2 += 2) {
                uint32_t ko = kvbK + 2 * ((nf2 * 8 + krL) * FSTR + ks * 16 + kdL);
                uint32_t bh[4], bl[4];
                ldsm_x4(bh, ko);
                ldsm_x4(bl, ko + 2 * KV_ONE);
                mma16816(s[nf2],     qhi[ks], &bh[0]);
                mma16816(s[nf2],     qhi[ks], &bl[0]);
                mma16816(s[nf2],     qlo[ks], &bh[0]);
                mma16816(s[nf2 + 1], qhi[ks], &bh[2]);
                mma16816(s[nf2 + 1], qhi[ks], &bl[2]);
                mma16816(s[nf2 + 1], qlo[ks], &bh[2]);
            }
        }

        // stage RAW scores for diag phase
        {
            float* Sw0 = Stile + (wr + r4) * SCS + c2;
            float* Sw1 = Sw0 + 8 * SCS;
#pragma unroll
            for (int nf = 0; nf < 8; nf++) {
                float2 w0 = { s[nf][0], s[nf][1] };
                float2 w1 = { s[nf][2], s[nf][3] };
                *(float2*)(Sw0 + nf * 8) = w0;
                *(float2*)(Sw1 + nf * 8) = w1;
            }
        }

        // scale + mask + row max
        const float* mrow0 = Mbase + (size_t)qrow * SQ + s0 + c2;
        const float* mrow1 = mrow0 + 8 * SQ;
        float mx0 = -INFINITY, mx1 = -INFINITY;
#pragma unroll
        for (int nf = 0; nf < 8; nf++) {
            float2 ma = *(const float2*)(mrow0 + nf * 8);
            float2 mb = *(const float2*)(mrow1 + nf * 8);
            s[nf][0] = s[nf][0] * 0.125f + ma.x;
            s[nf][1] = s[nf][1] * 0.125f + ma.y;
            s[nf][2] = s[nf][2] * 0.125f + mb.x;
            s[nf][3] = s[nf][3] * 0.125f + mb.y;
            mx0 = fmaxf(mx0, fmaxf(s[nf][0], s[nf][1]));
            mx1 = fmaxf(mx1, fmaxf(s[nf][2], s[nf][3]));
        }
        mx0 = fmaxf(mx0, __shfl_xor_sync(0xffffffffu, mx0, 1));
        mx0 = fmaxf(mx0, __shfl_xor_sync(0xffffffffu, mx0, 2));
        mx1 = fmaxf(mx1, __shfl_xor_sync(0xffffffffu, mx1, 1));
        mx1 = fmaxf(mx1, __shfl_xor_sync(0xffffffffu, mx1, 2));
        float nm0 = fmaxf(m0, mx0), nm1 = fmaxf(m1, mx1);
        float cor0 = __expf(m0 - nm0), cor1 = __expf(m1 - nm1);
        m0 = nm0; m1 = nm1;

        // exp -> bf16 P (a-frag packing), row sums from bf16 values
        uint32_t pa[4][4];
        float rs0 = 0.f, rs1 = 0.f;
#pragma unroll
        for (int kc = 0; kc < 4; kc++) {
            int n0 = 2 * kc, n1 = 2 * kc + 1;
            pa[kc][0] = pack_bf2(__expf(s[n0][0] - nm0), __expf(s[n0][1] - nm0));
            pa[kc][1] = pack_bf2(__expf(s[n0][2] - nm1), __expf(s[n0][3] - nm1));
            pa[kc][2] = pack_bf2(__expf(s[n1][0] - nm0), __expf(s[n1][1] - nm0));
            pa[kc][3] = pack_bf2(__expf(s[n1][2] - nm1), __expf(s[n1][3] - nm1));
            float2 u;
            u = __bfloat1622float2(*(__nv_bfloat162*)&pa[kc][0]); rs0 += u.x + u.y;
            u = __bfloat1622float2(*(__nv_bfloat162*)&pa[kc][2]); rs0 += u.x + u.y;
            u = __bfloat1622float2(*(__nv_bfloat162*)&pa[kc][1]); rs1 += u.x + u.y;
            u = __bfloat1622float2(*(__nv_bfloat162*)&pa[kc][3]); rs1 += u.x + u.y;
        }
        rs0 += __shfl_xor_sync(0xffffffffu, rs0, 1);
        rs0 += __shfl_xor_sync(0xffffffffu, rs0, 2);
        rs1 += __shfl_xor_sync(0xffffffffu, rs1, 1);
        rs1 += __shfl_xor_sync(0xffffffffu, rs1, 2);
        l0 = l0 * cor0 + rs0;
        l1 = l1 * cor1 + rs1;
#pragma unroll
        for (int df = 0; df < 8; df++) {
            o[df][0] *= cor0; o[df][1] *= cor0;
            o[df][2] *= cor1; o[df][3] *= cor1;
        }

        // O += P @ (Vhi + Vlo), x4t serving df pairs
#pragma unroll
        for (int kc = 0; kc < 4; kc++) {
#pragma unroll
            for (int df2 = 0; df2 < 8; df2 += 2) {
                uint32_t vo = kvbV + 2 * ((kc * 16 + vRow) * FSTR + (df2 + vSel) * 8);
                uint32_t vh[4], vl[4];
                ldsm_x4t(vh, vo);
                ldsm_x4t(vl, vo + 2 * KV_ONE);
                mma16816(o[df2],     pa[kc], &vh[0]);
                mma16816(o[df2],     pa[kc], &vl[0]);
                mma16816(o[df2 + 1], pa[kc], &vh[2]);
                mma16816(o[df2 + 1], pa[kc], &vl[2]);
            }
        }
        __syncthreads();                 // Stile complete; PV reads of KV done

        // diagonal reduction: one thread per tau, NO atomics
        if (tid < 191) {
            float sa = 0.f, sb = 0.f;
            int r = drlo;
            for (; r + 1 < drhi; r += 2) {
                sa += dbase[r * (SCS + 1)];
                sb += dbase[r * (SCS + 1) + (SCS + 1)];
            }
            if (r < drhi) sa += dbase[r * (SCS + 1)];
            int tau = (t0 - s0 + du) & (SQ - 1);
            acb[tau] += (sa + sb) * (1.f / 64.f);
        }
    }

    // flush tau bins
    __syncthreads();
    for (int i = tid; i < SQ; i += 256)
        atomicAdd(&acrow[i], acb[i]);

    // epilogue: Comb = 0.5 * ctx
    float inv0 = 0.5f / l0, inv1 = 0.5f / l1;
    float* C0 = Comb + (size_t)b * SQ * HID + (size_t)qrow * HID + h * HD + c2;
#pragma unroll
    for (int df = 0; df < 8; df++) {
        float2 va = { o[df][0] * inv0, o[df][1] * inv0 };
        float2 vb = { o[df][2] * inv1, o[df][3] * inv1 };
        *(float2*)(C0 + df * 8)            = va;
        *(float2*)(C0 + 8 * HID + df * 8)  = vb;
    }
}

// ---------------- top-k (k=15) + softmax weights ----------------
__global__ __launch_bounds__(256) void topk_kernel(
    const float* __restrict__ ac, int* __restrict__ topi, float* __restrict__ topw)
{
    int bh = blockIdx.x;
    __shared__ float svv[SQ];
    __shared__ float rv[256];
    __shared__ int ri[256];
    __shared__ float tvals[KTOP];
    __shared__ int tidxs[KTOP];
    int tid = threadIdx.x;

    for (int i = tid; i < SQ; i += 256)
        svv[i] = ac[(size_t)bh * SQ + i];
    __syncthreads();

    for (int t = 0; t < KTOP; t++) {
        float bv = -INFINITY;
        int bi = 0;
        for (int i = tid; i < SQ; i += 256) {
            float v = svv[i];
            if (v > bv || (v == bv && i < bi)) { bv = v; bi = i; }
        }
        rv[tid] = bv; ri[tid] = bi;
        __syncthreads();
        for (int st = 128; st > 0; st >>= 1) {
            if (tid < st) {
                float v2 = rv[tid + st]; int i2 = ri[tid + st];
                if (v2 > rv[tid] || (v2 == rv[tid] && i2 < ri[tid])) { rv[tid] = v2; ri[tid] = i2; }
            }
            __syncthreads();
        }
        if (tid == 0) {
            tvals[t] = rv[0]; tidxs[t] = ri[0];
            svv[ri[0]] = -INFINITY;
        }
        __syncthreads();
    }

    if (tid == 0) {
        float mx = tvals[0];
        float e[KTOP], ssum = 0.f;
#pragma unroll
        for (int t = 0; t < KTOP; t++) { e[t] = __expf(tvals[t] - mx); ssum += e[t]; }
        float inv = 1.f / ssum;
#pragma unroll
        for (int t = 0; t < KTOP; t++) {
            topw[bh * KTOP + t] = e[t] * inv;
            topi[bh * KTOP + t] = tidxs[t];
        }
    }
}

// ---------------- frequency branch gather ----------------
__global__ __launch_bounds__(256) void freq_kernel(
    const float* __restrict__ V, const int* __restrict__ topi,
    const float* __restrict__ topw, float* __restrict__ Comb)
{
    int t = blockIdx.x, b = blockIdx.y;
    __shared__ int si[NH * KTOP];
    __shared__ float sw[NH * KTOP];
    int tid = threadIdx.x;
    if (tid < NH * KTOP) {
        si[tid] = topi[b * NH * KTOP + tid];
        sw[tid] = topw[b * NH * KTOP + tid];
    }
    __syncthreads();

    int c = tid * 4;
    int h = c >> 6;
    float* crow = Comb + ((size_t)b * SQ + t) * HID + c;
    float4 acc = *(float4*)crow;
    const float* Vb = V + (size_t)b * SQ * HID;
#pragma unroll
    for (int j = 0; j < KTOP; j++) {
        int row = (t + si[h * KTOP + j]) & (SQ - 1);
        float w = 0.5f * sw[h * KTOP + j];
        float4 v = *(const float4*)&Vb[(size_t)row * HID + c];
        acc.x += w * v.x; acc.y += w * v.y; acc.z += w * v.z; acc.w += w * v.w;
    }
    *(float4*)crow = acc;
}

// ---------------- launcher ----------------
extern "C" void kernel_launch(void* const* d_in, const int* in_sizes, int n_in,
                              void* d_out, int out_size)
{
    const float* X    = (const float*)d_in[0];
    const float* mask = (const float*)d_in[1];
    const float* Wq   = (const float*)d_in[2];
    const float* bq   = (const float*)d_in[3];
    const float* Wk   = (const float*)d_in[4];
    const float* bk   = (const float*)d_in[5];
    const float* Wv   = (const float*)d_in[6];
    const float* bv   = (const float*)d_in[7];
    const float* Wo   = (const float*)d_in[8];
    const float* bo   = (const float*)d_in[9];
    const int*   li   = (const int*)d_in[10];
    const int*   nl   = (const int*)d_in[11];
    float* out = (float*)d_out;

    float *cP, *dcP, *VbP, *CbP, *acP, *twP;
    int* tiP;
    __nv_bfloat16 *chiP, *cloP, *ChiP, *CloP, *XhiP, *XloP, *XfhiP, *XfloP, *CbhiP, *CbloP;
    __nv_bfloat16 *QfhiP, *QfloP, *KfhiP, *KfloP, *VfhiP, *VfloP;
    __nv_bfloat16 *WqhiP, *WqloP, *WkhiP, *WkloP, *WvhiP, *WvloP, *WohiP, *WoloP;
    cudaGetSymbolAddress((void**)&cP,  d_c);
    cudaGetSymbolAddress((void**)&dcP, d_dcflag);
    cudaGetSymbolAddress((void**)&VbP, d_Vbuf);
    cudaGetSymbolAddress((void**)&CbP, d_Comb);
    cudaGetSymbolAddress((void**)&acP, d_ac);
    cudaGetSymbolAddress((void**)&tiP, d_topi);
    cudaGetSymbolAddress((void**)&twP, d_topw);
    cudaGetSymbolAddress((void**)&chiP, d_chi);
    cudaGetSymbolAddress((void**)&cloP, d_clo);
    cudaGetSymbolAddress((void**)&ChiP, d_Chi);
    cudaGetSymbolAddress((void**)&CloP, d_Clo);
    cudaGetSymbolAddress((void**)&XhiP, d_Xhi);
    cudaGetSymbolAddress((void**)&XloP, d_Xlo);
    cudaGetSymbolAddress((void**)&XfhiP, d_Xfhi);
    cudaGetSymbolAddress((void**)&XfloP, d_Xflo);
    cudaGetSymbolAddress((void**)&QfhiP, d_Qfhi);
    cudaGetSymbolAddress((void**)&QfloP, d_Qflo);
    cudaGetSymbolAddress((void**)&KfhiP, d_Kfhi);
    cudaGetSymbolAddress((void**)&KfloP, d_Kflo);
    cudaGetSymbolAddress((void**)&VfhiP, d_Vfhi);
    cudaGetSymbolAddress((void**)&VfloP, d_Vflo);
    cudaGetSymbolAddress((void**)&CbhiP, d_Cbhi);
    cudaGetSymbolAddress((void**)&CbloP, d_Cblo);
    cudaGetSymbolAddress((void**)&WqhiP, d_Wqhi);
    cudaGetSymbolAddress((void**)&WqloP, d_Wqlo);
    cudaGetSymbolAddress((void**)&WkhiP, d_Wkhi);
    cudaGetSymbolAddress((void**)&WkloP, d_Wklo);
    cudaGetSymbolAddress((void**)&WvhiP, d_Wvhi);
    cudaGetSymbolAddress((void**)&WvloP, d_Wvlo);
    cudaGetSymbolAddress((void**)&WohiP, d_Wohi);
    cudaGetSymbolAddress((void**)&WoloP, d_Wolo);

    const long long SH = (long long)SQ * HID;
    const int NELT = BSZ * SQ * HID;
    const int WELT = HID * HID;

    static bool attrs_set = false;
    if (!attrs_set) {
        cudaFuncSetAttribute(gemm_bf16_kernel, cudaFuncAttributeMaxDynamicSharedMemorySize, 75776);
        cudaFuncSetAttribute(flash_kernel,     cudaFuncAttributeMaxDynamicSharedMemorySize, FLASH_SMEM);
        attrs_set = true;
    }

    // 1) filter taps + circulant (bf16)
    filter_kernel<<<8, 256>>>(li, nl, cP, dcP, chiP, cloP);
    cmat_kernel<<<(SQ * SQ) / 256, 256>>>(ChiP, CloP, chiP, cloP);

    // 2) split inputs
    split_kernel<<<NELT / 256, 256>>>(X, XhiP, XloP, NELT);
    split_kernel<<<WELT / 256, 256>>>(Wq, WqhiP, WqloP, WELT);
    split_kernel<<<WELT / 256, 256>>>(Wk, WkhiP, WkloP, WELT);
    split_kernel<<<WELT / 256, 256>>>(Wv, WvhiP, WvloP, WELT);
    split_kernel<<<WELT / 256, 256>>>(Wo, WohiP, WoloP, WELT);

    // 3) Xf = C @ X  -> bf16 hi/lo directly
    gemm_bf16_kernel<<<dim3(HID / 128, SQ / 128, BSZ), 256, 75776>>>(
        ChiP, CloP, XhiP, XloP, nullptr, nullptr, nullptr, XfhiP, XfloP, SQ, HID, SQ, 0, SH, SH);

    // 4) projections -> bf16 hi/lo for flash; Vbuf fp32 for freq branch
    gemm_bf16_kernel<<<dim3(HID / 128, SQ / 128, BSZ), 256, 75776>>>(
        XfhiP, XfloP, WqhiP, WqloP, bq, dcP, nullptr, QfhiP, QfloP, SQ, HID, HID, SH, 0, SH);
    gemm_bf16_kernel<<<dim3(HID / 128, SQ / 128, BSZ), 256, 75776>>>(
        XfhiP, XfloP, WkhiP, WkloP, bk, dcP, nullptr, KfhiP, KfloP, SQ, HID, HID, SH, 0, SH);
    gemm_bf16_kernel<<<dim3(HID / 128, SQ / 128, BSZ), 256, 75776>>>(
        XfhiP, XfloP, WvhiP, WvloP, bv, dcP, nullptr, VfhiP, VfloP, SQ, HID, HID, SH, 0, SH);
    gemm_bf16_kernel<<<dim3(HID / 128, SQ / 128, BSZ), 256, 75776>>>(
        XhiP, XloP, WvhiP, WvloP, bv, nullptr, VbP, nullptr, nullptr, SQ, HID, HID, SH, 0, SH);

    // 5) flash attention (2 blocks/SM) + diag-sum autocorrelation
    zero_kernel<<<(BSZ * NH * SQ) / 256, 256>>>(acP, BSZ * NH * SQ);
    flash_kernel<<<dim3(SQ / 128, NH, BSZ), 256, FLASH_SMEM>>>(
        QfhiP, QfloP, KfhiP, KfloP, VfhiP, VfloP, mask, CbP, acP);

    // 6) top-k + frequency gather
    topk_kernel<<<BSZ * NH, 256>>>(acP, tiP, twP);
    freq_kernel<<<dim3(SQ, BSZ), 256>>>(VbP, tiP, twP, CbP);

    // 7) output projection
    split_kernel<<<NELT / 256, 256>>>(CbP, CbhiP, CbloP, NELT);
    gemm_bf16_kernel<<<dim3(HID / 128, (BSZ * SQ) / 128, 1), 256, 75776>>>(
        CbhiP, CbloP, WohiP, WoloP, bo, nullptr, out, nullptr, nullptr, BSZ * SQ, HID, HID, 0, 0, 0);
}

// round 9
// speedup vs baseline: 2.1346x; 1.0286x over previous
#include <cuda_runtime.h>
#include <cuda_bf16.h>
#include <math.h>
#include <stdint.h>

#define SQ   2048
#define HID  1024
#define NH   16
#define HD   64
#define BSZ  2
#define MFREQ (SQ/2 + 1)
#define KTOP 15

// ---------------- scratch ----------------
__device__ float d_c[SQ];
__device__ float d_dcflag;
__device__ float d_Vbuf[BSZ * SQ * HID];
__device__ float d_Comb[BSZ * SQ * HID];
__device__ float d_ac  [BSZ * NH * SQ];
__device__ int   d_topi[BSZ * NH * KTOP];
__device__ float d_topw[BSZ * NH * KTOP];

__device__ __nv_bfloat16 d_chi[SQ], d_clo[SQ];
__device__ __nv_bfloat16 d_Chi [SQ * SQ],        d_Clo [SQ * SQ];
__device__ __nv_bfloat16 d_Xhi [BSZ * SQ * HID], d_Xlo [BSZ * SQ * HID];
__device__ __nv_bfloat16 d_Xfhi[BSZ * SQ * HID], d_Xflo[BSZ * SQ * HID];
__device__ __nv_bfloat16 d_Qfhi[BSZ * SQ * HID], d_Qflo[BSZ * SQ * HID];
__device__ __nv_bfloat16 d_Kfhi[BSZ * SQ * HID], d_Kflo[BSZ * SQ * HID];
__device__ __nv_bfloat16 d_Vfhi[BSZ * SQ * HID], d_Vflo[BSZ * SQ * HID];
__device__ __nv_bfloat16 d_Cbhi[BSZ * SQ * HID], d_Cblo[BSZ * SQ * HID];
__device__ __nv_bfloat16 d_Wqhi[HID * HID], d_Wqlo[HID * HID];
__device__ __nv_bfloat16 d_Wkhi[HID * HID], d_Wklo[HID * HID];
__device__ __nv_bfloat16 d_Wvhi[HID * HID], d_Wvlo[HID * HID];
__device__ __nv_bfloat16 d_Wohi[HID * HID], d_Wolo[HID * HID];

// ---------------- cp.async helpers ----------------
__device__ __forceinline__ void cp_async16(void* smem, const void* gmem) {
    unsigned s = (unsigned)__cvta_generic_to_shared(smem);
    asm volatile("cp.async.cg.shared.global [%0], [%1], 16;" :: "r"(s), "l"(gmem));
}
__device__ __forceinline__ void cp_commit() { asm volatile("cp.async.commit_group;"); }
__device__ __forceinline__ void cp_wait0()  { asm volatile("cp.async.wait_group 0;"); }
__device__ __forceinline__ void cp_wait1()  { asm volatile("cp.async.wait_group 1;"); }

// ---------------- mma / ldmatrix helpers ----------------
__device__ __forceinline__ void mma16816(float* d, const uint32_t* a, const uint32_t* b) {
    asm volatile(
        "mma.sync.aligned.m16n8k16.row.col.f32.bf16.bf16.f32 "
        "{%0,%1,%2,%3}, {%4,%5,%6,%7}, {%8,%9}, {%0,%1,%2,%3};"
        : "+f"(d[0]), "+f"(d[1]), "+f"(d[2]), "+f"(d[3])
        : "r"(a[0]), "r"(a[1]), "r"(a[2]), "r"(a[3]), "r"(b[0]), "r"(b[1]));
}
__device__ __forceinline__ void ldsm_x4(uint32_t* r, uint32_t addr) {
    asm volatile("ldmatrix.sync.aligned.m8n8.x4.shared.b16 {%0,%1,%2,%3}, [%4];"
        : "=r"(r[0]), "=r"(r[1]), "=r"(r[2]), "=r"(r[3]) : "r"(addr));
}
__device__ __forceinline__ void ldsm_x4t(uint32_t* r, uint32_t addr) {
    asm volatile("ldmatrix.sync.aligned.m8n8.x4.trans.shared.b16 {%0,%1,%2,%3}, [%4];"
        : "=r"(r[0]), "=r"(r[1]), "=r"(r[2]), "=r"(r[3]) : "r"(addr));
}
__device__ __forceinline__ void ldsm_x2t(uint32_t* r, uint32_t addr) {
    asm volatile("ldmatrix.sync.aligned.m8n8.x2.trans.shared.b16 {%0,%1}, [%2];"
        : "=r"(r[0]), "=r"(r[1]) : "r"(addr));
}
__device__ __forceinline__ uint32_t pack_bf2(float a, float b) {
    __nv_bfloat162 t = __floats2bfloat162_rn(a, b);
    return *(uint32_t*)&t;
}

// ---------------- filter taps ----------------
__global__ void filter_kernel(const int* __restrict__ li_p, const int* __restrict__ nl_p,
                              float* __restrict__ c, float* __restrict__ dcflag,
                              __nv_bfloat16* __restrict__ chi, __nv_bfloat16* __restrict__ clo)
{
    int n = blockIdx.x * blockDim.x + threadIdx.x;
    if (n >= SQ) return;
    int li = *li_p;
    int nl = *nl_p;
    const double ALPHA = 0.5;
    int M = MFREQ;
    int p, q;
    if (ALPHA <= 1.0 / (double)nl) {
        p = (int)(M * (1.0 - (double)(li + 1) / (double)nl));
        q = (int)((double)p + (double)M / (double)nl);
    } else {
        p = (nl > 1) ? (int)(M * (1.0 - ALPHA) * (1.0 - (double)li / (double)(nl - 1))) : 0;
        q = (int)((double)p + ALPHA * (double)M);
    }
    p = max(0, min(p, M - 1));
    q = max(p + 1, min(q, M));

    double acc = 0.0;
    const double w2 = 2.0 / (double)SQ;
    const double w1 = 1.0 / (double)SQ;
    const double tpn = 6.283185307179586476925286766559 * (double)n / (double)SQ;
    for (int f = p; f < q; f++) {
        double wf = (f == 0 || f == M - 1) ? w1 : w2;
        acc += wf * cos(tpn * (double)f);
    }
    float cf = (float)acc;
    c[n] = cf;
    __nv_bfloat16 h = __float2bfloat16_rn(cf);
    chi[n] = h;
    clo[n] = __float2bfloat16_rn(cf - __bfloat162float(h));
    if (n == 0) *dcflag = (p == 0) ? 1.0f : 0.0f;
}

__global__ void cmat_kernel(__nv_bfloat16* __restrict__ Chi, __nv_bfloat16* __restrict__ Clo,
                            const __nv_bfloat16* __restrict__ chi, const __nv_bfloat16* __restrict__ clo)
{
    int idx = blockIdx.x * blockDim.x + threadIdx.x;
    int t = idx >> 11;
    int s = idx & (SQ - 1);
    int tau = (t - s) & (SQ - 1);
    Chi[idx] = chi[tau];
    Clo[idx] = clo[tau];
}

__global__ void split_kernel(const float* __restrict__ in,
                             __nv_bfloat16* __restrict__ hi, __nv_bfloat16* __restrict__ lo, int n)
{
    int i = blockIdx.x * blockDim.x + threadIdx.x;
    if (i >= n) return;
    float f = in[i];
    __nv_bfloat16 h = __float2bfloat16_rn(f);
    hi[i] = h;
    lo[i] = __float2bfloat16_rn(f - __bfloat162float(h));
}

__global__ void zero_kernel(float* __restrict__ p, int n)
{
    int i = blockIdx.x * blockDim.x + threadIdx.x;
    if (i < n) p[i] = 0.f;
}

// ---------------- bf16-split tensor-core GEMM ----------------
#define GA_STR 40
#define GB_STR 136
#define A_BUF_ELEMS (128 * GA_STR)
#define B_BUF_ELEMS (32 * GB_STR)
__global__ __launch_bounds__(256) void gemm_bf16_kernel(
    const __nv_bfloat16* __restrict__ Ahi, const __nv_bfloat16* __restrict__ Alo,
    const __nv_bfloat16* __restrict__ Bhi, const __nv_bfloat16* __restrict__ Blo,
    const float* __restrict__ bias, const float* __restrict__ bscalep,
    float* __restrict__ C,
    __nv_bfloat16* __restrict__ Ohi, __nv_bfloat16* __restrict__ Olo,
    int M, int N, int K,
    long long sA, long long sB, long long sC)
{
    extern __shared__ __nv_bfloat16 sm[];
    __nv_bfloat16* AsHi = sm;
    __nv_bfloat16* AsLo = sm + 2 * A_BUF_ELEMS;
    __nv_bfloat16* BsHi = sm + 4 * A_BUF_ELEMS;
    __nv_bfloat16* BsLo = sm + 4 * A_BUF_ELEMS + 2 * B_BUF_ELEMS;
    uint32_t sbase = (uint32_t)__cvta_generic_to_shared(sm);

    int z = blockIdx.z;
    Ahi += (size_t)z * sA;  Alo += (size_t)z * sA;
    Bhi += (size_t)z * sB;  Blo += (size_t)z * sB;
    if (C)   C   += (size_t)z * sC;
    if (Ohi) { Ohi += (size_t)z * sC; Olo += (size_t)z * sC; }

    int tid = threadIdx.x;
    int lane = tid & 31;
    int wid = tid >> 5;
    int mBase = (wid >> 2) * 64;
    int nBase = (wid & 3) * 32;
    int row0 = blockIdx.y * 128;
    int col0 = blockIdx.x * 128;

    float acc[4][4][4];
#pragma unroll
    for (int mf = 0; mf < 4; mf++)
#pragma unroll
        for (int nf = 0; nf < 4; nf++)
#pragma unroll
            for (int r = 0; r < 4; r++) acc[mf][nf][r] = 0.f;

    int ar = tid >> 1;
    int br = tid >> 3;
    const __nv_bfloat16* Ah0 = Ahi + (size_t)(row0 + ar) * K;
    const __nv_bfloat16* Al0 = Alo + (size_t)(row0 + ar) * K;

#define LOAD_TILES(buf, k0)                                                             \
    do {                                                                                \
        _Pragma("unroll")                                                               \
        for (int j = 0; j < 2; j++) {                                                   \
            int s = (tid & 1) * 2 + j;                                                  \
            cp_async16(&AsHi[(buf) * A_BUF_ELEMS + ar * GA_STR + s * 8],                \
                       Ah0 + (k0) + s * 8);                                             \
            cp_async16(&AsLo[(buf) * A_BUF_ELEMS + ar * GA_STR + s * 8],                \
                       Al0 + (k0) + s * 8);                                             \
            int sb = (tid & 7) * 2 + j;                                                 \
            cp_async16(&BsHi[(buf) * B_BUF_ELEMS + br * GB_STR + sb * 8],               \
                       Bhi + (size_t)((k0) + br) * N + col0 + sb * 8);                  \
            cp_async16(&BsLo[(buf) * B_BUF_ELEMS + br * GB_STR + sb * 8],               \
                       Blo + (size_t)((k0) + br) * N + col0 + sb * 8);                  \
        }                                                                               \
    } while (0)

    LOAD_TILES(0, 0);
    cp_commit();
    cp_wait0();
    __syncthreads();

    int nIter = K >> 5;
    int lr = lane & 15;
    int khalf = (lane >> 4) << 3;

    for (int it = 0; it < nIter; it++) {
        int buf = it & 1;
        if (it + 1 < nIter) {
            LOAD_TILES(buf ^ 1, (it + 1) << 5);
            cp_commit();
        }

        uint32_t aHiB = sbase + 2 * (buf * A_BUF_ELEMS);
        uint32_t aLoB = sbase + 2 * (2 * A_BUF_ELEMS + buf * A_BUF_ELEMS);
        uint32_t bHiB = sbase + 2 * (4 * A_BUF_ELEMS + buf * B_BUF_ELEMS);
        uint32_t bLoB = sbase + 2 * (4 * A_BUF_ELEMS + 2 * B_BUF_ELEMS + buf * B_BUF_ELEMS);

#pragma unroll
        for (int ks = 0; ks < 32; ks += 16) {
            uint32_t ahi[4][4], alo[4][4], bhi[4][2], blo[4][2];
#pragma unroll
            for (int mf = 0; mf < 4; mf++) {
                uint32_t off = 2 * ((mBase + mf * 16 + lr) * GA_STR + ks + khalf);
                ldsm_x4(ahi[mf], aHiB + off);
                ldsm_x4(alo[mf], aLoB + off);
            }
#pragma unroll
            for (int nf = 0; nf < 4; nf++) {
                uint32_t off = 2 * ((ks + lr) * GB_STR + nBase + nf * 8);
                ldsm_x2t(bhi[nf], bHiB + off);
                ldsm_x2t(blo[nf], bLoB + off);
            }
#pragma unroll
            for (int mf = 0; mf < 4; mf++)
#pragma unroll
                for (int nf = 0; nf < 4; nf++) {
                    mma16816(acc[mf][nf], ahi[mf], bhi[nf]);
                    mma16816(acc[mf][nf], ahi[mf], blo[nf]);
                    mma16816(acc[mf][nf], alo[mf], bhi[nf]);
                }
        }

        if (it + 1 < nIter) cp_wait0();
        __syncthreads();
    }

    float bscale = 0.f;
    if (bias) bscale = bscalep ? *bscalep : 1.f;

#pragma unroll
    for (int mf = 0; mf < 4; mf++) {
        int r0 = row0 + mBase + mf * 16 + (lane >> 2);
#pragma unroll
        for (int nf = 0; nf < 4; nf++) {
            int c0 = col0 + nBase + nf * 8 + (lane & 3) * 2;
            float b0 = 0.f, b1 = 0.f;
            if (bias) { b0 = bias[c0] * bscale; b1 = bias[c0 + 1] * bscale; }
            float v0 = acc[mf][nf][0] + b0, v1 = acc[mf][nf][1] + b1;
            float v2 = acc[mf][nf][2] + b0, v3 = acc[mf][nf][3] + b1;
            if (C) {
                float2 w0 = {v0, v1}, w1 = {v2, v3};
                *(float2*)&C[(size_t)r0 * N + c0]       = w0;
                *(float2*)&C[(size_t)(r0 + 8) * N + c0] = w1;
            }
            if (Ohi) {
                __nv_bfloat16 h0 = __float2bfloat16_rn(v0), h1 = __float2bfloat16_rn(v1);
                __nv_bfloat16 h2 = __float2bfloat16_rn(v2), h3 = __float2bfloat16_rn(v3);
                __nv_bfloat162 hv0 = {h0, h1}, hv1 = {h2, h3};
                __nv_bfloat162 lv0 = {__float2bfloat16_rn(v0 - __bfloat162float(h0)),
                                      __float2bfloat16_rn(v1 - __bfloat162float(h1))};
                __nv_bfloat162 lv1 = {__float2bfloat16_rn(v2 - __bfloat162float(h2)),
                                      __float2bfloat16_rn(v3 - __bfloat162float(h3))};
                *(__nv_bfloat162*)&Ohi[(size_t)r0 * N + c0]       = hv0;
                *(__nv_bfloat162*)&Olo[(size_t)r0 * N + c0]       = lv0;
                *(__nv_bfloat162*)&Ohi[(size_t)(r0 + 8) * N + c0] = hv1;
                *(__nv_bfloat162*)&Olo[(size_t)(r0 + 8) * N + c0] = lv1;
            }
        }
    }
}

// ---------------- tensor-core flash attention (2 blocks/SM, double-buffered KV) ----------------
// 3-term QK (ac path needs accurate scores), 1-term PV (time-ctx error is diluted).
// KV per buffer: Khi | Klo | Vhi. Q smem reused as score tile after prologue.
#define FSTR 72
#define Q_ELEMS (128 * FSTR)          // 9216 elems (hi); lo at +Q_ELEMS
#define KV_BASE (2 * Q_ELEMS)         // 18432 elems
#define KV_ONE  (64 * FSTR)           // 4608 elems
#define KV_STRIDE (3 * KV_ONE)        // Khi,Klo,Vhi per buffer
#define SCS 66
#define ACB_OFF (2 * (KV_BASE + 2 * KV_STRIDE))   // 92160 bytes
#define FLASH_SMEM (ACB_OFF + SQ * 4)             // 100352 bytes
__global__ __launch_bounds__(256, 2) void flash_kernel(
    const __nv_bfloat16* __restrict__ Qhi_, const __nv_bfloat16* __restrict__ Qlo_,
    const __nv_bfloat16* __restrict__ Khi_, const __nv_bfloat16* __restrict__ Klo_,
    const __nv_bfloat16* __restrict__ Vhi_,
    const float* __restrict__ mask, float* __restrict__ Comb, float* __restrict__ ac)
{
    extern __shared__ __nv_bfloat16 smb[];
    float* Stile = (float*)smb;                      // aliases Q region after prologue
    float* acb   = (float*)((char*)smb + ACB_OFF);
    uint32_t sbase = (uint32_t)__cvta_generic_to_shared(smb);

    int tid = threadIdx.x;
    int lane = tid & 31, wid = tid >> 5;
    int qb = blockIdx.x, h = blockIdx.y, b = blockIdx.z;
    int t0 = qb * 128;
    int wr = wid * 16;

    size_t hoff = (size_t)b * SQ * HID + h * HD;
    const __nv_bfloat16* Qh = Qhi_ + hoff;
    const __nv_bfloat16* Ql = Qlo_ + hoff;
    const __nv_bfloat16* Kh = Khi_ + hoff;
    const __nv_bfloat16* Kl = Klo_ + hoff;
    const __nv_bfloat16* Vh = Vhi_ + hoff;
    const float* Mbase = mask + (size_t)b * SQ * SQ;
    float* acrow = ac + (size_t)(b * NH + h) * SQ;

#define LOAD_KV(bufi, kti)                                                              \
    do {                                                                                \
        int s0_ = (kti) * 64;                                                           \
        unsigned kvo_ = KV_BASE + (bufi) * KV_STRIDE;                                   \
        _Pragma("unroll")                                                               \
        for (int kk = 0; kk < 2; kk++) {                                                \
            int id_ = tid + kk * 256;                                                   \
            int r_ = id_ >> 3, c8_ = (id_ & 7) * 8;                                     \
            size_t src_ = (size_t)(s0_ + r_) * HID + c8_;                               \
            unsigned dst_ = kvo_ + r_ * FSTR + c8_;                                     \
            cp_async16(&smb[dst_],              Kh + src_);                             \
            cp_async16(&smb[dst_ + KV_ONE],     Kl + src_);                             \
            cp_async16(&smb[dst_ + 2 * KV_ONE], Vh + src_);                             \
        }                                                                               \
    } while (0)

    // prologue: Q tile + KV0 in flight
#pragma unroll
    for (int k = 0; k < 4; k++) {
        int id = tid + k * 256;
        int r = id >> 3, c8 = (id & 7) * 8;
        size_t src = (size_t)(t0 + r) * HID + c8;
        cp_async16(&smb[r * FSTR + c8],           Qh + src);
        cp_async16(&smb[Q_ELEMS + r * FSTR + c8], Ql + src);
    }
    cp_commit();
    LOAD_KV(0, 0);
    cp_commit();
    for (int i = tid; i < SQ; i += 256) acb[i] = 0.f;
    cp_wait1();          // Q arrived
    __syncthreads();

    // Q fragments (resident)
    uint32_t qhi[4][4], qlo[4][4];
    int lr = lane & 15, kh8 = (lane >> 4) * 8;
#pragma unroll
    for (int ks = 0; ks < 4; ks++) {
        uint32_t off = sbase + 2 * ((wr + lr) * FSTR + ks * 16 + kh8);
        ldsm_x4(qhi[ks], off);
        ldsm_x4(qlo[ks], off + 2 * Q_ELEMS);
    }
    cp_wait0();          // KV0 arrived
    __syncthreads();     // Q-frag reads done (Stile may now alias), KV0 visible

    float m0 = -INFINITY, m1 = -INFINITY, l0 = 0.f, l1 = 0.f;
    float o[8][4];
#pragma unroll
    for (int df = 0; df < 8; df++)
#pragma unroll
        for (int r = 0; r < 4; r++) o[df][r] = 0.f;

    int r4 = lane >> 2, c2 = (lane & 3) * 2;
    int qrow = t0 + wr + r4;
    int krL = ((lane >> 4) << 3) | (lane & 7);
    int kdL = ((lane >> 3) & 1) << 3;
    int vRow = lane & 15;
    int vSel = lane >> 4;

    int du = tid - 63;
    int drlo = du > 0 ? du : 0;
    int drhi = (du + 64 < 128) ? du + 64 : 128;
    const float* dbase = Stile - du;

    for (int kt = 0; kt < 32; kt++) {
        int s0 = kt * 64;
        int buf = kt & 1;
        bool has_next = (kt + 1 < 32);
        if (has_next) {
            LOAD_KV(buf ^ 1, kt + 1);   // safe: buf^1 reads ended before prev-iter sync
            cp_commit();
        }

        uint32_t kvbK = sbase + 2 * (KV_BASE + buf * KV_STRIDE);
        uint32_t kvbV = kvbK + 2 * (2 * KV_ONE);

        // scores: S = Qhi*Khi + Qhi*Klo + Qlo*Khi  (raw, fp32 acc)
        float s[8][4];
#pragma unroll
        for (int nf = 0; nf < 8; nf++)
#pragma unroll
            for (int r = 0; r < 4; r++) s[nf][r] = 0.f;
#pragma unroll
        for (int ks = 0; ks < 4; ks++) {
#pragma unroll
            for (int nf2 = 0; nf2 < 8; nf2 += 2) {
                uint32_t ko = kvbK + 2 * ((nf2 * 8 + krL) * FSTR + ks * 16 + kdL);
                uint32_t bh[4], bl[4];
                ldsm_x4(bh, ko);
                ldsm_x4(bl, ko + 2 * KV_ONE);
                mma16816(s[nf2],     qhi[ks], &bh[0]);
                mma16816(s[nf2],     qhi[ks], &bl[0]);
                mma16816(s[nf2],     qlo[ks], &bh[0]);
                mma16816(s[nf2 + 1], qhi[ks], &bh[2]);
                mma16816(s[nf2 + 1], qhi[ks], &bl[2]);
                mma16816(s[nf2 + 1], qlo[ks], &bh[2]);
            }
        }

        // stage RAW scores for diag phase
        {
            float* Sw0 = Stile + (wr + r4) * SCS + c2;
            float* Sw1 = Sw0 + 8 * SCS;
#pragma unroll
            for (int nf = 0; nf < 8; nf++) {
                float2 w0 = { s[nf][0], s[nf][1] };
                float2 w1 = { s[nf][2], s[nf][3] };
                *(float2*)(Sw0 + nf * 8) = w0;
                *(float2*)(Sw1 + nf * 8) = w1;
            }
        }

        // scale + mask + row max
        const float* mrow0 = Mbase + (size_t)qrow * SQ + s0 + c2;
        const float* mrow1 = mrow0 + 8 * SQ;
        float mx0 = -INFINITY, mx1 = -INFINITY;
#pragma unroll
        for (int nf = 0; nf < 8; nf++) {
            float2 ma = *(const float2*)(mrow0 + nf * 8);
            float2 mb = *(const float2*)(mrow1 + nf * 8);
            s[nf][0] = s[nf][0] * 0.125f + ma.x;
            s[nf][1] = s[nf][1] * 0.125f + ma.y;
            s[nf][2] = s[nf][2] * 0.125f + mb.x;
            s[nf][3] = s[nf][3] * 0.125f + mb.y;
            mx0 = fmaxf(mx0, fmaxf(s[nf][0], s[nf][1]));
            mx1 = fmaxf(mx1, fmaxf(s[nf][2], s[nf][3]));
        }
        mx0 = fmaxf(mx0, __shfl_xor_sync(0xffffffffu, mx0, 1));
        mx0 = fmaxf(mx0, __shfl_xor_sync(0xffffffffu, mx0, 2));
        mx1 = fmaxf(mx1, __shfl_xor_sync(0xffffffffu, mx1, 1));
        mx1 = fmaxf(mx1, __shfl_xor_sync(0xffffffffu, mx1, 2));
        float nm0 = fmaxf(m0, mx0), nm1 = fmaxf(m1, mx1);
        float cor0 = __expf(m0 - nm0), cor1 = __expf(m1 - nm1);
        m0 = nm0; m1 = nm1;

        // exp -> bf16 P, row sums from bf16 values
        uint32_t pa[4][4];
        float rs0 = 0.f, rs1 = 0.f;
#pragma unroll
        for (int kc = 0; kc < 4; kc++) {
            int n0 = 2 * kc, n1 = 2 * kc + 1;
            pa[kc][0] = pack_bf2(__expf(s[n0][0] - nm0), __expf(s[n0][1] - nm0));
            pa[kc][1] = pack_bf2(__expf(s[n0][2] - nm1), __expf(s[n0][3] - nm1));
            pa[kc][2] = pack_bf2(__expf(s[n1][0] - nm0), __expf(s[n1][1] - nm0));
            pa[kc][3] = pack_bf2(__expf(s[n1][2] - nm1), __expf(s[n1][3] - nm1));
            float2 u;
            u = __bfloat1622float2(*(__nv_bfloat162*)&pa[kc][0]); rs0 += u.x + u.y;
            u = __bfloat1622float2(*(__nv_bfloat162*)&pa[kc][2]); rs0 += u.x + u.y;
            u = __bfloat1622float2(*(__nv_bfloat162*)&pa[kc][1]); rs1 += u.x + u.y;
            u = __bfloat1622float2(*(__nv_bfloat162*)&pa[kc][3]); rs1 += u.x + u.y;
        }
        rs0 += __shfl_xor_sync(0xffffffffu, rs0, 1);
        rs0 += __shfl_xor_sync(0xffffffffu, rs0, 2);
        rs1 += __shfl_xor_sync(0xffffffffu, rs1, 1);
        rs1 += __shfl_xor_sync(0xffffffffu, rs1, 2);
        l0 = l0 * cor0 + rs0;
        l1 = l1 * cor1 + rs1;
#pragma unroll
        for (int df = 0; df < 8; df++) {
            o[df][0] *= cor0; o[df][1] *= cor0;
            o[df][2] *= cor1; o[df][3] *= cor1;
        }

        // O += P @ Vhi (1-term)
#pragma unroll
        for (int kc = 0; kc < 4; kc++) {
#pragma unroll
            for (int df2 = 0; df2 < 8; df2 += 2) {
                uint32_t vo = kvbV + 2 * ((kc * 16 + vRow) * FSTR + (df2 + vSel) * 8);
                uint32_t vh[4];
                ldsm_x4t(vh, vo);
                mma16816(o[df2],     pa[kc], &vh[0]);
                mma16816(o[df2 + 1], pa[kc], &vh[2]);
            }
        }
        __syncthreads();                 // Stile written; cur-buf KV reads done

        // diagonal reduction (overlaps next-KV load in flight)
        if (tid < 191) {
            float sa = 0.f, sb = 0.f;
            int r = drlo;
            for (; r + 1 < drhi; r += 2) {
                sa += dbase[r * (SCS + 1)];
                sb += dbase[r * (SCS + 1) + (SCS + 1)];
            }
            if (r < drhi) sa += dbase[r * (SCS + 1)];
            int tau = (t0 - s0 + du) & (SQ - 1);
            acb[tau] += (sa + sb) * (1.f / 64.f);
        }
        if (has_next) cp_wait0();
        __syncthreads();                 // next KV visible; Stile reads done
    }

    // flush tau bins
    for (int i = tid; i < SQ; i += 256)
        atomicAdd(&acrow[i], acb[i]);

    // epilogue: Comb = 0.5 * ctx
    float inv0 = 0.5f / l0, inv1 = 0.5f / l1;
    float* C0 = Comb + (size_t)b * SQ * HID + (size_t)qrow * HID + h * HD + c2;
#pragma unroll
    for (int df = 0; df < 8; df++) {
        float2 va = { o[df][0] * inv0, o[df][1] * inv0 };
        float2 vb = { o[df][2] * inv1, o[df][3] * inv1 };
        *(float2*)(C0 + df * 8)            = va;
        *(float2*)(C0 + 8 * HID + df * 8)  = vb;
    }
}

// ---------------- top-k (k=15) + softmax weights ----------------
__global__ __launch_bounds__(256) void topk_kernel(
    const float* __restrict__ ac, int* __restrict__ topi, float* __restrict__ topw)
{
    int bh = blockIdx.x;
    __shared__ float svv[SQ];
    __shared__ float rv[256];
    __shared__ int ri[256];
    __shared__ float tvals[KTOP];
    __shared__ int tidxs[KTOP];
    int tid = threadIdx.x;

    for (int i = tid; i < SQ; i += 256)
        svv[i] = ac[(size_t)bh * SQ + i];
    __syncthreads();

    for (int t = 0; t < KTOP; t++) {
        float bv = -INFINITY;
        int bi = 0;
        for (int i = tid; i < SQ; i += 256) {
            float v = svv[i];
            if (v > bv || (v == bv && i < bi)) { bv = v; bi = i; }
        }
        rv[tid] = bv; ri[tid] = bi;
        __syncthreads();
        for (int st = 128; st > 0; st >>= 1) {
            if (tid < st) {
                float v2 = rv[tid + st]; int i2 = ri[tid + st];
                if (v2 > rv[tid] || (v2 == rv[tid] && i2 < ri[tid])) { rv[tid] = v2; ri[tid] = i2; }
            }
            __syncthreads();
        }
        if (tid == 0) {
            tvals[t] = rv[0]; tidxs[t] = ri[0];
            svv[ri[0]] = -INFINITY;
        }
        __syncthreads();
    }

    if (tid == 0) {
        float mx = tvals[0];
        float e[KTOP], ssum = 0.f;
#pragma unroll
        for (int t = 0; t < KTOP; t++) { e[t] = __expf(tvals[t] - mx); ssum += e[t]; }
        float inv = 1.f / ssum;
#pragma unroll
        for (int t = 0; t < KTOP; t++) {
            topw[bh * KTOP + t] = e[t] * inv;
            topi[bh * KTOP + t] = tidxs[t];
        }
    }
}

// ---------------- frequency branch gather ----------------
__global__ __launch_bounds__(256) void freq_kernel(
    const float* __restrict__ V, const int* __restrict__ topi,
    const float* __restrict__ topw, float* __restrict__ Comb)
{
    int t = blockIdx.x, b = blockIdx.y;
    __shared__ int si[NH * KTOP];
    __shared__ float sw[NH * KTOP];
    int tid = threadIdx.x;
    if (tid < NH * KTOP) {
        si[tid] = topi[b * NH * KTOP + tid];
        sw[tid] = topw[b * NH * KTOP + tid];
    }
    __syncthreads();

    int c = tid * 4;
    int h = c >> 6;
    float* crow = Comb + ((size_t)b * SQ + t) * HID + c;
    float4 acc = *(float4*)crow;
    const float* Vb = V + (size_t)b * SQ * HID;
#pragma unroll
    for (int j = 0; j < KTOP; j++) {
        int row = (t + si[h * KTOP + j]) & (SQ - 1);
        float w = 0.5f * sw[h * KTOP + j];
        float4 v = *(const float4*)&Vb[(size_t)row * HID + c];
        acc.x += w * v.x; acc.y += w * v.y; acc.z += w * v.z; acc.w += w * v.w;
    }
    *(float4*)crow = acc;
}

// ---------------- launcher ----------------
extern "C" void kernel_launch(void* const* d_in, const int* in_sizes, int n_in,
                              void* d_out, int out_size)
{
    const float* X    = (const float*)d_in[0];
    const float* mask = (const float*)d_in[1];
    const float* Wq   = (const float*)d_in[2];
    const float* bq   = (const float*)d_in[3];
    const float* Wk   = (const float*)d_in[4];
    const float* bk   = (const float*)d_in[5];
    const float* Wv   = (const float*)d_in[6];
    const float* bv   = (const float*)d_in[7];
    const float* Wo   = (const float*)d_in[8];
    const float* bo   = (const float*)d_in[9];
    const int*   li   = (const int*)d_in[10];
    const int*   nl   = (const int*)d_in[11];
    float* out = (float*)d_out;

    float *cP, *dcP, *VbP, *CbP, *acP, *twP;
    int* tiP;
    __nv_bfloat16 *chiP, *cloP, *ChiP, *CloP, *XhiP, *XloP, *XfhiP, *XfloP, *CbhiP, *CbloP;
    __nv_bfloat16 *QfhiP, *QfloP, *KfhiP, *KfloP, *VfhiP, *VfloP;
    __nv_bfloat16 *WqhiP, *WqloP, *WkhiP, *WkloP, *WvhiP, *WvloP, *WohiP, *WoloP;
    cudaGetSymbolAddress((void**)&cP,  d_c);
    cudaGetSymbolAddress((void**)&dcP, d_dcflag);
    cudaGetSymbolAddress((void**)&VbP, d_Vbuf);
    cudaGetSymbolAddress((void**)&CbP, d_Comb);
    cudaGetSymbolAddress((void**)&acP, d_ac);
    cudaGetSymbolAddress((void**)&tiP, d_topi);
    cudaGetSymbolAddress((void**)&twP, d_topw);
    cudaGetSymbolAddress((void**)&chiP, d_chi);
    cudaGetSymbolAddress((void**)&cloP, d_clo);
    cudaGetSymbolAddress((void**)&ChiP, d_Chi);
    cudaGetSymbolAddress((void**)&CloP, d_Clo);
    cudaGetSymbolAddress((void**)&XhiP, d_Xhi);
    cudaGetSymbolAddress((void**)&XloP, d_Xlo);
    cudaGetSymbolAddress((void**)&XfhiP, d_Xfhi);
    cudaGetSymbolAddress((void**)&XfloP, d_Xflo);
    cudaGetSymbolAddress((void**)&QfhiP, d_Qfhi);
    cudaGetSymbolAddress((void**)&QfloP, d_Qflo);
    cudaGetSymbolAddress((void**)&KfhiP, d_Kfhi);
    cudaGetSymbolAddress((void**)&KfloP, d_Kflo);
    cudaGetSymbolAddress((void**)&VfhiP, d_Vfhi);
    cudaGetSymbolAddress((void**)&VfloP, d_Vflo);
    cudaGetSymbolAddress((void**)&CbhiP, d_Cbhi);
    cudaGetSymbolAddress((void**)&CbloP, d_Cblo);
    cudaGetSymbolAddress((void**)&WqhiP, d_Wqhi);
    cudaGetSymbolAddress((void**)&WqloP, d_Wqlo);
    cudaGetSymbolAddress((void**)&WkhiP, d_Wkhi);
    cudaGetSymbolAddress((void**)&WkloP, d_Wklo);
    cudaGetSymbolAddress((void**)&WvhiP, d_Wvhi);
    cudaGetSymbolAddress((void**)&WvloP, d_Wvlo);
    cudaGetSymbolAddress((void**)&WohiP, d_Wohi);
    cudaGetSymbolAddress((void**)&WoloP, d_Wolo);

    const long long SH = (long long)SQ * HID;
    const int NELT = BSZ * SQ * HID;
    const int WELT = HID * HID;

    static bool attrs_set = false;
    if (!attrs_set) {
        cudaFuncSetAttribute(gemm_bf16_kernel, cudaFuncAttributeMaxDynamicSharedMemorySize, 75776);
        cudaFuncSetAttribute(flash_kernel,     cudaFuncAttributeMaxDynamicSharedMemorySize, FLASH_SMEM);
        attrs_set = true;
    }

    // 1) filter taps + circulant (bf16)
    filter_kernel<<<8, 256>>>(li, nl, cP, dcP, chiP, cloP);
    cmat_kernel<<<(SQ * SQ) / 256, 256>>>(ChiP, CloP, chiP, cloP);

    // 2) split inputs
    split_kernel<<<NELT / 256, 256>>>(X, XhiP, XloP, NELT);
    split_kernel<<<WELT / 256, 256>>>(Wq, WqhiP, WqloP, WELT);
    split_kernel<<<WELT / 256, 256>>>(Wk, WkhiP, WkloP, WELT);
    split_kernel<<<WELT / 256, 256>>>(Wv, WvhiP, WvloP, WELT);
    split_kernel<<<WELT / 256, 256>>>(Wo, WohiP, WoloP, WELT);

    // 3) Xf = C @ X  -> bf16 hi/lo directly
    gemm_bf16_kernel<<<dim3(HID / 128, SQ / 128, BSZ), 256, 75776>>>(
        ChiP, CloP, XhiP, XloP, nullptr, nullptr, nullptr, XfhiP, XfloP, SQ, HID, SQ, 0, SH, SH);

    // 4) projections -> bf16 hi/lo for flash; Vbuf fp32 for freq branch
    gemm_bf16_kernel<<<dim3(HID / 128, SQ / 128, BSZ), 256, 75776>>>(
        XfhiP, XfloP, WqhiP, WqloP, bq, dcP, nullptr, QfhiP, QfloP, SQ, HID, HID, SH, 0, SH);
    gemm_bf16_kernel<<<dim3(HID / 128, SQ / 128, BSZ), 256, 75776>>>(
        XfhiP, XfloP, WkhiP, WkloP, bk, dcP, nullptr, KfhiP, KfloP, SQ, HID, HID, SH, 0, SH);
    gemm_bf16_kernel<<<dim3(HID / 128, SQ / 128, BSZ), 256, 75776>>>(
        XfhiP, XfloP, WvhiP, WvloP, bv, dcP, nullptr, VfhiP, VfloP, SQ, HID, HID, SH, 0, SH);
    gemm_bf16_kernel<<<dim3(HID / 128, SQ / 128, BSZ), 256, 75776>>>(
        XhiP, XloP, WvhiP, WvloP, bv, nullptr, VbP, nullptr, nullptr, SQ, HID, HID, SH, 0, SH);

    // 5) flash attention (2 blocks/SM, double-buffered) + diag-sum autocorrelation
    zero_kernel<<<(BSZ * NH * SQ) / 256, 256>>>(acP, BSZ * NH * SQ);
    flash_kernel<<<dim3(SQ / 128, NH, BSZ), 256, FLASH_SMEM>>>(
        QfhiP, QfloP, KfhiP, KfloP, VfhiP, mask, CbP, acP);

    // 6) top-k + frequency gather
    topk_kernel<<<BSZ * NH, 256>>>(acP, tiP, twP);
    freq_kernel<<<dim3(SQ, BSZ), 256>>>(VbP, tiP, twP, CbP);

    // 7) output projection
    split_kernel<<<NELT / 256, 256>>>(CbP, CbhiP, CbloP, NELT);
    gemm_bf16_kernel<<<dim3(HID / 128, (BSZ * SQ) / 128, 1), 256, 75776>>>(
        CbhiP, CbloP, WohiP, WoloP, bo, nullptr, out, nullptr, nullptr, BSZ * SQ, HID, HID, 0, 0, 0);
}

// round 10
// speedup vs baseline: 2.1510x; 1.0077x over previous
#include <cuda_runtime.h>
#include <cuda_bf16.h>
#include <math.h>
#include <stdint.h>

#define SQ   2048
#define HID  1024
#define NH   16
#define HD   64
#define BSZ  2
#define MFREQ (SQ/2 + 1)
#define KTOP 15

// ---------------- scratch ----------------
__device__ float d_c[SQ];
__device__ float d_dcflag;
__device__ int   d_maskflag;
__device__ float d_Vbuf[BSZ * SQ * HID];
__device__ float d_Comb[BSZ * SQ * HID];
__device__ float d_ac  [BSZ * NH * SQ];
__device__ int   d_topi[BSZ * NH * KTOP];
__device__ float d_topw[BSZ * NH * KTOP];

__device__ __nv_bfloat16 d_chi[SQ], d_clo[SQ];
__device__ __nv_bfloat16 d_Chi [SQ * SQ],        d_Clo [SQ * SQ];
__device__ __nv_bfloat16 d_Xhi [BSZ * SQ * HID], d_Xlo [BSZ * SQ * HID];
__device__ __nv_bfloat16 d_Xfhi[BSZ * SQ * HID], d_Xflo[BSZ * SQ * HID];
__device__ __nv_bfloat16 d_Qfhi[BSZ * SQ * HID], d_Qflo[BSZ * SQ * HID];
__device__ __nv_bfloat16 d_Kfhi[BSZ * SQ * HID], d_Kflo[BSZ * SQ * HID];
__device__ __nv_bfloat16 d_Vfhi[BSZ * SQ * HID], d_Vflo[BSZ * SQ * HID];
__device__ __nv_bfloat16 d_Cbhi[BSZ * SQ * HID], d_Cblo[BSZ * SQ * HID];
__device__ __nv_bfloat16 d_Wqhi[HID * HID], d_Wqlo[HID * HID];
__device__ __nv_bfloat16 d_Wkhi[HID * HID], d_Wklo[HID * HID];
__device__ __nv_bfloat16 d_Wvhi[HID * HID], d_Wvlo[HID * HID];
__device__ __nv_bfloat16 d_Wohi[HID * HID], d_Wolo[HID * HID];

// ---------------- cp.async helpers ----------------
__device__ __forceinline__ void cp_async16(void* smem, const void* gmem) {
    unsigned s = (unsigned)__cvta_generic_to_shared(smem);
    asm volatile("cp.async.cg.shared.global [%0], [%1], 16;" :: "r"(s), "l"(gmem));
}
__device__ __forceinline__ void cp_commit() { asm volatile("cp.async.commit_group;"); }
__device__ __forceinline__ void cp_wait0()  { asm volatile("cp.async.wait_group 0;"); }
__device__ __forceinline__ void cp_wait1()  { asm volatile("cp.async.wait_group 1;"); }

// ---------------- mma / ldmatrix helpers ----------------
__device__ __forceinline__ void mma16816(float* d, const uint32_t* a, const uint32_t* b) {
    asm volatile(
        "mma.sync.aligned.m16n8k16.row.col.f32.bf16.bf16.f32 "
        "{%0,%1,%2,%3}, {%4,%5,%6,%7}, {%8,%9}, {%0,%1,%2,%3};"
        : "+f"(d[0]), "+f"(d[1]), "+f"(d[2]), "+f"(d[3])
        : "r"(a[0]), "r"(a[1]), "r"(a[2]), "r"(a[3]), "r"(b[0]), "r"(b[1]));
}
__device__ __forceinline__ void ldsm_x4(uint32_t* r, uint32_t addr) {
    asm volatile("ldmatrix.sync.aligned.m8n8.x4.shared.b16 {%0,%1,%2,%3}, [%4];"
        : "=r"(r[0]), "=r"(r[1]), "=r"(r[2]), "=r"(r[3]) : "r"(addr));
}
__device__ __forceinline__ void ldsm_x4t(uint32_t* r, uint32_t addr) {
    asm volatile("ldmatrix.sync.aligned.m8n8.x4.trans.shared.b16 {%0,%1,%2,%3}, [%4];"
        : "=r"(r[0]), "=r"(r[1]), "=r"(r[2]), "=r"(r[3]) : "r"(addr));
}
__device__ __forceinline__ void ldsm_x2t(uint32_t* r, uint32_t addr) {
    asm volatile("ldmatrix.sync.aligned.m8n8.x2.trans.shared.b16 {%0,%1}, [%2];"
        : "=r"(r[0]), "=r"(r[1]) : "r"(addr));
}
__device__ __forceinline__ uint32_t pack_bf2(float a, float b) {
    __nv_bfloat162 t = __floats2bfloat162_rn(a, b);
    return *(uint32_t*)&t;
}

// ---------------- filter taps ----------------
__global__ void filter_kernel(const int* __restrict__ li_p, const int* __restrict__ nl_p,
                              float* __restrict__ c, float* __restrict__ dcflag,
                              __nv_bfloat16* __restrict__ chi, __nv_bfloat16* __restrict__ clo)
{
    int n = blockIdx.x * blockDim.x + threadIdx.x;
    if (n >= SQ) return;
    int li = *li_p;
    int nl = *nl_p;
    const double ALPHA = 0.5;
    int M = MFREQ;
    int p, q;
    if (ALPHA <= 1.0 / (double)nl) {
        p = (int)(M * (1.0 - (double)(li + 1) / (double)nl));
        q = (int)((double)p + (double)M / (double)nl);
    } else {
        p = (nl > 1) ? (int)(M * (1.0 - ALPHA) * (1.0 - (double)li / (double)(nl - 1))) : 0;
        q = (int)((double)p + ALPHA * (double)M);
    }
    p = max(0, min(p, M - 1));
    q = max(p + 1, min(q, M));

    double acc = 0.0;
    const double w2 = 2.0 / (double)SQ;
    const double w1 = 1.0 / (double)SQ;
    const double tpn = 6.283185307179586476925286766559 * (double)n / (double)SQ;
    for (int f = p; f < q; f++) {
        double wf = (f == 0 || f == M - 1) ? w1 : w2;
        acc += wf * cos(tpn * (double)f);
    }
    float cf = (float)acc;
    c[n] = cf;
    __nv_bfloat16 h = __float2bfloat16_rn(cf);
    chi[n] = h;
    clo[n] = __float2bfloat16_rn(cf - __bfloat162float(h));
    if (n == 0) *dcflag = (p == 0) ? 1.0f : 0.0f;
}

__global__ void cmat_kernel(__nv_bfloat16* __restrict__ Chi, __nv_bfloat16* __restrict__ Clo,
                            const __nv_bfloat16* __restrict__ chi, const __nv_bfloat16* __restrict__ clo)
{
    int idx = blockIdx.x * blockDim.x + threadIdx.x;
    int t = idx >> 11;
    int s = idx & (SQ - 1);
    int tau = (t - s) & (SQ - 1);
    Chi[idx] = chi[tau];
    Clo[idx] = clo[tau];
}

__global__ void split_kernel(const float* __restrict__ in,
                             __nv_bfloat16* __restrict__ hi, __nv_bfloat16* __restrict__ lo, int n)
{
    int i = blockIdx.x * blockDim.x + threadIdx.x;
    if (i >= n) return;
    float f = in[i];
    __nv_bfloat16 h = __float2bfloat16_rn(f);
    hi[i] = h;
    lo[i] = __float2bfloat16_rn(f - __bfloat162float(h));
}

__global__ void zero_kernel(float* __restrict__ p, int n)
{
    int i = blockIdx.x * blockDim.x + threadIdx.x;
    if (i < n) p[i] = 0.f;
}

__global__ void setflag_kernel(int* __restrict__ flag) { *flag = 0; }

// OR-reduce: flag=1 if any mask element nonzero
__global__ void maskcheck_kernel(const float4* __restrict__ m, int n4, int* __restrict__ flag)
{
    int i = blockIdx.x * blockDim.x + threadIdx.x;
    int stride = gridDim.x * blockDim.x;
    bool nz = false;
    for (; i < n4; i += stride) {
        float4 v = m[i];
        nz = nz || (v.x != 0.f) || (v.y != 0.f) || (v.z != 0.f) || (v.w != 0.f);
    }
    if (__syncthreads_or(nz) && threadIdx.x == 0)
        atomicOr(flag, 1);
}

// ---------------- bf16-split tensor-core GEMM ----------------
#define GA_STR 40
#define GB_STR 136
#define A_BUF_ELEMS (128 * GA_STR)
#define B_BUF_ELEMS (32 * GB_STR)
__global__ __launch_bounds__(256) void gemm_bf16_kernel(
    const __nv_bfloat16* __restrict__ Ahi, const __nv_bfloat16* __restrict__ Alo,
    const __nv_bfloat16* __restrict__ Bhi, const __nv_bfloat16* __restrict__ Blo,
    const float* __restrict__ bias, const float* __restrict__ bscalep,
    float* __restrict__ C,
    __nv_bfloat16* __restrict__ Ohi, __nv_bfloat16* __restrict__ Olo,
    int M, int N, int K,
    long long sA, long long sB, long long sC)
{
    extern __shared__ __nv_bfloat16 sm[];
    __nv_bfloat16* AsHi = sm;
    __nv_bfloat16* AsLo = sm + 2 * A_BUF_ELEMS;
    __nv_bfloat16* BsHi = sm + 4 * A_BUF_ELEMS;
    __nv_bfloat16* BsLo = sm + 4 * A_BUF_ELEMS + 2 * B_BUF_ELEMS;
    uint32_t sbase = (uint32_t)__cvta_generic_to_shared(sm);

    int z = blockIdx.z;
    Ahi += (size_t)z * sA;  Alo += (size_t)z * sA;
    Bhi += (size_t)z * sB;  Blo += (size_t)z * sB;
    if (C)   C   += (size_t)z * sC;
    if (Ohi) { Ohi += (size_t)z * sC; Olo += (size_t)z * sC; }

    int tid = threadIdx.x;
    int lane = tid & 31;
    int wid = tid >> 5;
    int mBase = (wid >> 2) * 64;
    int nBase = (wid & 3) * 32;
    int row0 = blockIdx.y * 128;
    int col0 = blockIdx.x * 128;

    float acc[4][4][4];
#pragma unroll
    for (int mf = 0; mf < 4; mf++)
#pragma unroll
        for (int nf = 0; nf < 4; nf++)
#pragma unroll
            for (int r = 0; r < 4; r++) acc[mf][nf][r] = 0.f;

    int ar = tid >> 1;
    int br = tid >> 3;
    const __nv_bfloat16* Ah0 = Ahi + (size_t)(row0 + ar) * K;
    const __nv_bfloat16* Al0 = Alo + (size_t)(row0 + ar) * K;

#define LOAD_TILES(buf, k0)                                                             \
    do {                                                                                \
        _Pragma("unroll")                                                               \
        for (int j = 0; j < 2; j++) {                                                   \
            int s = (tid & 1) * 2 + j;                                                  \
            cp_async16(&AsHi[(buf) * A_BUF_ELEMS + ar * GA_STR + s * 8],                \
                       Ah0 + (k0) + s * 8);                                             \
            cp_async16(&AsLo[(buf) * A_BUF_ELEMS + ar * GA_STR + s * 8],                \
                       Al0 + (k0) + s * 8);                                             \
            int sb = (tid & 7) * 2 + j;                                                 \
            cp_async16(&BsHi[(buf) * B_BUF_ELEMS + br * GB_STR + sb * 8],               \
                       Bhi + (size_t)((k0) + br) * N + col0 + sb * 8);                  \
            cp_async16(&BsLo[(buf) * B_BUF_ELEMS + br * GB_STR + sb * 8],               \
                       Blo + (size_t)((k0) + br) * N + col0 + sb * 8);                  \
        }                                                                               \
    } while (0)

    LOAD_TILES(0, 0);
    cp_commit();
    cp_wait0();
    __syncthreads();

    int nIter = K >> 5;
    int lr = lane & 15;
    int khalf = (lane >> 4) << 3;

    for (int it = 0; it < nIter; it++) {
        int buf = it & 1;
        if (it + 1 < nIter) {
            LOAD_TILES(buf ^ 1, (it + 1) << 5);
            cp_commit();
        }

        uint32_t aHiB = sbase + 2 * (buf * A_BUF_ELEMS);
        uint32_t aLoB = sbase + 2 * (2 * A_BUF_ELEMS + buf * A_BUF_ELEMS);
        uint32_t bHiB = sbase + 2 * (4 * A_BUF_ELEMS + buf * B_BUF_ELEMS);
        uint32_t bLoB = sbase + 2 * (4 * A_BUF_ELEMS + 2 * B_BUF_ELEMS + buf * B_BUF_ELEMS);

#pragma unroll
        for (int ks = 0; ks < 32; ks += 16) {
            uint32_t ahi[4][4], alo[4][4], bhi[4][2], blo[4][2];
#pragma unroll
            for (int mf = 0; mf < 4; mf++) {
                uint32_t off = 2 * ((mBase + mf * 16 + lr) * GA_STR + ks + khalf);
                ldsm_x4(ahi[mf], aHiB + off);
                ldsm_x4(alo[mf], aLoB + off);
            }
#pragma unroll
            for (int nf = 0; nf < 4; nf++) {
                uint32_t off = 2 * ((ks + lr) * GB_STR + nBase + nf * 8);
                ldsm_x2t(bhi[nf], bHiB + off);
                ldsm_x2t(blo[nf], bLoB + off);
            }
#pragma unroll
            for (int mf = 0; mf < 4; mf++)
#pragma unroll
                for (int nf = 0; nf < 4; nf++) {
                    mma16816(acc[mf][nf], ahi[mf], bhi[nf]);
                    mma16816(acc[mf][nf], ahi[mf], blo[nf]);
                    mma16816(acc[mf][nf], alo[mf], bhi[nf]);
                }
        }

        if (it + 1 < nIter) cp_wait0();
        __syncthreads();
    }

    float bscale = 0.f;
    if (bias) bscale = bscalep ? *bscalep : 1.f;

#pragma unroll
    for (int mf = 0; mf < 4; mf++) {
        int r0 = row0 + mBase + mf * 16 + (lane >> 2);
#pragma unroll
        for (int nf = 0; nf < 4; nf++) {
            int c0 = col0 + nBase + nf * 8 + (lane & 3) * 2;
            float b0 = 0.f, b1 = 0.f;
            if (bias) { b0 = bias[c0] * bscale; b1 = bias[c0 + 1] * bscale; }
            float v0 = acc[mf][nf][0] + b0, v1 = acc[mf][nf][1] + b1;
            float v2 = acc[mf][nf][2] + b0, v3 = acc[mf][nf][3] + b1;
            if (C) {
                float2 w0 = {v0, v1}, w1 = {v2, v3};
                *(float2*)&C[(size_t)r0 * N + c0]       = w0;
                *(float2*)&C[(size_t)(r0 + 8) * N + c0] = w1;
            }
            if (Ohi) {
                __nv_bfloat16 h0 = __float2bfloat16_rn(v0), h1 = __float2bfloat16_rn(v1);
                __nv_bfloat16 h2 = __float2bfloat16_rn(v2), h3 = __float2bfloat16_rn(v3);
                __nv_bfloat162 hv0 = {h0, h1}, hv1 = {h2, h3};
                __nv_bfloat162 lv0 = {__float2bfloat16_rn(v0 - __bfloat162float(h0)),
                                      __float2bfloat16_rn(v1 - __bfloat162float(h1))};
                __nv_bfloat162 lv1 = {__float2bfloat16_rn(v2 - __bfloat162float(h2)),
                                      __float2bfloat16_rn(v3 - __bfloat162float(h3))};
                *(__nv_bfloat162*)&Ohi[(size_t)r0 * N + c0]       = hv0;
                *(__nv_bfloat162*)&Olo[(size_t)r0 * N + c0]       = lv0;
                *(__nv_bfloat162*)&Ohi[(size_t)(r0 + 8) * N + c0] = hv1;
                *(__nv_bfloat162*)&Olo[(size_t)(r0 + 8) * N + c0] = lv1;
            }
        }
    }
}

// ---------------- tensor-core flash attention (2 blocks/SM, double-buffered KV) ----------------
// 3-term QK, 1-term PV. Mask loads skipped entirely when maskflag==0 (bit-identical).
#define FSTR 72
#define Q_ELEMS (128 * FSTR)
#define KV_BASE (2 * Q_ELEMS)
#define KV_ONE  (64 * FSTR)
#define KV_STRIDE (3 * KV_ONE)
#define SCS 66
#define ACB_OFF (2 * (KV_BASE + 2 * KV_STRIDE))   // 92160 bytes
#define FLASH_SMEM (ACB_OFF + SQ * 4)             // 100352 bytes
__global__ __launch_bounds__(256, 2) void flash_kernel(
    const __nv_bfloat16* __restrict__ Qhi_, const __nv_bfloat16* __restrict__ Qlo_,
    const __nv_bfloat16* __restrict__ Khi_, const __nv_bfloat16* __restrict__ Klo_,
    const __nv_bfloat16* __restrict__ Vhi_,
    const float* __restrict__ mask, const int* __restrict__ maskflag,
    float* __restrict__ Comb, float* __restrict__ ac)
{
    extern __shared__ __nv_bfloat16 smb[];
    float* Stile = (float*)smb;
    float* acb   = (float*)((char*)smb + ACB_OFF);
    uint32_t sbase = (uint32_t)__cvta_generic_to_shared(smb);

    int tid = threadIdx.x;
    int lane = tid & 31, wid = tid >> 5;
    int qb = blockIdx.x, h = blockIdx.y, b = blockIdx.z;
    int t0 = qb * 128;
    int wr = wid * 16;
    const int useMask = *maskflag;

    size_t hoff = (size_t)b * SQ * HID + h * HD;
    const __nv_bfloat16* Qh = Qhi_ + hoff;
    const __nv_bfloat16* Ql = Qlo_ + hoff;
    const __nv_bfloat16* Kh = Khi_ + hoff;
    const __nv_bfloat16* Kl = Klo_ + hoff;
    const __nv_bfloat16* Vh = Vhi_ + hoff;
    const float* Mbase = mask + (size_t)b * SQ * SQ;
    float* acrow = ac + (size_t)(b * NH + h) * SQ;

#define LOAD_KV(bufi, kti)                                                              \
    do {                                                                                \
        int s0_ = (kti) * 64;                                                           \
        unsigned kvo_ = KV_BASE + (bufi) * KV_STRIDE;                                   \
        _Pragma("unroll")                                                               \
        for (int kk = 0; kk < 2; kk++) {                                                \
            int id_ = tid + kk * 256;                                                   \
            int r_ = id_ >> 3, c8_ = (id_ & 7) * 8;                                     \
            size_t src_ = (size_t)(s0_ + r_) * HID + c8_;                               \
            unsigned dst_ = kvo_ + r_ * FSTR + c8_;                                     \
            cp_async16(&smb[dst_],              Kh + src_);                             \
            cp_async16(&smb[dst_ + KV_ONE],     Kl + src_);                             \
            cp_async16(&smb[dst_ + 2 * KV_ONE], Vh + src_);                             \
        }                                                                               \
    } while (0)

    // prologue: Q tile + KV0 in flight
#pragma unroll
    for (int k = 0; k < 4; k++) {
        int id = tid + k * 256;
        int r = id >> 3, c8 = (id & 7) * 8;
        size_t src = (size_t)(t0 + r) * HID + c8;
        cp_async16(&smb[r * FSTR + c8],           Qh + src);
        cp_async16(&smb[Q_ELEMS + r * FSTR + c8], Ql + src);
    }
    cp_commit();
    LOAD_KV(0, 0);
    cp_commit();
    for (int i = tid; i < SQ; i += 256) acb[i] = 0.f;
    cp_wait1();
    __syncthreads();

    // Q fragments (resident)
    uint32_t qhi[4][4], qlo[4][4];
    int lr = lane & 15, kh8 = (lane >> 4) * 8;
#pragma unroll
    for (int ks = 0; ks < 4; ks++) {
        uint32_t off = sbase + 2 * ((wr + lr) * FSTR + ks * 16 + kh8);
        ldsm_x4(qhi[ks], off);
        ldsm_x4(qlo[ks], off + 2 * Q_ELEMS);
    }
    cp_wait0();
    __syncthreads();

    float m0 = -INFINITY, m1 = -INFINITY, l0 = 0.f, l1 = 0.f;
    float o[8][4];
#pragma unroll
    for (int df = 0; df < 8; df++)
#pragma unroll
        for (int r = 0; r < 4; r++) o[df][r] = 0.f;

    int r4 = lane >> 2, c2 = (lane & 3) * 2;
    int qrow = t0 + wr + r4;
    int krL = ((lane >> 4) << 3) | (lane & 7);
    int kdL = ((lane >> 3) & 1) << 3;
    int vRow = lane & 15;
    int vSel = lane >> 4;

    int du = tid - 63;
    int drlo = du > 0 ? du : 0;
    int drhi = (du + 64 < 128) ? du + 64 : 128;
    const float* dbase = Stile - du;

    for (int kt = 0; kt < 32; kt++) {
        int s0 = kt * 64;
        int buf = kt & 1;
        bool has_next = (kt + 1 < 32);
        if (has_next) {
            LOAD_KV(buf ^ 1, kt + 1);
            cp_commit();
        }

        uint32_t kvbK = sbase + 2 * (KV_BASE + buf * KV_STRIDE);
        uint32_t kvbV = kvbK + 2 * (2 * KV_ONE);

        // scores: S = Qhi*Khi + Qhi*Klo + Qlo*Khi  (raw, fp32 acc)
        float s[8][4];
#pragma unroll
        for (int nf = 0; nf < 8; nf++)
#pragma unroll
            for (int r = 0; r < 4; r++) s[nf][r] = 0.f;
#pragma unroll
        for (int ks = 0; ks < 4; ks++) {
#pragma unroll
            for (int nf2 = 0; nf2 < 8; nf2 += 2) {
                uint32_t ko = kvbK + 2 * ((nf2 * 8 + krL) * FSTR + ks * 16 + kdL);
                uint32_t bh[4], bl[4];
                ldsm_x4(bh, ko);
                ldsm_x4(bl, ko + 2 * KV_ONE);
                mma16816(s[nf2],     qhi[ks], &bh[0]);
                mma16816(s[nf2],     qhi[ks], &bl[0]);
                mma16816(s[nf2],     qlo[ks], &bh[0]);
                mma16816(s[nf2 + 1], qhi[ks], &bh[2]);
                mma16816(s[nf2 + 1], qhi[ks], &bl[2]);
                mma16816(s[nf2 + 1], qlo[ks], &bh[2]);
            }
        }

        // stage RAW scores for diag phase
        {
            float* Sw0 = Stile + (wr + r4) * SCS + c2;
            float* Sw1 = Sw0 + 8 * SCS;
#pragma unroll
            for (int nf = 0; nf < 8; nf++) {
                float2 w0 = { s[nf][0], s[nf][1] };
                float2 w1 = { s[nf][2], s[nf][3] };
                *(float2*)(Sw0 + nf * 8) = w0;
                *(float2*)(Sw1 + nf * 8) = w1;
            }
        }

        // scale + (optional) mask + row max
        const float* mrow0 = Mbase + (size_t)qrow * SQ + s0 + c2;
        const float* mrow1 = mrow0 + 8 * SQ;
        float mx0 = -INFINITY, mx1 = -INFINITY;
#pragma unroll
        for (int nf = 0; nf < 8; nf++) {
            float2 ma = {0.f, 0.f}, mb = {0.f, 0.f};
            if (useMask) {
                ma = *(const float2*)(mrow0 + nf * 8);
                mb = *(const float2*)(mrow1 + nf * 8);
            }
            s[nf][0] = s[nf][0] * 0.125f + ma.x;
            s[nf][1] = s[nf][1] * 0.125f + ma.y;
            s[nf][2] = s[nf][2] * 0.125f + mb.x;
            s[nf][3] = s[nf][3] * 0.125f + mb.y;
            mx0 = fmaxf(mx0, fmaxf(s[nf][0], s[nf][1]));
            mx1 = fmaxf(mx1, fmaxf(s[nf][2], s[nf][3]));
        }
        mx0 = fmaxf(mx0, __shfl_xor_sync(0xffffffffu, mx0, 1));
        mx0 = fmaxf(mx0, __shfl_xor_sync(0xffffffffu, mx0, 2));
        mx1 = fmaxf(mx1, __shfl_xor_sync(0xffffffffu, mx1, 1));
        mx1 = fmaxf(mx1, __shfl_xor_sync(0xffffffffu, mx1, 2));
        float nm0 = fmaxf(m0, mx0), nm1 = fmaxf(m1, mx1);
        float cor0 = __expf(m0 - nm0), cor1 = __expf(m1 - nm1);
        m0 = nm0; m1 = nm1;

        // exp -> bf16 P, row sums from bf16 values
        uint32_t pa[4][4];
        float rs0 = 0.f, rs1 = 0.f;
#pragma unroll
        for (int kc = 0; kc < 4; kc++) {
            int n0 = 2 * kc, n1 = 2 * kc + 1;
            pa[kc][0] = pack_bf2(__expf(s[n0][0] - nm0), __expf(s[n0][1] - nm0));
            pa[kc][1] = pack_bf2(__expf(s[n0][2] - nm1), __expf(s[n0][3] - nm1));
            pa[kc][2] = pack_bf2(__expf(s[n1][0] - nm0), __expf(s[n1][1] - nm0));
            pa[kc][3] = pack_bf2(__expf(s[n1][2] - nm1), __expf(s[n1][3] - nm1));
            float2 u;
            u = __bfloat1622float2(*(__nv_bfloat162*)&pa[kc][0]); rs0 += u.x + u.y;
            u = __bfloat1622float2(*(__nv_bfloat162*)&pa[kc][2]); rs0 += u.x + u.y;
            u = __bfloat1622float2(*(__nv_bfloat162*)&pa[kc][1]); rs1 += u.x + u.y;
            u = __bfloat1622float2(*(__nv_bfloat162*)&pa[kc][3]); rs1 += u.x + u.y;
        }
        rs0 += __shfl_xor_sync(0xffffffffu, rs0, 1);
        rs0 += __shfl_xor_sync(0xffffffffu, rs0, 2);
        rs1 += __shfl_xor_sync(0xffffffffu, rs1, 1);
        rs1 += __shfl_xor_sync(0xffffffffu, rs1, 2);
        l0 = l0 * cor0 + rs0;
        l1 = l1 * cor1 + rs1;
#pragma unroll
        for (int df = 0; df < 8; df++) {
            o[df][0] *= cor0; o[df][1] *= cor0;
            o[df][2] *= cor1; o[df][3] *= cor1;
        }

        // O += P @ Vhi (1-term)
#pragma unroll
        for (int kc = 0; kc < 4; kc++) {
#pragma unroll
            for (int df2 = 0; df2 < 8; df2 += 2) {
                uint32_t vo = kvbV + 2 * ((kc * 16 + vRow) * FSTR + (df2 + vSel) * 8);
                uint32_t vh[4];
                ldsm_x4t(vh, vo);
                mma16816(o[df2],     pa[kc], &vh[0]);
                mma16816(o[df2 + 1], pa[kc], &vh[2]);
            }
        }
        __syncthreads();

        // diagonal reduction (overlaps next-KV load in flight)
        if (tid < 191) {
            float sa = 0.f, sb = 0.f;
            int r = drlo;
            for (; r + 1 < drhi; r += 2) {
                sa += dbase[r * (SCS + 1)];
                sb += dbase[r * (SCS + 1) + (SCS + 1)];
            }
            if (r < drhi) sa += dbase[r * (SCS + 1)];
            int tau = (t0 - s0 + du) & (SQ - 1);
            acb[tau] += (sa + sb) * (1.f / 64.f);
        }
        if (has_next) cp_wait0();
        __syncthreads();
    }

    // flush tau bins
    for (int i = tid; i < SQ; i += 256)
        atomicAdd(&acrow[i], acb[i]);

    // epilogue: Comb = 0.5 * ctx
    float inv0 = 0.5f / l0, inv1 = 0.5f / l1;
    float* C0 = Comb + (size_t)b * SQ * HID + (size_t)qrow * HID + h * HD + c2;
#pragma unroll
    for (int df = 0; df < 8; df++) {
        float2 va = { o[df][0] * inv0, o[df][1] * inv0 };
        float2 vb = { o[df][2] * inv1, o[df][3] * inv1 };
        *(float2*)(C0 + df * 8)            = va;
        *(float2*)(C0 + 8 * HID + df * 8)  = vb;
    }
}

// ---------------- top-k (k=15) + softmax weights ----------------
__global__ __launch_bounds__(256) void topk_kernel(
    const float* __restrict__ ac, int* __restrict__ topi, float* __restrict__ topw)
{
    int bh = blockIdx.x;
    __shared__ float svv[SQ];
    __shared__ float rv[256];
    __shared__ int ri[256];
    __shared__ float tvals[KTOP];
    __shared__ int tidxs[KTOP];
    int tid = threadIdx.x;

    for (int i = tid; i < SQ; i += 256)
        svv[i] = ac[(size_t)bh * SQ + i];
    __syncthreads();

    for (int t = 0; t < KTOP; t++) {
        float bv = -INFINITY;
        int bi = 0;
        for (int i = tid; i < SQ; i += 256) {
            float v = svv[i];
            if (v > bv || (v == bv && i < bi)) { bv = v; bi = i; }
        }
        rv[tid] = bv; ri[tid] = bi;
        __syncthreads();
        for (int st = 128; st > 0; st >>= 1) {
            if (tid < st) {
                float v2 = rv[tid + st]; int i2 = ri[tid + st];
                if (v2 > rv[tid] || (v2 == rv[tid] && i2 < ri[tid])) { rv[tid] = v2; ri[tid] = i2; }
            }
            __syncthreads();
        }
        if (tid == 0) {
            tvals[t] = rv[0]; tidxs[t] = ri[0];
            svv[ri[0]] = -INFINITY;
        }
        __syncthreads();
    }

    if (tid == 0) {
        float mx = tvals[0];
        float e[KTOP], ssum = 0.f;
#pragma unroll
        for (int t = 0; t < KTOP; t++) { e[t] = __expf(tvals[t] - mx); ssum += e[t]; }
        float inv = 1.f / ssum;
#pragma unroll
        for (int t = 0; t < KTOP; t++) {
            topw[bh * KTOP + t] = e[t] * inv;
            topi[bh * KTOP + t] = tidxs[t];
        }
    }
}

// ---------------- frequency branch gather + fused hi/lo split ----------------
__global__ __launch_bounds__(256) void freq_kernel(
    const float* __restrict__ V, const int* __restrict__ topi,
    const float* __restrict__ topw, const float* __restrict__ Comb,
    __nv_bfloat16* __restrict__ Cbhi, __nv_bfloat16* __restrict__ Cblo)
{
    int t = blockIdx.x, b = blockIdx.y;
    __shared__ int si[NH * KTOP];
    __shared__ float sw[NH * KTOP];
    int tid = threadIdx.x;
    if (tid < NH * KTOP) {
        si[tid] = topi[b * NH * KTOP + tid];
        sw[tid] = topw[b * NH * KTOP + tid];
    }
    __syncthreads();

    int c = tid * 4;
    int h = c >> 6;
    size_t off = ((size_t)b * SQ + t) * HID + c;
    float4 acc = *(const float4*)&Comb[off];
    const float* Vb = V + (size_t)b * SQ * HID;
#pragma unroll
    for (int j = 0; j < KTOP; j++) {
        int row = (t + si[h * KTOP + j]) & (SQ - 1);
        float w = 0.5f * sw[h * KTOP + j];
        float4 v = *(const float4*)&Vb[(size_t)row * HID + c];
        acc.x += w * v.x; acc.y += w * v.y; acc.z += w * v.z; acc.w += w * v.w;
    }
    // fused split
    __nv_bfloat16 h0 = __float2bfloat16_rn(acc.x), h1 = __float2bfloat16_rn(acc.y);
    __nv_bfloat16 h2 = __float2bfloat16_rn(acc.z), h3 = __float2bfloat16_rn(acc.w);
    __nv_bfloat162 hv0 = {h0, h1}, hv1 = {h2, h3};
    __nv_bfloat162 lv0 = {__float2bfloat16_rn(acc.x - __bfloat162float(h0)),
                          __float2bfloat16_rn(acc.y - __bfloat162float(h1))};
    __nv_bfloat162 lv1 = {__float2bfloat16_rn(acc.z - __bfloat162float(h2)),
                          __float2bfloat16_rn(acc.w - __bfloat162float(h3))};
    *(__nv_bfloat162*)&Cbhi[off]     = hv0;
    *(__nv_bfloat162*)&Cblo[off]     = lv0;
    *(__nv_bfloat162*)&Cbhi[off + 2] = hv1;
    *(__nv_bfloat162*)&Cblo[off + 2] = lv1;
}

// ---------------- launcher ----------------
extern "C" void kernel_launch(void* const* d_in, const int* in_sizes, int n_in,
                              void* d_out, int out_size)
{
    const float* X    = (const float*)d_in[0];
    const float* mask = (const float*)d_in[1];
    const float* Wq   = (const float*)d_in[2];
    const float* bq   = (const float*)d_in[3];
    const float* Wk   = (const float*)d_in[4];
    const float* bk   = (const float*)d_in[5];
    const float* Wv   = (const float*)d_in[6];
    const float* bv   = (const float*)d_in[7];
    const float* Wo   = (const float*)d_in[8];
    const float* bo   = (const float*)d_in[9];
    const int*   li   = (const int*)d_in[10];
    const int*   nl   = (const int*)d_in[11];
    float* out = (float*)d_out;

    float *cP, *dcP, *VbP, *CbP, *acP, *twP;
    int *tiP, *mfP;
    __nv_bfloat16 *chiP, *cloP, *ChiP, *CloP, *XhiP, *XloP, *XfhiP, *XfloP, *CbhiP, *CbloP;
    __nv_bfloat16 *QfhiP, *QfloP, *KfhiP, *KfloP, *VfhiP, *VfloP;
    __nv_bfloat16 *WqhiP, *WqloP, *WkhiP, *WkloP, *WvhiP, *WvloP, *WohiP, *WoloP;
    cudaGetSymbolAddress((void**)&cP,  d_c);
    cudaGetSymbolAddress((void**)&dcP, d_dcflag);
    cudaGetSymbolAddress((void**)&mfP, d_maskflag);
    cudaGetSymbolAddress((void**)&VbP, d_Vbuf);
    cudaGetSymbolAddress((void**)&CbP, d_Comb);
    cudaGetSymbolAddress((void**)&acP, d_ac);
    cudaGetSymbolAddress((void**)&tiP, d_topi);
    cudaGetSymbolAddress((void**)&twP, d_topw);
    cudaGetSymbolAddress((void**)&chiP, d_chi);
    cudaGetSymbolAddress((void**)&cloP, d_clo);
    cudaGetSymbolAddress((void**)&ChiP, d_Chi);
    cudaGetSymbolAddress((void**)&CloP, d_Clo);
    cudaGetSymbolAddress((void**)&XhiP, d_Xhi);
    cudaGetSymbolAddress((void**)&XloP, d_Xlo);
    cudaGetSymbolAddress((void**)&XfhiP, d_Xfhi);
    cudaGetSymbolAddress((void**)&XfloP, d_Xflo);
    cudaGetSymbolAddress((void**)&QfhiP, d_Qfhi);
    cudaGetSymbolAddress((void**)&QfloP, d_Qflo);
    cudaGetSymbolAddress((void**)&KfhiP, d_Kfhi);
    cudaGetSymbolAddress((void**)&KfloP, d_Kflo);
    cudaGetSymbolAddress((void**)&VfhiP, d_Vfhi);
    cudaGetSymbolAddress((void**)&VfloP, d_Vflo);
    cudaGetSymbolAddress((void**)&CbhiP, d_Cbhi);
    cudaGetSymbolAddress((void**)&CbloP, d_Cblo);
    cudaGetSymbolAddress((void**)&WqhiP, d_Wqhi);
    cudaGetSymbolAddress((void**)&WqloP, d_Wqlo);
    cudaGetSymbolAddress((void**)&WkhiP, d_Wkhi);
    cudaGetSymbolAddress((void**)&WkloP, d_Wklo);
    cudaGetSymbolAddress((void**)&WvhiP, d_Wvhi);
    cudaGetSymbolAddress((void**)&WvloP, d_Wvlo);
    cudaGetSymbolAddress((void**)&WohiP, d_Wohi);
    cudaGetSymbolAddress((void**)&WoloP, d_Wolo);

    const long long SH = (long long)SQ * HID;
    const int NELT = BSZ * SQ * HID;
    const int WELT = HID * HID;

    static bool attrs_set = false;
    if (!attrs_set) {
        cudaFuncSetAttribute(gemm_bf16_kernel, cudaFuncAttributeMaxDynamicSharedMemorySize, 75776);
        cudaFuncSetAttribute(flash_kernel,     cudaFuncAttributeMaxDynamicSharedMemorySize, FLASH_SMEM);
        attrs_set = true;
    }

    // 0) mask all-zero check
    setflag_kernel<<<1, 1>>>(mfP);
    maskcheck_kernel<<<2048, 256>>>((const float4*)mask, BSZ * SQ * SQ / 4, mfP);

    // 1) filter taps + circulant (bf16)
    filter_kernel<<<8, 256>>>(li, nl, cP, dcP, chiP, cloP);
    cmat_kernel<<<(SQ * SQ) / 256, 256>>>(ChiP, CloP, chiP, cloP);

    // 2) split inputs
    split_kernel<<<NELT / 256, 256>>>(X, XhiP, XloP, NELT);
    split_kernel<<<WELT / 256, 256>>>(Wq, WqhiP, WqloP, WELT);
    split_kernel<<<WELT / 256, 256>>>(Wk, WkhiP, WkloP, WELT);
    split_kernel<<<WELT / 256, 256>>>(Wv, WvhiP, WvloP, WELT);
    split_kernel<<<WELT / 256, 256>>>(Wo, WohiP, WoloP, WELT);

    // 3) Xf = C @ X  -> bf16 hi/lo directly
    gemm_bf16_kernel<<<dim3(HID / 128, SQ / 128, BSZ), 256, 75776>>>(
        ChiP, CloP, XhiP, XloP, nullptr, nullptr, nullptr, XfhiP, XfloP, SQ, HID, SQ, 0, SH, SH);

    // 4) projections -> bf16 hi/lo for flash; Vbuf fp32 for freq branch
    gemm_bf16_kernel<<<dim3(HID / 128, SQ / 128, BSZ), 256, 75776>>>(
        XfhiP, XfloP, WqhiP, WqloP, bq, dcP, nullptr, QfhiP, QfloP, SQ, HID, HID, SH, 0, SH);
    gemm_bf16_kernel<<<dim3(HID / 128, SQ / 128, BSZ), 256, 75776>>>(
        XfhiP, XfloP, WkhiP, WkloP, bk, dcP, nullptr, KfhiP, KfloP, SQ, HID, HID, SH, 0, SH);
    gemm_bf16_kernel<<<dim3(HID / 128, SQ / 128, BSZ), 256, 75776>>>(
        XfhiP, XfloP, WvhiP, WvloP, bv, dcP, nullptr, VfhiP, VfloP, SQ, HID, HID, SH, 0, SH);
    gemm_bf16_kernel<<<dim3(HID / 128, SQ / 128, BSZ), 256, 75776>>>(
        XhiP, XloP, WvhiP, WvloP, bv, nullptr, VbP, nullptr, nullptr, SQ, HID, HID, SH, 0, SH);

    // 5) flash attention + diag-sum autocorrelation
    zero_kernel<<<(BSZ * NH * SQ) / 256, 256>>>(acP, BSZ * NH * SQ);
    flash_kernel<<<dim3(SQ / 128, NH, BSZ), 256, FLASH_SMEM>>>(
        QfhiP, QfloP, KfhiP, KfloP, VfhiP, mask, mfP, CbP, acP);

    // 6) top-k + frequency gather (with fused hi/lo split)
    topk_kernel<<<BSZ * NH, 256>>>(acP, tiP, twP);
    freq_kernel<<<dim3(SQ, BSZ), 256>>>(VbP, tiP, twP, CbP, CbhiP, CbloP);

    // 7) output projection
    gemm_bf16_kernel<<<dim3(HID / 128, (BSZ * SQ) / 128, 1), 256, 75776>>>(
        CbhiP, CbloP, WohiP, WoloP, bo, nullptr, out, nullptr, nullptr, BSZ * SQ, HID, HID, 0, 0, 0);
}

// round 11
// speedup vs baseline: 2.1520x; 1.0005x over previous
#include <cuda_runtime.h>
#include <cuda_bf16.h>
#include <math.h>
#include <stdint.h>

#define SQ   2048
#define HID  1024
#define NH   16
#define HD   64
#define BSZ  2
#define MFREQ (SQ/2 + 1)
#define KTOP 15

// ---------------- scratch ----------------
__device__ float d_c[SQ];
__device__ float d_dcflag;
__device__ int   d_maskflag;
__device__ float d_Vbuf[BSZ * SQ * HID];
__device__ float d_Comb[BSZ * SQ * HID];
__device__ float d_ac  [BSZ * NH * SQ];
__device__ int   d_topi[BSZ * NH * KTOP];
__device__ float d_topw[BSZ * NH * KTOP];

__device__ __nv_bfloat16 d_chi[SQ], d_clo[SQ];
__device__ __nv_bfloat16 d_Chi [SQ * SQ],        d_Clo [SQ * SQ];
__device__ __nv_bfloat16 d_Xhi [BSZ * SQ * HID], d_Xlo [BSZ * SQ * HID];
__device__ __nv_bfloat16 d_Xfhi[BSZ * SQ * HID], d_Xflo[BSZ * SQ * HID];
__device__ __nv_bfloat16 d_Qfhi[BSZ * SQ * HID], d_Qflo[BSZ * SQ * HID];
__device__ __nv_bfloat16 d_Kfhi[BSZ * SQ * HID], d_Kflo[BSZ * SQ * HID];
__device__ __nv_bfloat16 d_Vfhi[BSZ * SQ * HID], d_Vflo[BSZ * SQ * HID];
__device__ __nv_bfloat16 d_Cbhi[BSZ * SQ * HID], d_Cblo[BSZ * SQ * HID];
__device__ __nv_bfloat16 d_Wqhi[HID * HID], d_Wqlo[HID * HID];
__device__ __nv_bfloat16 d_Wkhi[HID * HID], d_Wklo[HID * HID];
__device__ __nv_bfloat16 d_Wvhi[HID * HID], d_Wvlo[HID * HID];
__device__ __nv_bfloat16 d_Wohi[HID * HID], d_Wolo[HID * HID];

// ---------------- cp.async helpers ----------------
__device__ __forceinline__ void cp_async16(void* smem, const void* gmem) {
    unsigned s = (unsigned)__cvta_generic_to_shared(smem);
    asm volatile("cp.async.cg.shared.global [%0], [%1], 16;" :: "r"(s), "l"(gmem));
}
__device__ __forceinline__ void cp_commit() { asm volatile("cp.async.commit_group;"); }
__device__ __forceinline__ void cp_wait0()  { asm volatile("cp.async.wait_group 0;"); }
__device__ __forceinline__ void cp_wait1()  { asm volatile("cp.async.wait_group 1;"); }

// ---------------- mma / ldmatrix helpers ----------------
__device__ __forceinline__ void mma16816(float* d, const uint32_t* a, const uint32_t* b) {
    asm volatile(
        "mma.sync.aligned.m16n8k16.row.col.f32.bf16.bf16.f32 "
        "{%0,%1,%2,%3}, {%4,%5,%6,%7}, {%8,%9}, {%0,%1,%2,%3};"
        : "+f"(d[0]), "+f"(d[1]), "+f"(d[2]), "+f"(d[3])
        : "r"(a[0]), "r"(a[1]), "r"(a[2]), "r"(a[3]), "r"(b[0]), "r"(b[1]));
}
__device__ __forceinline__ void ldsm_x4(uint32_t* r, uint32_t addr) {
    asm volatile("ldmatrix.sync.aligned.m8n8.x4.shared.b16 {%0,%1,%2,%3}, [%4];"
        : "=r"(r[0]), "=r"(r[1]), "=r"(r[2]), "=r"(r[3]) : "r"(addr));
}
__device__ __forceinline__ void ldsm_x4t(uint32_t* r, uint32_t addr) {
    asm volatile("ldmatrix.sync.aligned.m8n8.x4.trans.shared.b16 {%0,%1,%2,%3}, [%4];"
        : "=r"(r[0]), "=r"(r[1]), "=r"(r[2]), "=r"(r[3]) : "r"(addr));
}
__device__ __forceinline__ void ldsm_x2t(uint32_t* r, uint32_t addr) {
    asm volatile("ldmatrix.sync.aligned.m8n8.x2.trans.shared.b16 {%0,%1}, [%2];"
        : "=r"(r[0]), "=r"(r[1]) : "r"(addr));
}
__device__ __forceinline__ uint32_t pack_bf2(float a, float b) {
    __nv_bfloat162 t = __floats2bfloat162_rn(a, b);
    return *(uint32_t*)&t;
}

// ---------------- filter taps ----------------
__global__ void filter_kernel(const int* __restrict__ li_p, const int* __restrict__ nl_p,
                              float* __restrict__ c, float* __restrict__ dcflag,
                              __nv_bfloat16* __restrict__ chi, __nv_bfloat16* __restrict__ clo)
{
    int n = blockIdx.x * blockDim.x + threadIdx.x;
    if (n >= SQ) return;
    int li = *li_p;
    int nl = *nl_p;
    const double ALPHA = 0.5;
    int M = MFREQ;
    int p, q;
    if (ALPHA <= 1.0 / (double)nl) {
        p = (int)(M * (1.0 - (double)(li + 1) / (double)nl));
        q = (int)((double)p + (double)M / (double)nl);
    } else {
        p = (nl > 1) ? (int)(M * (1.0 - ALPHA) * (1.0 - (double)li / (double)(nl - 1))) : 0;
        q = (int)((double)p + ALPHA * (double)M);
    }
    p = max(0, min(p, M - 1));
    q = max(p + 1, min(q, M));

    double acc = 0.0;
    const double w2 = 2.0 / (double)SQ;
    const double w1 = 1.0 / (double)SQ;
    const double tpn = 6.283185307179586476925286766559 * (double)n / (double)SQ;
    for (int f = p; f < q; f++) {
        double wf = (f == 0 || f == M - 1) ? w1 : w2;
        acc += wf * cos(tpn * (double)f);
    }
    float cf = (float)acc;
    c[n] = cf;
    __nv_bfloat16 h = __float2bfloat16_rn(cf);
    chi[n] = h;
    clo[n] = __float2bfloat16_rn(cf - __bfloat162float(h));
    if (n == 0) *dcflag = (p == 0) ? 1.0f : 0.0f;
}

__global__ void cmat_kernel(__nv_bfloat16* __restrict__ Chi, __nv_bfloat16* __restrict__ Clo,
                            const __nv_bfloat16* __restrict__ chi, const __nv_bfloat16* __restrict__ clo)
{
    int idx = blockIdx.x * blockDim.x + threadIdx.x;
    int t = idx >> 11;
    int s = idx & (SQ - 1);
    int tau = (t - s) & (SQ - 1);
    Chi[idx] = chi[tau];
    Clo[idx] = clo[tau];
}

__global__ void split_kernel(const float* __restrict__ in,
                             __nv_bfloat16* __restrict__ hi, __nv_bfloat16* __restrict__ lo, int n)
{
    int i = blockIdx.x * blockDim.x + threadIdx.x;
    if (i >= n) return;
    float f = in[i];
    __nv_bfloat16 h = __float2bfloat16_rn(f);
    hi[i] = h;
    lo[i] = __float2bfloat16_rn(f - __bfloat162float(h));
}

__global__ void zero_kernel(float* __restrict__ p, int n)
{
    int i = blockIdx.x * blockDim.x + threadIdx.x;
    if (i < n) p[i] = 0.f;
}

__global__ void setflag_kernel(int* __restrict__ flag) { *flag = 0; }

// OR-reduce: flag=1 if any mask element nonzero
__global__ void maskcheck_kernel(const float4* __restrict__ m, int n4, int* __restrict__ flag)
{
    int i = blockIdx.x * blockDim.x + threadIdx.x;
    int stride = gridDim.x * blockDim.x;
    bool nz = false;
    for (; i < n4; i += stride) {
        float4 v = m[i];
        nz = nz || (v.x != 0.f) || (v.y != 0.f) || (v.z != 0.f) || (v.w != 0.f);
    }
    if (__syncthreads_or(nz) && threadIdx.x == 0)
        atomicOr(flag, 1);
}

// ---------------- bf16-split tensor-core GEMM ----------------
#define GA_STR 40
#define GB_STR 136
#define A_BUF_ELEMS (128 * GA_STR)
#define B_BUF_ELEMS (32 * GB_STR)
__global__ __launch_bounds__(256) void gemm_bf16_kernel(
    const __nv_bfloat16* __restrict__ Ahi, const __nv_bfloat16* __restrict__ Alo,
    const __nv_bfloat16* __restrict__ Bhi, const __nv_bfloat16* __restrict__ Blo,
    const float* __restrict__ bias, const float* __restrict__ bscalep,
    float* __restrict__ C,
    __nv_bfloat16* __restrict__ Ohi, __nv_bfloat16* __restrict__ Olo,
    int M, int N, int K,
    long long sA, long long sB, long long sC)
{
    extern __shared__ __nv_bfloat16 sm[];
    __nv_bfloat16* AsHi = sm;
    __nv_bfloat16* AsLo = sm + 2 * A_BUF_ELEMS;
    __nv_bfloat16* BsHi = sm + 4 * A_BUF_ELEMS;
    __nv_bfloat16* BsLo = sm + 4 * A_BUF_ELEMS + 2 * B_BUF_ELEMS;
    uint32_t sbase = (uint32_t)__cvta_generic_to_shared(sm);

    int z = blockIdx.z;
    Ahi += (size_t)z * sA;  Alo += (size_t)z * sA;
    Bhi += (size_t)z * sB;  Blo += (size_t)z * sB;
    if (C)   C   += (size_t)z * sC;
    if (Ohi) { Ohi += (size_t)z * sC; Olo += (size_t)z * sC; }

    int tid = threadIdx.x;
    int lane = tid & 31;
    int wid = tid >> 5;
    int mBase = (wid >> 2) * 64;
    int nBase = (wid & 3) * 32;
    int row0 = blockIdx.y * 128;
    int col0 = blockIdx.x * 128;

    float acc[4][4][4];
#pragma unroll
    for (int mf = 0; mf < 4; mf++)
#pragma unroll
        for (int nf = 0; nf < 4; nf++)
#pragma unroll
            for (int r = 0; r < 4; r++) acc[mf][nf][r] = 0.f;

    int ar = tid >> 1;
    int br = tid >> 3;
    const __nv_bfloat16* Ah0 = Ahi + (size_t)(row0 + ar) * K;
    const __nv_bfloat16* Al0 = Alo + (size_t)(row0 + ar) * K;

#define LOAD_TILES(buf, k0)                                                             \
    do {                                                                                \
        _Pragma("unroll")                                                               \
        for (int j = 0; j < 2; j++) {                                                   \
            int s = (tid & 1) * 2 + j;                                                  \
            cp_async16(&AsHi[(buf) * A_BUF_ELEMS + ar * GA_STR + s * 8],                \
                       Ah0 + (k0) + s * 8);                                             \
            cp_async16(&AsLo[(buf) * A_BUF_ELEMS + ar * GA_STR + s * 8],                \
                       Al0 + (k0) + s * 8);                                             \
            int sb = (tid & 7) * 2 + j;                                                 \
            cp_async16(&BsHi[(buf) * B_BUF_ELEMS + br * GB_STR + sb * 8],               \
                       Bhi + (size_t)((k0) + br) * N + col0 + sb * 8);                  \
            cp_async16(&BsLo[(buf) * B_BUF_ELEMS + br * GB_STR + sb * 8],               \
                       Blo + (size_t)((k0) + br) * N + col0 + sb * 8);                  \
        }                                                                               \
    } while (0)

    LOAD_TILES(0, 0);
    cp_commit();
    cp_wait0();
    __syncthreads();

    int nIter = K >> 5;
    int lr = lane & 15;
    int khalf = (lane >> 4) << 3;

    for (int it = 0; it < nIter; it++) {
        int buf = it & 1;
        if (it + 1 < nIter) {
            LOAD_TILES(buf ^ 1, (it + 1) << 5);
            cp_commit();
        }

        uint32_t aHiB = sbase + 2 * (buf * A_BUF_ELEMS);
        uint32_t aLoB = sbase + 2 * (2 * A_BUF_ELEMS + buf * A_BUF_ELEMS);
        uint32_t bHiB = sbase + 2 * (4 * A_BUF_ELEMS + buf * B_BUF_ELEMS);
        uint32_t bLoB = sbase + 2 * (4 * A_BUF_ELEMS + 2 * B_BUF_ELEMS + buf * B_BUF_ELEMS);

#pragma unroll
        for (int ks = 0; ks < 32; ks += 16) {
            uint32_t ahi[4][4], alo[4][4], bhi[4][2], blo[4][2];
#pragma unroll
            for (int mf = 0; mf < 4; mf++) {
                uint32_t off = 2 * ((mBase + mf * 16 + lr) * GA_STR + ks + khalf);
                ldsm_x4(ahi[mf], aHiB + off);
                ldsm_x4(alo[mf], aLoB + off);
            }
#pragma unroll
            for (int nf = 0; nf < 4; nf++) {
                uint32_t off = 2 * ((ks + lr) * GB_STR + nBase + nf * 8);
                ldsm_x2t(bhi[nf], bHiB + off);
                ldsm_x2t(blo[nf], bLoB + off);
            }
#pragma unroll
            for (int mf = 0; mf < 4; mf++)
#pragma unroll
                for (int nf = 0; nf < 4; nf++) {
                    mma16816(acc[mf][nf], ahi[mf], bhi[nf]);
                    mma16816(acc[mf][nf], ahi[mf], blo[nf]);
                    mma16816(acc[mf][nf], alo[mf], bhi[nf]);
                }
        }

        if (it + 1 < nIter) cp_wait0();
        __syncthreads();
    }

    float bscale = 0.f;
    if (bias) bscale = bscalep ? *bscalep : 1.f;

#pragma unroll
    for (int mf = 0; mf < 4; mf++) {
        int r0 = row0 + mBase + mf * 16 + (lane >> 2);
#pragma unroll
        for (int nf = 0; nf < 4; nf++) {
            int c0 = col0 + nBase + nf * 8 + (lane & 3) * 2;
            float b0 = 0.f, b1 = 0.f;
            if (bias) { b0 = bias[c0] * bscale; b1 = bias[c0 + 1] * bscale; }
            float v0 = acc[mf][nf][0] + b0, v1 = acc[mf][nf][1] + b1;
            float v2 = acc[mf][nf][2] + b0, v3 = acc[mf][nf][3] + b1;
            if (C) {
                float2 w0 = {v0, v1}, w1 = {v2, v3};
                *(float2*)&C[(size_t)r0 * N + c0]       = w0;
                *(float2*)&C[(size_t)(r0 + 8) * N + c0] = w1;
            }
            if (Ohi) {
                __nv_bfloat16 h0 = __float2bfloat16_rn(v0), h1 = __float2bfloat16_rn(v1);
                __nv_bfloat16 h2 = __float2bfloat16_rn(v2), h3 = __float2bfloat16_rn(v3);
                __nv_bfloat162 hv0 = {h0, h1}, hv1 = {h2, h3};
                __nv_bfloat162 lv0 = {__float2bfloat16_rn(v0 - __bfloat162float(h0)),
                                      __float2bfloat16_rn(v1 - __bfloat162float(h1))};
                __nv_bfloat162 lv1 = {__float2bfloat16_rn(v2 - __bfloat162float(h2)),
                                      __float2bfloat16_rn(v3 - __bfloat162float(h3))};
                *(__nv_bfloat162*)&Ohi[(size_t)r0 * N + c0]       = hv0;
                *(__nv_bfloat162*)&Olo[(size_t)r0 * N + c0]       = lv0;
                *(__nv_bfloat162*)&Ohi[(size_t)(r0 + 8) * N + c0] = hv1;
                *(__nv_bfloat162*)&Olo[(size_t)(r0 + 8) * N + c0] = lv1;
            }
        }
    }
}

// ---------------- tensor-core flash attention (2 blocks/SM, double-buffered KV) ----------------
// 3-term QK, 1-term PV. Mask loads skipped entirely when maskflag==0 (bit-identical).
#define FSTR 72
#define Q_ELEMS (128 * FSTR)
#define KV_BASE (2 * Q_ELEMS)
#define KV_ONE  (64 * FSTR)
#define KV_STRIDE (3 * KV_ONE)
#define SCS 66
#define ACB_OFF (2 * (KV_BASE + 2 * KV_STRIDE))   // 92160 bytes
#define FLASH_SMEM (ACB_OFF + SQ * 4)             // 100352 bytes
__global__ __launch_bounds__(256, 2) void flash_kernel(
    const __nv_bfloat16* __restrict__ Qhi_, const __nv_bfloat16* __restrict__ Qlo_,
    const __nv_bfloat16* __restrict__ Khi_, const __nv_bfloat16* __restrict__ Klo_,
    const __nv_bfloat16* __restrict__ Vhi_,
    const float* __restrict__ mask, const int* __restrict__ maskflag,
    float* __restrict__ Comb, float* __restrict__ ac)
{
    extern __shared__ __nv_bfloat16 smb[];
    float* Stile = (float*)smb;
    float* acb   = (float*)((char*)smb + ACB_OFF);
    uint32_t sbase = (uint32_t)__cvta_generic_to_shared(smb);

    int tid = threadIdx.x;
    int lane = tid & 31, wid = tid >> 5;
    int qb = blockIdx.x, h = blockIdx.y, b = blockIdx.z;
    int t0 = qb * 128;
    int wr = wid * 16;
    const int useMask = *maskflag;

    size_t hoff = (size_t)b * SQ * HID + h * HD;
    const __nv_bfloat16* Qh = Qhi_ + hoff;
    const __nv_bfloat16* Ql = Qlo_ + hoff;
    const __nv_bfloat16* Kh = Khi_ + hoff;
    const __nv_bfloat16* Kl = Klo_ + hoff;
    const __nv_bfloat16* Vh = Vhi_ + hoff;
    const float* Mbase = mask + (size_t)b * SQ * SQ;
    float* acrow = ac + (size_t)(b * NH + h) * SQ;

#define LOAD_KV(bufi, kti)                                                              \
    do {                                                                                \
        int s0_ = (kti) * 64;                                                           \
        unsigned kvo_ = KV_BASE + (bufi) * KV_STRIDE;                                   \
        _Pragma("unroll")                                                               \
        for (int kk = 0; kk < 2; kk++) {                                                \
            int id_ = tid + kk * 256;                                                   \
            int r_ = id_ >> 3, c8_ = (id_ & 7) * 8;                                     \
            size_t src_ = (size_t)(s0_ + r_) * HID + c8_;                               \
            unsigned dst_ = kvo_ + r_ * FSTR + c8_;                                     \
            cp_async16(&smb[dst_],              Kh + src_);                             \
            cp_async16(&smb[dst_ + KV_ONE],     Kl + src_);                             \
            cp_async16(&smb[dst_ + 2 * KV_ONE], Vh + src_);                             \
        }                                                                               \
    } while (0)

    // prologue: Q tile + KV0 in flight
#pragma unroll
    for (int k = 0; k < 4; k++) {
        int id = tid + k * 256;
        int r = id >> 3, c8 = (id & 7) * 8;
        size_t src = (size_t)(t0 + r) * HID + c8;
        cp_async16(&smb[r * FSTR + c8],           Qh + src);
        cp_async16(&smb[Q_ELEMS + r * FSTR + c8], Ql + src);
    }
    cp_commit();
    LOAD_KV(0, 0);
    cp_commit();
    for (int i = tid; i < SQ; i += 256) acb[i] = 0.f;
    cp_wait1();
    __syncthreads();

    // Q fragments (resident)
    uint32_t qhi[4][4], qlo[4][4];
    int lr = lane & 15, kh8 = (lane >> 4) * 8;
#pragma unroll
    for (int ks = 0; ks < 4; ks++) {
        uint32_t off = sbase + 2 * ((wr + lr) * FSTR + ks * 16 + kh8);
        ldsm_x4(qhi[ks], off);
        ldsm_x4(qlo[ks], off + 2 * Q_ELEMS);
    }
    cp_wait0();
    __syncthreads();

    float m0 = -INFINITY, m1 = -INFINITY, l0 = 0.f, l1 = 0.f;
    float o[8][4];
#pragma unroll
    for (int df = 0; df < 8; df++)
#pragma unroll
        for (int r = 0; r < 4; r++) o[df][r] = 0.f;

    int r4 = lane >> 2, c2 = (lane & 3) * 2;
    int qrow = t0 + wr + r4;
    int krL = ((lane >> 4) << 3) | (lane & 7);
    int kdL = ((lane >> 3) & 1) << 3;
    int vRow = lane & 15;
    int vSel = lane >> 4;

    int du = tid - 63;
    int drlo = du > 0 ? du : 0;
    int drhi = (du + 64 < 128) ? du + 64 : 128;
    const float* dbase = Stile - du;

    for (int kt = 0; kt < 32; kt++) {
        int s0 = kt * 64;
        int buf = kt & 1;
        bool has_next = (kt + 1 < 32);
        if (has_next) {
            LOAD_KV(buf ^ 1, kt + 1);
            cp_commit();
        }

        uint32_t kvbK = sbase + 2 * (KV_BASE + buf * KV_STRIDE);
        uint32_t kvbV = kvbK + 2 * (2 * KV_ONE);

        // scores: S = Qhi*Khi + Qhi*Klo + Qlo*Khi  (raw, fp32 acc)
        float s[8][4];
#pragma unroll
        for (int nf = 0; nf < 8; nf++)
#pragma unroll
            for (int r = 0; r < 4; r++) s[nf][r] = 0.f;
#pragma unroll
        for (int ks = 0; ks < 4; ks++) {
#pragma unroll
            for (int nf2 = 0; nf2 < 8; nf2 += 2) {
                uint32_t ko = kvbK + 2 * ((nf2 * 8 + krL) * FSTR + ks * 16 + kdL);
                uint32_t bh[4], bl[4];
                ldsm_x4(bh, ko);
                ldsm_x4(bl, ko + 2 * KV_ONE);
                mma16816(s[nf2],     qhi[ks], &bh[0]);
                mma16816(s[nf2],     qhi[ks], &bl[0]);
                mma16816(s[nf2],     qlo[ks], &bh[0]);
                mma16816(s[nf2 + 1], qhi[ks], &bh[2]);
                mma16816(s[nf2 + 1], qhi[ks], &bl[2]);
                mma16816(s[nf2 + 1], qlo[ks], &bh[2]);
            }
        }

        // stage RAW scores for diag phase
        {
            float* Sw0 = Stile + (wr + r4) * SCS + c2;
            float* Sw1 = Sw0 + 8 * SCS;
#pragma unroll
            for (int nf = 0; nf < 8; nf++) {
                float2 w0 = { s[nf][0], s[nf][1] };
                float2 w1 = { s[nf][2], s[nf][3] };
                *(float2*)(Sw0 + nf * 8) = w0;
                *(float2*)(Sw1 + nf * 8) = w1;
            }
        }

        // scale + (optional) mask + row max
        const float* mrow0 = Mbase + (size_t)qrow * SQ + s0 + c2;
        const float* mrow1 = mrow0 + 8 * SQ;
        float mx0 = -INFINITY, mx1 = -INFINITY;
#pragma unroll
        for (int nf = 0; nf < 8; nf++) {
            float2 ma = {0.f, 0.f}, mb = {0.f, 0.f};
            if (useMask) {
                ma = *(const float2*)(mrow0 + nf * 8);
                mb = *(const float2*)(mrow1 + nf * 8);
            }
            s[nf][0] = s[nf][0] * 0.125f + ma.x;
            s[nf][1] = s[nf][1] * 0.125f + ma.y;
            s[nf][2] = s[nf][2] * 0.125f + mb.x;
            s[nf][3] = s[nf][3] * 0.125f + mb.y;
            mx0 = fmaxf(mx0, fmaxf(s[nf][0], s[nf][1]));
            mx1 = fmaxf(mx1, fmaxf(s[nf][2], s[nf][3]));
        }
        mx0 = fmaxf(mx0, __shfl_xor_sync(0xffffffffu, mx0, 1));
        mx0 = fmaxf(mx0, __shfl_xor_sync(0xffffffffu, mx0, 2));
        mx1 = fmaxf(mx1, __shfl_xor_sync(0xffffffffu, mx1, 1));
        mx1 = fmaxf(mx1, __shfl_xor_sync(0xffffffffu, mx1, 2));
        float nm0 = fmaxf(m0, mx0), nm1 = fmaxf(m1, mx1);
        float cor0 = __expf(m0 - nm0), cor1 = __expf(m1 - nm1);
        m0 = nm0; m1 = nm1;

        // exp -> bf16 P, row sums from bf16 values
        uint32_t pa[4][4];
        float rs0 = 0.f, rs1 = 0.f;
#pragma unroll
        for (int kc = 0; kc < 4; kc++) {
            int n0 = 2 * kc, n1 = 2 * kc + 1;
            pa[kc][0] = pack_bf2(__expf(s[n0][0] - nm0), __expf(s[n0][1] - nm0));
            pa[kc][1] = pack_bf2(__expf(s[n0][2] - nm1), __expf(s[n0][3] - nm1));
            pa[kc][2] = pack_bf2(__expf(s[n1][0] - nm0), __expf(s[n1][1] - nm0));
            pa[kc][3] = pack_bf2(__expf(s[n1][2] - nm1), __expf(s[n1][3] - nm1));
            float2 u;
            u = __bfloat1622float2(*(__nv_bfloat162*)&pa[kc][0]); rs0 += u.x + u.y;
            u = __bfloat1622float2(*(__nv_bfloat162*)&pa[kc][2]); rs0 += u.x + u.y;
            u = __bfloat1622float2(*(__nv_bfloat162*)&pa[kc][1]); rs1 += u.x + u.y;
            u = __bfloat1622float2(*(__nv_bfloat162*)&pa[kc][3]); rs1 += u.x + u.y;
        }
        rs0 += __shfl_xor_sync(0xffffffffu, rs0, 1);
        rs0 += __shfl_xor_sync(0xffffffffu, rs0, 2);
        rs1 += __shfl_xor_sync(0xffffffffu, rs1, 1);
        rs1 += __shfl_xor_sync(0xffffffffu, rs1, 2);
        l0 = l0 * cor0 + rs0;
        l1 = l1 * cor1 + rs1;
#pragma unroll
        for (int df = 0; df < 8; df++) {
            o[df][0] *= cor0; o[df][1] *= cor0;
            o[df][2] *= cor1; o[df][3] *= cor1;
        }

        // O += P @ Vhi (1-term)
#pragma unroll
        for (int kc = 0; kc < 4; kc++) {
#pragma unroll
            for (int df2 = 0; df2 < 8; df2 += 2) {
                uint32_t vo = kvbV + 2 * ((kc * 16 + vRow) * FSTR + (df2 + vSel) * 8);
                uint32_t vh[4];
                ldsm_x4t(vh, vo);
                mma16816(o[df2],     pa[kc], &vh[0]);
                mma16816(o[df2 + 1], pa[kc], &vh[2]);
            }
        }
        __syncthreads();

        // diagonal reduction (overlaps next-KV load in flight)
        if (tid < 191) {
            float sa = 0.f, sb = 0.f;
            int r = drlo;
            for (; r + 1 < drhi; r += 2) {
                sa += dbase[r * (SCS + 1)];
                sb += dbase[r * (SCS + 1) + (SCS + 1)];
            }
            if (r < drhi) sa += dbase[r * (SCS + 1)];
            int tau = (t0 - s0 + du) & (SQ - 1);
            acb[tau] += (sa + sb) * (1.f / 64.f);
        }
        if (has_next) cp_wait0();
        __syncthreads();
    }

    // flush tau bins
    for (int i = tid; i < SQ; i += 256)
        atomicAdd(&acrow[i], acb[i]);

    // epilogue: Comb = 0.5 * ctx
    float inv0 = 0.5f / l0, inv1 = 0.5f / l1;
    float* C0 = Comb + (size_t)b * SQ * HID + (size_t)qrow * HID + h * HD + c2;
#pragma unroll
    for (int df = 0; df < 8; df++) {
        float2 va = { o[df][0] * inv0, o[df][1] * inv0 };
        float2 vb = { o[df][2] * inv1, o[df][3] * inv1 };
        *(float2*)(C0 + df * 8)            = va;
        *(float2*)(C0 + 8 * HID + df * 8)  = vb;
    }
}

// ---------------- top-k (k=15) + softmax weights ----------------
__global__ __launch_bounds__(256) void topk_kernel(
    const float* __restrict__ ac, int* __restrict__ topi, float* __restrict__ topw)
{
    int bh = blockIdx.x;
    __shared__ float svv[SQ];
    __shared__ float rv[256];
    __shared__ int ri[256];
    __shared__ float tvals[KTOP];
    __shared__ int tidxs[KTOP];
    int tid = threadIdx.x;

    for (int i = tid; i < SQ; i += 256)
        svv[i] = ac[(size_t)bh * SQ + i];
    __syncthreads();

    for (int t = 0; t < KTOP; t++) {
        float bv = -INFINITY;
        int bi = 0;
        for (int i = tid; i < SQ; i += 256) {
            float v = svv[i];
            if (v > bv || (v == bv && i < bi)) { bv = v; bi = i; }
        }
        rv[tid] = bv; ri[tid] = bi;
        __syncthreads();
        for (int st = 128; st > 0; st >>= 1) {
            if (tid < st) {
                float v2 = rv[tid + st]; int i2 = ri[tid + st];
                if (v2 > rv[tid] || (v2 == rv[tid] && i2 < ri[tid])) { rv[tid] = v2; ri[tid] = i2; }
            }
            __syncthreads();
        }
        if (tid == 0) {
            tvals[t] = rv[0]; tidxs[t] = ri[0];
            svv[ri[0]] = -INFINITY;
        }
        __syncthreads();
    }

    if (tid == 0) {
        float mx = tvals[0];
        float e[KTOP], ssum = 0.f;
#pragma unroll
        for (int t = 0; t < KTOP; t++) { e[t] = __expf(tvals[t] - mx); ssum += e[t]; }
        float inv = 1.f / ssum;
#pragma unroll
        for (int t = 0; t < KTOP; t++) {
            topw[bh * KTOP + t] = e[t] * inv;
            topi[bh * KTOP + t] = tidxs[t];
        }
    }
}

// ---------------- frequency branch gather + fused hi/lo split ----------------
__global__ __launch_bounds__(256) void freq_kernel(
    const float* __restrict__ V, const int* __restrict__ topi,
    const float* __restrict__ topw, const float* __restrict__ Comb,
    __nv_bfloat16* __restrict__ Cbhi, __nv_bfloat16* __restrict__ Cblo)
{
    int t = blockIdx.x, b = blockIdx.y;
    __shared__ int si[NH * KTOP];
    __shared__ float sw[NH * KTOP];
    int tid = threadIdx.x;
    if (tid < NH * KTOP) {
        si[tid] = topi[b * NH * KTOP + tid];
        sw[tid] = topw[b * NH * KTOP + tid];
    }
    __syncthreads();

    int c = tid * 4;
    int h = c >> 6;
    size_t off = ((size_t)b * SQ + t) * HID + c;
    float4 acc = *(const float4*)&Comb[off];
    const float* Vb = V + (size_t)b * SQ * HID;
#pragma unroll
    for (int j = 0; j < KTOP; j++) {
        int row = (t + si[h * KTOP + j]) & (SQ - 1);
        float w = 0.5f * sw[h * KTOP + j];
        float4 v = *(const float4*)&Vb[(size_t)row * HID + c];
        acc.x += w * v.x; acc.y += w * v.y; acc.z += w * v.z; acc.w += w * v.w;
    }
    // fused split
    __nv_bfloat16 h0 = __float2bfloat16_rn(acc.x), h1 = __float2bfloat16_rn(acc.y);
    __nv_bfloat16 h2 = __float2bfloat16_rn(acc.z), h3 = __float2bfloat16_rn(acc.w);
    __nv_bfloat162 hv0 = {h0, h1}, hv1 = {h2, h3};
    __nv_bfloat162 lv0 = {__float2bfloat16_rn(acc.x - __bfloat162float(h0)),
                          __float2bfloat16_rn(acc.y - __bfloat162float(h1))};
    __nv_bfloat162 lv1 = {__float2bfloat16_rn(acc.z - __bfloat162float(h2)),
                          __float2bfloat16_rn(acc.w - __bfloat162float(h3))};
    *(__nv_bfloat162*)&Cbhi[off]     = hv0;
    *(__nv_bfloat162*)&Cblo[off]     = lv0;
    *(__nv_bfloat162*)&Cbhi[off + 2] = hv1;
    *(__nv_bfloat162*)&Cblo[off + 2] = lv1;
}

// ---------------- launcher ----------------
extern "C" void kernel_launch(void* const* d_in, const int* in_sizes, int n_in,
                              void* d_out, int out_size)
{
    const float* X    = (const float*)d_in[0];
    const float* mask = (const float*)d_in[1];
    const float* Wq   = (const float*)d_in[2];
    const float* bq   = (const float*)d_in[3];
    const float* Wk   = (const float*)d_in[4];
    const float* bk   = (const float*)d_in[5];
    const float* Wv   = (const float*)d_in[6];
    const float* bv   = (const float*)d_in[7];
    const float* Wo   = (const float*)d_in[8];
    const float* bo   = (const float*)d_in[9];
    const int*   li   = (const int*)d_in[10];
    const int*   nl   = (const int*)d_in[11];
    float* out = (float*)d_out;

    float *cP, *dcP, *VbP, *CbP, *acP, *twP;
    int *tiP, *mfP;
    __nv_bfloat16 *chiP, *cloP, *ChiP, *CloP, *XhiP, *XloP, *XfhiP, *XfloP, *CbhiP, *CbloP;
    __nv_bfloat16 *QfhiP, *QfloP, *KfhiP, *KfloP, *VfhiP, *VfloP;
    __nv_bfloat16 *WqhiP, *WqloP, *WkhiP, *WkloP, *WvhiP, *WvloP, *WohiP, *WoloP;
    cudaGetSymbolAddress((void**)&cP,  d_c);
    cudaGetSymbolAddress((void**)&dcP, d_dcflag);
    cudaGetSymbolAddress((void**)&mfP, d_maskflag);
    cudaGetSymbolAddress((void**)&VbP, d_Vbuf);
    cudaGetSymbolAddress((void**)&CbP, d_Comb);
    cudaGetSymbolAddress((void**)&acP, d_ac);
    cudaGetSymbolAddress((void**)&tiP, d_topi);
    cudaGetSymbolAddress((void**)&twP, d_topw);
    cudaGetSymbolAddress((void**)&chiP, d_chi);
    cudaGetSymbolAddress((void**)&cloP, d_clo);
    cudaGetSymbolAddress((void**)&ChiP, d_Chi);
    cudaGetSymbolAddress((void**)&CloP, d_Clo);
    cudaGetSymbolAddress((void**)&XhiP, d_Xhi);
    cudaGetSymbolAddress((void**)&XloP, d_Xlo);
    cudaGetSymbolAddress((void**)&XfhiP, d_Xfhi);
    cudaGetSymbolAddress((void**)&XfloP, d_Xflo);
    cudaGetSymbolAddress((void**)&QfhiP, d_Qfhi);
    cudaGetSymbolAddress((void**)&QfloP, d_Qflo);
    cudaGetSymbolAddress((void**)&KfhiP, d_Kfhi);
    cudaGetSymbolAddress((void**)&KfloP, d_Kflo);
    cudaGetSymbolAddress((void**)&VfhiP, d_Vfhi);
    cudaGetSymbolAddress((void**)&VfloP, d_Vflo);
    cudaGetSymbolAddress((void**)&CbhiP, d_Cbhi);
    cudaGetSymbolAddress((void**)&CbloP, d_Cblo);
    cudaGetSymbolAddress((void**)&WqhiP, d_Wqhi);
    cudaGetSymbolAddress((void**)&WqloP, d_Wqlo);
    cudaGetSymbolAddress((void**)&WkhiP, d_Wkhi);
    cudaGetSymbolAddress((void**)&WkloP, d_Wklo);
    cudaGetSymbolAddress((void**)&WvhiP, d_Wvhi);
    cudaGetSymbolAddress((void**)&WvloP, d_Wvlo);
    cudaGetSymbolAddress((void**)&WohiP, d_Wohi);
    cudaGetSymbolAddress((void**)&WoloP, d_Wolo);

    const long long SH = (long long)SQ * HID;
    const int NELT = BSZ * SQ * HID;
    const int WELT = HID * HID;

    static bool attrs_set = false;
    if (!attrs_set) {
        cudaFuncSetAttribute(gemm_bf16_kernel, cudaFuncAttributeMaxDynamicSharedMemorySize, 75776);
        cudaFuncSetAttribute(flash_kernel,     cudaFuncAttributeMaxDynamicSharedMemorySize, FLASH_SMEM);
        attrs_set = true;
    }

    // 0) mask all-zero check
    setflag_kernel<<<1, 1>>>(mfP);
    maskcheck_kernel<<<2048, 256>>>((const float4*)mask, BSZ * SQ * SQ / 4, mfP);

    // 1) filter taps + circulant (bf16)
    filter_kernel<<<8, 256>>>(li, nl, cP, dcP, chiP, cloP);
    cmat_kernel<<<(SQ * SQ) / 256, 256>>>(ChiP, CloP, chiP, cloP);

    // 2) split inputs
    split_kernel<<<NELT / 256, 256>>>(X, XhiP, XloP, NELT);
    split_kernel<<<WELT / 256, 256>>>(Wq, WqhiP, WqloP, WELT);
    split_kernel<<<WELT / 256, 256>>>(Wk, WkhiP, WkloP, WELT);
    split_kernel<<<WELT / 256, 256>>>(Wv, WvhiP, WvloP, WELT);
    split_kernel<<<WELT / 256, 256>>>(Wo, WohiP, WoloP, WELT);

    // 3) Xf = C @ X  -> bf16 hi/lo directly
    gemm_bf16_kernel<<<dim3(HID / 128, SQ / 128, BSZ), 256, 75776>>>(
        ChiP, CloP, XhiP, XloP, nullptr, nullptr, nullptr, XfhiP, XfloP, SQ, HID, SQ, 0, SH, SH);

    // 4) projections -> bf16 hi/lo for flash; Vbuf fp32 for freq branch
    gemm_bf16_kernel<<<dim3(HID / 128, SQ / 128, BSZ), 256, 75776>>>(
        XfhiP, XfloP, WqhiP, WqloP, bq, dcP, nullptr, QfhiP, QfloP, SQ, HID, HID, SH, 0, SH);
    gemm_bf16_kernel<<<dim3(HID / 128, SQ / 128, BSZ), 256, 75776>>>(
        XfhiP, XfloP, WkhiP, WkloP, bk, dcP, nullptr, KfhiP, KfloP, SQ, HID, HID, SH, 0, SH);
    gemm_bf16_kernel<<<dim3(HID / 128, SQ / 128, BSZ), 256, 75776>>>(
        XfhiP, XfloP, WvhiP, WvloP, bv, dcP, nullptr, VfhiP, VfloP, SQ, HID, HID, SH, 0, SH);
    gemm_bf16_kernel<<<dim3(HID / 128, SQ / 128, BSZ), 256, 75776>>>(
        XhiP, XloP, WvhiP, WvloP, bv, nullptr, VbP, nullptr, nullptr, SQ, HID, HID, SH, 0, SH);

    // 5) flash attention + diag-sum autocorrelation
    zero_kernel<<<(BSZ * NH * SQ) / 256, 256>>>(acP, BSZ * NH * SQ);
    flash_kernel<<<dim3(SQ / 128, NH, BSZ), 256, FLASH_SMEM>>>(
        QfhiP, QfloP, KfhiP, KfloP, VfhiP, mask, mfP, CbP, acP);

    // 6) top-k + frequency gather (with fused hi/lo split)
    topk_kernel<<<BSZ * NH, 256>>>(acP, tiP, twP);
    freq_kernel<<<dim3(SQ, BSZ), 256>>>(VbP, tiP, twP, CbP, CbhiP, CbloP);

    // 7) output projection
    gemm_bf16_kernel<<<dim3(HID / 128, (BSZ * SQ) / 128, 1), 256, 75776>>>(
        CbhiP, CbloP, WohiP, WoloP, bo, nullptr, out, nullptr, nullptr, BSZ * SQ, HID, HID, 0, 0, 0);
}